// round 1
// baseline (speedup 1.0000x reference)
#include <cuda_runtime.h>
#include <cuda_bf16.h>
#include <math.h>

// ---------------- problem constants ----------------
#define BB   2
#define TT   2048
#define CC   1024
#define HH   16
#define DD   64
#define FF   4096
#define MM   (BB*TT)          // 4096 rows
#define QKVC (3*CC)           // 3072

// ---------------- scratch (device globals; no allocs allowed) ----------------
__device__ float g_h  [MM*CC];    // LN output (reused for both LNs)
__device__ float g_qkv[MM*QKVC];  // qkv
__device__ float g_att[MM*CC];    // attention output (pre out-proj)
__device__ float g_x1 [MM*CC];    // x + attn proj (residual stream)
__device__ float g_ff [MM*FF];    // gelu(ff1) output

// ---------------- LayerNorm: one block per row ----------------
__global__ void __launch_bounds__(256) ln_kernel(const float* __restrict__ x,
                                                 const float* __restrict__ g,
                                                 const float* __restrict__ b,
                                                 float* __restrict__ y)
{
    int row = blockIdx.x;
    const float* xr = x + row * CC;
    int tid = threadIdx.x;

    float v[4];
    float s1 = 0.f, s2 = 0.f;
#pragma unroll
    for (int i = 0; i < 4; i++) {
        v[i] = xr[tid + i * 256];
        s1 += v[i];
        s2 += v[i] * v[i];
    }
#pragma unroll
    for (int o = 16; o; o >>= 1) {
        s1 += __shfl_xor_sync(0xffffffffu, s1, o);
        s2 += __shfl_xor_sync(0xffffffffu, s2, o);
    }
    __shared__ float r1[8], r2[8], sh_mean, sh_rstd;
    if ((tid & 31) == 0) { r1[tid >> 5] = s1; r2[tid >> 5] = s2; }
    __syncthreads();
    if (tid == 0) {
        float t1 = 0.f, t2 = 0.f;
#pragma unroll
        for (int i = 0; i < 8; i++) { t1 += r1[i]; t2 += r2[i]; }
        float mean = t1 * (1.0f / CC);
        float var  = t2 * (1.0f / CC) - mean * mean;
        sh_mean = mean;
        sh_rstd = rsqrtf(var + 1e-5f);
    }
    __syncthreads();
    float mean = sh_mean, rstd = sh_rstd;
    float* yr = y + row * CC;
#pragma unroll
    for (int i = 0; i < 4; i++) {
        int c = tid + i * 256;
        yr[c] = (v[i] - mean) * rstd * g[c] + b[c];
    }
}

// ---------------- SGEMM 128x128x8, 256 threads, 8x8 micro-tile ----------------
// C[M,N] = A[M,K] @ W[K,N] + bias[N]  (+ optional GELU) (+ optional residual)
template<int ACT>
__global__ void __launch_bounds__(256) gemm_kernel(const float* __restrict__ A,
                                                   const float* __restrict__ W,
                                                   const float* __restrict__ bias,
                                                   const float* __restrict__ res,
                                                   float* __restrict__ C,
                                                   int M, int N, int K)
{
    __shared__ float As[8][128];
    __shared__ float Ws[8][128];

    int tid = threadIdx.x;
    int bx = blockIdx.x, by = blockIdx.y;
    int tx = tid & 15, ty = tid >> 4;

    float acc[8][8] = {};

    int arow = tid >> 1;          // 0..127
    int acol = (tid & 1) * 4;     // 0 or 4
    int wrow = tid >> 5;          // 0..7
    int wcol = (tid & 31) * 4;    // 0..124

    const float* Aptr = A + (by * 128 + arow) * K + acol;
    const float* Wptr = W + wrow * N + bx * 128 + wcol;

    for (int k0 = 0; k0 < K; k0 += 8) {
        float4 av = *(const float4*)(Aptr + k0);
        As[acol + 0][arow] = av.x;
        As[acol + 1][arow] = av.y;
        As[acol + 2][arow] = av.z;
        As[acol + 3][arow] = av.w;
        float4 wv = *(const float4*)(Wptr + (size_t)k0 * N);
        *(float4*)&Ws[wrow][wcol] = wv;
        __syncthreads();
#pragma unroll
        for (int kk = 0; kk < 8; kk++) {
            float a[8], bv[8];
#pragma unroll
            for (int i = 0; i < 8; i++) a[i]  = As[kk][ty * 8 + i];
#pragma unroll
            for (int j = 0; j < 8; j++) bv[j] = Ws[kk][tx * 8 + j];
#pragma unroll
            for (int i = 0; i < 8; i++)
#pragma unroll
                for (int j = 0; j < 8; j++)
                    acc[i][j] += a[i] * bv[j];
        }
        __syncthreads();
    }

#pragma unroll
    for (int i = 0; i < 8; i++) {
        int r = by * 128 + ty * 8 + i;
#pragma unroll
        for (int j = 0; j < 8; j++) {
            int c = bx * 128 + tx * 8 + j;
            float v = acc[i][j] + bias[c];
            if (ACT == 1) v = 0.5f * v * (1.0f + erff(v * 0.70710678118654752f));
            if (res) v += res[(size_t)r * N + c];
            C[(size_t)r * N + c] = v;
        }
    }
}

// ---------------- causal flash attention ----------------
// grid: (T/64, H, B), block: 256 threads.
// 64-query tile; thread owns (q = tid/4, 16 dims at dbase = (tid%4)*16).
__global__ void __launch_bounds__(256) attn_kernel(const float* __restrict__ qkv,
                                                   float* __restrict__ out)
{
    extern __shared__ float sm[];
    float* sQ = sm;            // 64*64
    float* sK = sm + 4096;
    float* sV = sm + 8192;
    float* sS = sm + 12288;
    float* sMax   = sm + 16384;  // 64
    float* sSum   = sMax + 64;
    float* sScale = sSum + 64;

    int tid = threadIdx.x;
    int qt = blockIdx.x, h = blockIdx.y, b = blockIdx.z;
    int rowbase = b * TT;

    // load Q tile
    for (int i = tid; i < 4096; i += 256) {
        int q = i >> 6, d = i & 63;
        sQ[i] = qkv[(size_t)(rowbase + qt * 64 + q) * QKVC + h * DD + d];
    }
    if (tid < 64) { sMax[tid] = -1e30f; sSum[tid] = 0.f; }

    int q = tid >> 2;
    int dbase = (tid & 3) << 4;
    float acc[16] = {};

    for (int kt = 0; kt <= qt; kt++) {
        __syncthreads();
        // load K,V tiles
        for (int i = tid; i < 4096; i += 256) {
            int j = i >> 6, d = i & 63;
            size_t r = (size_t)(rowbase + kt * 64 + j) * QKVC + h * DD + d;
            sK[i] = qkv[r + CC];
            sV[i] = qkv[r + 2 * CC];
        }
        __syncthreads();

        // scores: thread computes S[q][jb..jb+15]
        {
            int jb = (tid & 3) << 4;
            float sreg[16] = {};
#pragma unroll
            for (int dc = 0; dc < 64; dc += 16) {
                float qr[16];
#pragma unroll
                for (int t = 0; t < 16; t++) qr[t] = sQ[q * 64 + dc + t];
#pragma unroll
                for (int jj = 0; jj < 16; jj++) {
                    const float* kp = &sK[(jb + jj) * 64 + dc];
                    float s = 0.f;
#pragma unroll
                    for (int t = 0; t < 16; t++) s += qr[t] * kp[t];
                    sreg[jj] += s;
                }
            }
            int qg = qt * 64 + q;
#pragma unroll
            for (int jj = 0; jj < 16; jj++) {
                int kg = kt * 64 + jb + jj;
                float s = sreg[jj] * 0.125f;
                if (kg > qg) s = -1e30f;
                sS[q * 64 + jb + jj] = s;
            }
        }
        __syncthreads();

        // online-softmax row stats (64 threads, one per row)
        if (tid < 64) {
            int qq = tid;
            float mold = sMax[qq];
            float mt = mold;
            for (int j = 0; j < 64; j++) mt = fmaxf(mt, sS[qq * 64 + j]);
            float scale = __expf(mold - mt);
            float psum = 0.f;
            for (int j = 0; j < 64; j++) {
                float p = __expf(sS[qq * 64 + j] - mt);
                sS[qq * 64 + j] = p;
                psum += p;
            }
            sSum[qq] = sSum[qq] * scale + psum;
            sMax[qq] = mt;
            sScale[qq] = scale;
        }
        __syncthreads();

        // O update
        float sc = sScale[q];
#pragma unroll
        for (int t = 0; t < 16; t++) acc[t] *= sc;
        for (int j = 0; j < 64; j++) {
            float p = sS[q * 64 + j];
            const float* vp = &sV[j * 64 + dbase];
#pragma unroll
            for (int t = 0; t < 16; t++) acc[t] += p * vp[t];
        }
    }

    float inv = 1.0f / sSum[q];
    size_t orow = (size_t)(rowbase + qt * 64 + q);
    float* op = out + orow * CC + h * DD + dbase;
#pragma unroll
    for (int t = 0; t < 16; t++) op[t] = acc[t] * inv;
}

// ---------------- launch ----------------
extern "C" void kernel_launch(void* const* d_in, const int* in_sizes, int n_in,
                              void* d_out, int out_size)
{
    const float* x     = (const float*)d_in[0];
    const float* ln1_g = (const float*)d_in[1];
    const float* ln1_b = (const float*)d_in[2];
    const float* qkv_w = (const float*)d_in[3];
    const float* qkv_b = (const float*)d_in[4];
    const float* out_w = (const float*)d_in[5];
    const float* out_b = (const float*)d_in[6];
    const float* ln2_g = (const float*)d_in[7];
    const float* ln2_b = (const float*)d_in[8];
    const float* ff1_w = (const float*)d_in[9];
    const float* ff1_b = (const float*)d_in[10];
    const float* ff2_w = (const float*)d_in[11];
    const float* ff2_b = (const float*)d_in[12];
    float* y = (float*)d_out;

    float *p_h, *p_qkv, *p_att, *p_x1, *p_ff;
    cudaGetSymbolAddress((void**)&p_h,   g_h);
    cudaGetSymbolAddress((void**)&p_qkv, g_qkv);
    cudaGetSymbolAddress((void**)&p_att, g_att);
    cudaGetSymbolAddress((void**)&p_x1,  g_x1);
    cudaGetSymbolAddress((void**)&p_ff,  g_ff);

    const int ATTN_SMEM = (16384 + 192) * 4;  // 66304 bytes
    cudaFuncSetAttribute(attn_kernel, cudaFuncAttributeMaxDynamicSharedMemorySize, ATTN_SMEM);

    // 1) h = LN1(x)
    ln_kernel<<<MM, 256>>>(x, ln1_g, ln1_b, p_h);
    // 2) qkv = h @ qkv_w + qkv_b
    gemm_kernel<0><<<dim3(QKVC / 128, MM / 128), 256>>>(p_h, qkv_w, qkv_b, nullptr, p_qkv, MM, QKVC, CC);
    // 3) attention
    attn_kernel<<<dim3(TT / 64, HH, BB), 256, ATTN_SMEM>>>(p_qkv, p_att);
    // 4) x1 = x + att @ out_w + out_b
    gemm_kernel<0><<<dim3(CC / 128, MM / 128), 256>>>(p_att, out_w, out_b, x, p_x1, MM, CC, CC);
    // 5) h = LN2(x1)
    ln_kernel<<<MM, 256>>>(p_x1, ln2_g, ln2_b, p_h);
    // 6) ff = gelu(h @ ff1_w + ff1_b)
    gemm_kernel<1><<<dim3(FF / 128, MM / 128), 256>>>(p_h, ff1_w, ff1_b, nullptr, p_ff, MM, FF, CC);
    // 7) out = x1 + ff @ ff2_w + ff2_b
    gemm_kernel<0><<<dim3(CC / 128, MM / 128), 256>>>(p_ff, ff2_w, ff2_b, p_x1, y, MM, CC, FF);
}

// round 2
// speedup vs baseline: 2.0968x; 2.0968x over previous
#include <cuda_runtime.h>
#include <cuda_bf16.h>
#include <math.h>

// ---------------- problem constants ----------------
#define BB   2
#define TT   2048
#define CC   1024
#define HH   16
#define DD   64
#define FF   4096
#define MM   (BB*TT)          // 4096 rows
#define QKVC (3*CC)           // 3072

// ---------------- scratch (device globals; no allocs allowed) ----------------
__device__ float g_h  [MM*CC];    // LN output (reused for both LNs)
__device__ float g_qkv[MM*QKVC];  // qkv
__device__ float g_att[MM*CC];    // attention output (pre out-proj)
__device__ float g_x1 [MM*CC];    // x + attn proj (residual stream)
__device__ float g_ff [MM*FF];    // gelu(ff1) output

// ---------------- LayerNorm: one block per row ----------------
__global__ void __launch_bounds__(256) ln_kernel(const float* __restrict__ x,
                                                 const float* __restrict__ g,
                                                 const float* __restrict__ b,
                                                 float* __restrict__ y)
{
    int row = blockIdx.x;
    const float* xr = x + row * CC;
    int tid = threadIdx.x;

    float v[4];
    float s1 = 0.f, s2 = 0.f;
#pragma unroll
    for (int i = 0; i < 4; i++) {
        v[i] = xr[tid + i * 256];
        s1 += v[i];
        s2 += v[i] * v[i];
    }
#pragma unroll
    for (int o = 16; o; o >>= 1) {
        s1 += __shfl_xor_sync(0xffffffffu, s1, o);
        s2 += __shfl_xor_sync(0xffffffffu, s2, o);
    }
    __shared__ float r1[8], r2[8], sh_mean, sh_rstd;
    if ((tid & 31) == 0) { r1[tid >> 5] = s1; r2[tid >> 5] = s2; }
    __syncthreads();
    if (tid == 0) {
        float t1 = 0.f, t2 = 0.f;
#pragma unroll
        for (int i = 0; i < 8; i++) { t1 += r1[i]; t2 += r2[i]; }
        float mean = t1 * (1.0f / CC);
        float var  = t2 * (1.0f / CC) - mean * mean;
        sh_mean = mean;
        sh_rstd = rsqrtf(var + 1e-5f);
    }
    __syncthreads();
    float mean = sh_mean, rstd = sh_rstd;
    float* yr = y + row * CC;
#pragma unroll
    for (int i = 0; i < 4; i++) {
        int c = tid + i * 256;
        yr[c] = (v[i] - mean) * rstd * g[c] + b[c];
    }
}

// ---------------- SGEMM 128x128x8, 256 threads, 8x8 micro-tile, reg prefetch ----
// C[M,N] = A[M,K] @ W[K,N] + bias[N]  (+ optional GELU) (+ optional residual)
template<int ACT>
__global__ void __launch_bounds__(256) gemm_kernel(const float* __restrict__ A,
                                                   const float* __restrict__ W,
                                                   const float* __restrict__ bias,
                                                   const float* __restrict__ res,
                                                   float* __restrict__ C,
                                                   int M, int N, int K)
{
    __shared__ float As[8][128];
    __shared__ float Ws[8][128];

    int tid = threadIdx.x;
    int bx = blockIdx.x, by = blockIdx.y;
    int tx = tid & 15, ty = tid >> 4;

    float acc[8][8] = {};

    int arow = tid >> 1;          // 0..127
    int acol = (tid & 1) * 4;     // 0 or 4
    int wrow = tid >> 5;          // 0..7
    int wcol = (tid & 31) * 4;    // 0..124

    const float* Aptr = A + (size_t)(by * 128 + arow) * K + acol;
    const float* Wptr = W + (size_t)wrow * N + bx * 128 + wcol;

    // prefetch first tile
    float4 av = *(const float4*)(Aptr);
    float4 wv = *(const float4*)(Wptr);

    for (int k0 = 0; k0 < K; k0 += 8) {
        As[acol + 0][arow] = av.x;
        As[acol + 1][arow] = av.y;
        As[acol + 2][arow] = av.z;
        As[acol + 3][arow] = av.w;
        *(float4*)&Ws[wrow][wcol] = wv;
        __syncthreads();

        // prefetch next tile (global-load latency hidden behind compute)
        if (k0 + 8 < K) {
            av = *(const float4*)(Aptr + k0 + 8);
            wv = *(const float4*)(Wptr + (size_t)(k0 + 8) * N);
        }

#pragma unroll
        for (int kk = 0; kk < 8; kk++) {
            float a[8], bv[8];
#pragma unroll
            for (int i = 0; i < 8; i++) a[i]  = As[kk][ty * 8 + i];
#pragma unroll
            for (int j = 0; j < 8; j++) bv[j] = Ws[kk][tx * 8 + j];
#pragma unroll
            for (int i = 0; i < 8; i++)
#pragma unroll
                for (int j = 0; j < 8; j++)
                    acc[i][j] += a[i] * bv[j];
        }
        __syncthreads();
    }

#pragma unroll
    for (int i = 0; i < 8; i++) {
        int r = by * 128 + ty * 8 + i;
#pragma unroll
        for (int j = 0; j < 8; j++) {
            int c = bx * 128 + tx * 8 + j;
            float v = acc[i][j] + bias[c];
            if (ACT == 1) v = 0.5f * v * (1.0f + erff(v * 0.70710678118654752f));
            if (res) v += res[(size_t)r * N + c];
            C[(size_t)r * N + c] = v;
        }
    }
}

// ---------------- causal flash attention, conflict-free smem ----------------
// grid: (T/64, H, B), block 256.
// Tiles 64x64, smem row stride 65 (==1 mod 32 -> conflict-free).
// Compute phases use 16x16 thread grid, 4x4 micro-tile over {t, t+16, t+32, t+48}.
#define ST 65
__global__ void __launch_bounds__(256) attn_kernel(const float* __restrict__ qkv,
                                                   float* __restrict__ out)
{
    extern __shared__ float sm[];
    float* sQ = sm;               // 64*65
    float* sK = sQ + 64 * ST;
    float* sV = sK + 64 * ST;
    float* sS = sV + 64 * ST;
    float* sMax   = sS + 64 * ST; // 64
    float* sSum   = sMax + 64;
    float* sScale = sSum + 64;

    int tid = threadIdx.x;
    int qt = blockIdx.x, h = blockIdx.y, b = blockIdx.z;
    int rowbase = b * TT;

    int tq = tid >> 4;      // 0..15
    int tj = tid & 15;      // 0..15

    // load Q tile (float4 gmem reads, scalar smem stores)
    for (int i = tid; i < 1024; i += 256) {
        int q = i >> 4, c4 = (i & 15) << 2;
        float4 v = *(const float4*)&qkv[(size_t)(rowbase + qt * 64 + q) * QKVC + h * DD + c4];
        float* d = &sQ[q * ST + c4];
        d[0] = v.x; d[1] = v.y; d[2] = v.z; d[3] = v.w;
    }
    if (tid < 64) { sMax[tid] = -1e30f; sSum[tid] = 0.f; }

    float acc[4][4] = {};

    for (int kt = 0; kt <= qt; kt++) {
        __syncthreads();
        // load K,V tiles
        for (int i = tid; i < 1024; i += 256) {
            int j = i >> 4, c4 = (i & 15) << 2;
            size_t r = (size_t)(rowbase + kt * 64 + j) * QKVC + h * DD + c4;
            float4 kv = *(const float4*)&qkv[r + CC];
            float4 vv = *(const float4*)&qkv[r + 2 * CC];
            float* dk = &sK[j * ST + c4];
            float* dv = &sV[j * ST + c4];
            dk[0] = kv.x; dk[1] = kv.y; dk[2] = kv.z; dk[3] = kv.w;
            dv[0] = vv.x; dv[1] = vv.y; dv[2] = vv.z; dv[3] = vv.w;
        }
        __syncthreads();

        // scores: 4x4 micro-tile, rows {tq+16i}, cols {tj+16j}
        {
            float s[4][4] = {};
#pragma unroll 8
            for (int d = 0; d < 64; d++) {
                float qv[4], kv[4];
#pragma unroll
                for (int i = 0; i < 4; i++) qv[i] = sQ[(tq + 16 * i) * ST + d];
#pragma unroll
                for (int j = 0; j < 4; j++) kv[j] = sK[(tj + 16 * j) * ST + d];
#pragma unroll
                for (int i = 0; i < 4; i++)
#pragma unroll
                    for (int j = 0; j < 4; j++)
                        s[i][j] += qv[i] * kv[j];
            }
            if (kt == qt) {
#pragma unroll
                for (int i = 0; i < 4; i++) {
                    int qg = (tq + 16 * i);
#pragma unroll
                    for (int j = 0; j < 4; j++) {
                        int kg = (tj + 16 * j);
                        float v = (kg > qg) ? -1e30f : s[i][j] * 0.125f;
                        sS[qg * ST + kg] = v;
                    }
                }
            } else {
#pragma unroll
                for (int i = 0; i < 4; i++)
#pragma unroll
                    for (int j = 0; j < 4; j++)
                        sS[(tq + 16 * i) * ST + tj + 16 * j] = s[i][j] * 0.125f;
            }
        }
        __syncthreads();

        // parallel online softmax: 4 threads per row, 16 cols each
        {
            int r = tid >> 2;
            int c0 = (tid & 3) << 4;
            float* row = &sS[r * ST + c0];
            float mold = sMax[r];
            float mt = mold;
#pragma unroll
            for (int jj = 0; jj < 16; jj++) mt = fmaxf(mt, row[jj]);
            mt = fmaxf(mt, __shfl_xor_sync(0xffffffffu, mt, 1));
            mt = fmaxf(mt, __shfl_xor_sync(0xffffffffu, mt, 2));
            float psum = 0.f;
#pragma unroll
            for (int jj = 0; jj < 16; jj++) {
                float p = __expf(row[jj] - mt);
                row[jj] = p;
                psum += p;
            }
            psum += __shfl_xor_sync(0xffffffffu, psum, 1);
            psum += __shfl_xor_sync(0xffffffffu, psum, 2);
            if ((tid & 3) == 0) {
                float scale = __expf(mold - mt);
                sScale[r] = scale;
                sSum[r] = sSum[r] * scale + psum;
                sMax[r] = mt;
            }
        }
        __syncthreads();

        // O update: rows {tq+16i}, dims {tj+16j}
        {
            float sc[4];
#pragma unroll
            for (int i = 0; i < 4; i++) sc[i] = sScale[tq + 16 * i];
#pragma unroll
            for (int i = 0; i < 4; i++)
#pragma unroll
                for (int j = 0; j < 4; j++)
                    acc[i][j] *= sc[i];
#pragma unroll 8
            for (int k = 0; k < 64; k++) {
                float pv[4], vv[4];
#pragma unroll
                for (int i = 0; i < 4; i++) pv[i] = sS[(tq + 16 * i) * ST + k];
#pragma unroll
                for (int j = 0; j < 4; j++) vv[j] = sV[k * ST + tj + 16 * j];
#pragma unroll
                for (int i = 0; i < 4; i++)
#pragma unroll
                    for (int j = 0; j < 4; j++)
                        acc[i][j] += pv[i] * vv[j];
            }
        }
    }

#pragma unroll
    for (int i = 0; i < 4; i++) {
        int r = tq + 16 * i;
        float inv = 1.0f / sSum[r];
        size_t orow = (size_t)(rowbase + qt * 64 + r);
#pragma unroll
        for (int j = 0; j < 4; j++) {
            out[orow * CC + h * DD + tj + 16 * j] = acc[i][j] * inv;
        }
    }
}

// ---------------- launch ----------------
extern "C" void kernel_launch(void* const* d_in, const int* in_sizes, int n_in,
                              void* d_out, int out_size)
{
    const float* x     = (const float*)d_in[0];
    const float* ln1_g = (const float*)d_in[1];
    const float* ln1_b = (const float*)d_in[2];
    const float* qkv_w = (const float*)d_in[3];
    const float* qkv_b = (const float*)d_in[4];
    const float* out_w = (const float*)d_in[5];
    const float* out_b = (const float*)d_in[6];
    const float* ln2_g = (const float*)d_in[7];
    const float* ln2_b = (const float*)d_in[8];
    const float* ff1_w = (const float*)d_in[9];
    const float* ff1_b = (const float*)d_in[10];
    const float* ff2_w = (const float*)d_in[11];
    const float* ff2_b = (const float*)d_in[12];
    float* y = (float*)d_out;

    float *p_h, *p_qkv, *p_att, *p_x1, *p_ff;
    cudaGetSymbolAddress((void**)&p_h,   g_h);
    cudaGetSymbolAddress((void**)&p_qkv, g_qkv);
    cudaGetSymbolAddress((void**)&p_att, g_att);
    cudaGetSymbolAddress((void**)&p_x1,  g_x1);
    cudaGetSymbolAddress((void**)&p_ff,  g_ff);

    const int ATTN_SMEM = (4 * 64 * ST + 192) * 4;  // 67328 bytes
    cudaFuncSetAttribute(attn_kernel, cudaFuncAttributeMaxDynamicSharedMemorySize, ATTN_SMEM);

    // 1) h = LN1(x)
    ln_kernel<<<MM, 256>>>(x, ln1_g, ln1_b, p_h);
    // 2) qkv = h @ qkv_w + qkv_b
    gemm_kernel<0><<<dim3(QKVC / 128, MM / 128), 256>>>(p_h, qkv_w, qkv_b, nullptr, p_qkv, MM, QKVC, CC);
    // 3) attention
    attn_kernel<<<dim3(TT / 64, HH, BB), 256, ATTN_SMEM>>>(p_qkv, p_att);
    // 4) x1 = x + att @ out_w + out_b
    gemm_kernel<0><<<dim3(CC / 128, MM / 128), 256>>>(p_att, out_w, out_b, x, p_x1, MM, CC, CC);
    // 5) h = LN2(x1)
    ln_kernel<<<MM, 256>>>(p_x1, ln2_g, ln2_b, p_h);
    // 6) ff = gelu(h @ ff1_w + ff1_b)
    gemm_kernel<1><<<dim3(FF / 128, MM / 128), 256>>>(p_h, ff1_w, ff1_b, nullptr, p_ff, MM, FF, CC);
    // 7) out = x1 + ff @ ff2_w + ff2_b
    gemm_kernel<0><<<dim3(CC / 128, MM / 128), 256>>>(p_ff, ff2_w, ff2_b, p_x1, y, MM, CC, FF);
}

// round 4
// speedup vs baseline: 3.5750x; 1.7050x over previous
#include <cuda_runtime.h>
#include <cuda_bf16.h>
#include <math.h>
#include <stdint.h>

// ---------------- problem constants ----------------
#define BB   2
#define TT   2048
#define CC   1024
#define HH   16
#define DD   64
#define FF   4096
#define MM   (BB*TT)          // 4096 rows
#define QKVC (3*CC)           // 3072

// ---------------- scratch (device globals; no allocs allowed) ----------------
__device__ float g_qkv[MM*QKVC];                 // qkv fp32 (attention input)
__device__ float g_x1 [MM*CC];                   // residual stream after attn
__device__ alignas(128) __nv_bfloat16 g_hhi[MM*CC], g_hlo[MM*CC];   // LN out split
__device__ alignas(128) __nv_bfloat16 g_ahi[MM*CC], g_alo[MM*CC];   // attn out split
__device__ alignas(128) __nv_bfloat16 g_fhi[MM*FF], g_flo[MM*FF];   // gelu out split
// transposed split weights: Wt[n][k]
__device__ alignas(128) __nv_bfloat16 g_wqkv_hi[CC*QKVC], g_wqkv_lo[CC*QKVC];
__device__ alignas(128) __nv_bfloat16 g_wout_hi[CC*CC],   g_wout_lo[CC*CC];
__device__ alignas(128) __nv_bfloat16 g_wff1_hi[CC*FF],   g_wff1_lo[CC*FF];
__device__ alignas(128) __nv_bfloat16 g_wff2_hi[FF*CC],   g_wff2_lo[FF*CC];

// ================= helpers =================
__device__ __forceinline__ uint32_t smem_to_u32(const void* p) {
    uint32_t a;
    asm("{ .reg .u64 t; cvta.to.shared.u64 t, %1; cvt.u32.u64 %0, t; }" : "=r"(a) : "l"(p));
    return a;
}
#define CP_ASYNC16(dst, src) \
    asm volatile("cp.async.cg.shared.global [%0], [%1], 16;" :: "r"(dst), "l"(src))
#define CP_COMMIT() asm volatile("cp.async.commit_group;" ::: "memory")
#define CP_WAIT(n)  asm volatile("cp.async.wait_group %0;" :: "n"(n) : "memory")

__device__ __forceinline__ void ldsm4(uint32_t* r, uint32_t addr) {
    asm volatile("ldmatrix.sync.aligned.m8n8.x4.shared.b16 {%0,%1,%2,%3}, [%4];"
                 : "=r"(r[0]), "=r"(r[1]), "=r"(r[2]), "=r"(r[3]) : "r"(addr));
}
__device__ __forceinline__ void mma16816(float* c, const uint32_t* a, const uint32_t* b) {
    asm volatile("mma.sync.aligned.m16n8k16.row.col.f32.bf16.bf16.f32 "
                 "{%0,%1,%2,%3}, {%4,%5,%6,%7}, {%8,%9}, {%0,%1,%2,%3};"
                 : "+f"(c[0]), "+f"(c[1]), "+f"(c[2]), "+f"(c[3])
                 : "r"(a[0]), "r"(a[1]), "r"(a[2]), "r"(a[3]), "r"(b[0]), "r"(b[1]));
}

// ================= weight transpose + bf16 split =================
// W[K][N] row-major -> Wt_hi/lo[N][K]
__global__ void __launch_bounds__(256) wsplit_kernel(const float* __restrict__ W,
                                                     __nv_bfloat16* __restrict__ Whi,
                                                     __nv_bfloat16* __restrict__ Wlo,
                                                     int K, int N)
{
    __shared__ float t[32][33];
    int tx = threadIdx.x, ty = threadIdx.y;   // block (32,8)
    int n0 = blockIdx.x * 32, k0 = blockIdx.y * 32;
#pragma unroll
    for (int i = 0; i < 4; i++)
        t[ty + 8 * i][tx] = W[(size_t)(k0 + ty + 8 * i) * N + n0 + tx];
    __syncthreads();
#pragma unroll
    for (int i = 0; i < 4; i++) {
        int n = n0 + ty + 8 * i, k = k0 + tx;
        float v = t[tx][ty + 8 * i];
        __nv_bfloat16 hi = __float2bfloat16(v);
        __nv_bfloat16 lo = __float2bfloat16(v - __bfloat162float(hi));
        Whi[(size_t)n * K + k] = hi;
        Wlo[(size_t)n * K + k] = lo;
    }
}

// ================= LayerNorm with split-bf16 output =================
__global__ void __launch_bounds__(256) ln_kernel(const float* __restrict__ x,
                                                 const float* __restrict__ g,
                                                 const float* __restrict__ b,
                                                 __nv_bfloat16* __restrict__ yhi,
                                                 __nv_bfloat16* __restrict__ ylo)
{
    int row = blockIdx.x;
    const float* xr = x + (size_t)row * CC;
    int tid = threadIdx.x;

    float v[4];
    float s1 = 0.f, s2 = 0.f;
#pragma unroll
    for (int i = 0; i < 4; i++) {
        v[i] = xr[tid + i * 256];
        s1 += v[i];
        s2 += v[i] * v[i];
    }
#pragma unroll
    for (int o = 16; o; o >>= 1) {
        s1 += __shfl_xor_sync(0xffffffffu, s1, o);
        s2 += __shfl_xor_sync(0xffffffffu, s2, o);
    }
    __shared__ float r1[8], r2[8], sh_mean, sh_rstd;
    if ((tid & 31) == 0) { r1[tid >> 5] = s1; r2[tid >> 5] = s2; }
    __syncthreads();
    if (tid == 0) {
        float t1 = 0.f, t2 = 0.f;
#pragma unroll
        for (int i = 0; i < 8; i++) { t1 += r1[i]; t2 += r2[i]; }
        float mean = t1 * (1.0f / CC);
        float var  = t2 * (1.0f / CC) - mean * mean;
        sh_mean = mean;
        sh_rstd = rsqrtf(var + 1e-5f);
    }
    __syncthreads();
    float mean = sh_mean, rstd = sh_rstd;
#pragma unroll
    for (int i = 0; i < 4; i++) {
        int c = tid + i * 256;
        float o = (v[i] - mean) * rstd * g[c] + b[c];
        __nv_bfloat16 hi = __float2bfloat16(o);
        __nv_bfloat16 lo = __float2bfloat16(o - __bfloat162float(hi));
        yhi[(size_t)row * CC + c] = hi;
        ylo[(size_t)row * CC + c] = lo;
    }
}

// ================= mma.sync GEMM (split-bf16, 3 terms) =================
// C[M,N] = A''[M,3K] @ B''[3K,N] where segments: (Ahi,Bhi),(Alo,Bhi),(Ahi,Blo)
// A row-major [M][K] bf16; B is Wt[N][K] bf16 (i.e., B col-major).
// Block tile 128x128, K-chunk 32, 8 warps (4m x 2n), warp tile 32x64.
// 4-stage cp.async pipeline. Padded smem stride 40 halves (80B).
// E: 0 = fp32 out (+bias); 1 = fp32 out (+bias+res); 2 = gelu -> split bf16.
#define GS 4
#define SSTRIDE 40                         // halves per row
#define ATILE_BYTES (128*SSTRIDE*2)        // 10240
#define STAGE_BYTES (2*ATILE_BYTES)        // 20480
#define GSMEM_TOTAL (GS*STAGE_BYTES)       // 81920

template<int E>
__global__ void __launch_bounds__(256) gemm_mma(const __nv_bfloat16* __restrict__ Ahi,
                                                const __nv_bfloat16* __restrict__ Alo,
                                                const __nv_bfloat16* __restrict__ Bhi,
                                                const __nv_bfloat16* __restrict__ Blo,
                                                const float* __restrict__ bias,
                                                const float* __restrict__ res,
                                                float* __restrict__ outf,
                                                __nv_bfloat16* __restrict__ outhi,
                                                __nv_bfloat16* __restrict__ outlo,
                                                int K, int gN)
{
    extern __shared__ char smem[];
    uint32_t sbase = smem_to_u32(smem);
    int tid = threadIdx.x, lane = tid & 31, wid = tid >> 5;
    int bx = blockIdx.x, by = blockIdx.y;
    const int NK = K >> 5;
    const int NC = 3 * NK;
    int m0 = (wid & 3) * 32, n0 = (wid >> 2) * 64;

    const __nv_bfloat16* AhiB = Ahi + (size_t)(by * 128) * K;
    const __nv_bfloat16* AloB = Alo + (size_t)(by * 128) * K;
    const __nv_bfloat16* BhiB = Bhi + (size_t)(bx * 128) * K;
    const __nv_bfloat16* BloB = Blo + (size_t)(bx * 128) * K;

    int u = tid & 3;        // 16B unit within 64B row-chunk
    int r0 = tid >> 2;      // 0..63

    auto issue = [&](int c) {
        int seg = (c >= 2 * NK) ? 2 : (c >= NK ? 1 : 0);
        int kk = c - seg * NK;
        const __nv_bfloat16* As = (seg == 1) ? AloB : AhiB;
        const __nv_bfloat16* Bs = (seg == 2) ? BloB : BhiB;
        uint32_t stA = sbase + (c & (GS - 1)) * STAGE_BYTES;
        uint32_t stB = stA + ATILE_BYTES;
#pragma unroll
        for (int rr = 0; rr < 2; rr++) {
            int r = r0 + rr * 64;
            const void* ga = As + (size_t)r * K + kk * 32 + u * 8;
            const void* gb = Bs + (size_t)r * K + kk * 32 + u * 8;
            CP_ASYNC16(stA + (r * SSTRIDE + u * 8) * 2, ga);
            CP_ASYNC16(stB + (r * SSTRIDE + u * 8) * 2, gb);
        }
        CP_COMMIT();
    };

    float acc[2][8][4] = {};

    for (int c = 0; c < GS - 1; c++) issue(c);

    for (int c = 0; c < NC; c++) {
        int pre = c + GS - 1;
        if (pre < NC) issue(pre); else CP_COMMIT();   // keep group count uniform
        CP_WAIT(GS - 1);
        __syncthreads();

        uint32_t aB = sbase + (c & (GS - 1)) * STAGE_BYTES;
        uint32_t bB = aB + ATILE_BYTES;
#pragma unroll
        for (int kh = 0; kh < 2; kh++) {
            uint32_t a[2][4];
#pragma unroll
            for (int i = 0; i < 2; i++) {
                int row = m0 + i * 16 + (lane & 15);
                int col = kh * 16 + (lane >> 4) * 8;
                ldsm4(a[i], aB + (row * SSTRIDE + col) * 2);
            }
            uint32_t b[4][4];
#pragma unroll
            for (int g = 0; g < 4; g++) {
                int nrow = n0 + g * 16 + (lane & 7) + ((lane >> 4) & 1) * 8;
                int col = kh * 16 + ((lane >> 3) & 1) * 8;
                ldsm4(b[g], bB + (nrow * SSTRIDE + col) * 2);
            }
#pragma unroll
            for (int i = 0; i < 2; i++)
#pragma unroll
                for (int g = 0; g < 4; g++) {
                    mma16816(acc[i][g * 2 + 0], a[i], &b[g][0]);
                    mma16816(acc[i][g * 2 + 1], a[i], &b[g][2]);
                }
        }
        __syncthreads();
    }

    // epilogue from registers
    int mb = by * 128 + m0;
    int nb = bx * 128 + n0;
#pragma unroll
    for (int i = 0; i < 2; i++) {
#pragma unroll
        for (int j = 0; j < 8; j++) {
            float* cc = acc[i][j];
            int n = nb + j * 8 + (lane & 3) * 2;
            float b0 = bias[n], b1 = bias[n + 1];
#pragma unroll
            for (int hrow = 0; hrow < 2; hrow++) {
                int m = mb + i * 16 + (lane >> 2) + hrow * 8;
                float v0 = cc[hrow * 2 + 0] + b0;
                float v1 = cc[hrow * 2 + 1] + b1;
                size_t off = (size_t)m * gN + n;
                if (E == 1) {
                    float2 rv = *(const float2*)(res + off);
                    v0 += rv.x; v1 += rv.y;
                }
                if (E == 2) {
                    v0 = 0.5f * v0 * (1.0f + erff(v0 * 0.70710678118654752f));
                    v1 = 0.5f * v1 * (1.0f + erff(v1 * 0.70710678118654752f));
                    __nv_bfloat16 h0 = __float2bfloat16(v0);
                    __nv_bfloat16 h1 = __float2bfloat16(v1);
                    __nv_bfloat162 hv; hv.x = h0; hv.y = h1;
                    __nv_bfloat162 lv;
                    lv.x = __float2bfloat16(v0 - __bfloat162float(h0));
                    lv.y = __float2bfloat16(v1 - __bfloat162float(h1));
                    *(__nv_bfloat162*)(outhi + off) = hv;
                    *(__nv_bfloat162*)(outlo + off) = lv;
                } else {
                    float2 ov; ov.x = v0; ov.y = v1;
                    *(float2*)(outf + off) = ov;
                }
            }
        }
    }
}

// ================= causal flash attention (fp32, split-bf16 output) =========
#define ST 65
__global__ void __launch_bounds__(256) attn_kernel(const float* __restrict__ qkv,
                                                   __nv_bfloat16* __restrict__ ohi,
                                                   __nv_bfloat16* __restrict__ olo)
{
    extern __shared__ float sm[];
    float* sQ = sm;               // 64*65
    float* sK = sQ + 64 * ST;
    float* sV = sK + 64 * ST;
    float* sS = sV + 64 * ST;
    float* sMax   = sS + 64 * ST; // 64
    float* sSum   = sMax + 64;
    float* sScale = sSum + 64;

    int tid = threadIdx.x;
    int qt = blockIdx.x, h = blockIdx.y, b = blockIdx.z;
    int rowbase = b * TT;

    int tq = tid >> 4;      // 0..15
    int tj = tid & 15;      // 0..15

    for (int i = tid; i < 1024; i += 256) {
        int q = i >> 4, c4 = (i & 15) << 2;
        float4 v = *(const float4*)&qkv[(size_t)(rowbase + qt * 64 + q) * QKVC + h * DD + c4];
        float* d = &sQ[q * ST + c4];
        d[0] = v.x; d[1] = v.y; d[2] = v.z; d[3] = v.w;
    }
    if (tid < 64) { sMax[tid] = -1e30f; sSum[tid] = 0.f; }

    float acc[4][4] = {};

    for (int kt = 0; kt <= qt; kt++) {
        __syncthreads();
        for (int i = tid; i < 1024; i += 256) {
            int j = i >> 4, c4 = (i & 15) << 2;
            size_t r = (size_t)(rowbase + kt * 64 + j) * QKVC + h * DD + c4;
            float4 kv = *(const float4*)&qkv[r + CC];
            float4 vv = *(const float4*)&qkv[r + 2 * CC];
            float* dk = &sK[j * ST + c4];
            float* dv = &sV[j * ST + c4];
            dk[0] = kv.x; dk[1] = kv.y; dk[2] = kv.z; dk[3] = kv.w;
            dv[0] = vv.x; dv[1] = vv.y; dv[2] = vv.z; dv[3] = vv.w;
        }
        __syncthreads();

        {
            float s[4][4] = {};
#pragma unroll 8
            for (int d = 0; d < 64; d++) {
                float qv[4], kv[4];
#pragma unroll
                for (int i = 0; i < 4; i++) qv[i] = sQ[(tq + 16 * i) * ST + d];
#pragma unroll
                for (int j = 0; j < 4; j++) kv[j] = sK[(tj + 16 * j) * ST + d];
#pragma unroll
                for (int i = 0; i < 4; i++)
#pragma unroll
                    for (int j = 0; j < 4; j++)
                        s[i][j] += qv[i] * kv[j];
            }
            if (kt == qt) {
#pragma unroll
                for (int i = 0; i < 4; i++) {
                    int qg = (tq + 16 * i);
#pragma unroll
                    for (int j = 0; j < 4; j++) {
                        int kg = (tj + 16 * j);
                        float v = (kg > qg) ? -1e30f : s[i][j] * 0.125f;
                        sS[qg * ST + kg] = v;
                    }
                }
            } else {
#pragma unroll
                for (int i = 0; i < 4; i++)
#pragma unroll
                    for (int j = 0; j < 4; j++)
                        sS[(tq + 16 * i) * ST + tj + 16 * j] = s[i][j] * 0.125f;
            }
        }
        __syncthreads();

        {
            int r = tid >> 2;
            int c0 = (tid & 3) << 4;
            float* row = &sS[r * ST + c0];
            float mold = sMax[r];
            float mt = mold;
#pragma unroll
            for (int jj = 0; jj < 16; jj++) mt = fmaxf(mt, row[jj]);
            mt = fmaxf(mt, __shfl_xor_sync(0xffffffffu, mt, 1));
            mt = fmaxf(mt, __shfl_xor_sync(0xffffffffu, mt, 2));
            float psum = 0.f;
#pragma unroll
            for (int jj = 0; jj < 16; jj++) {
                float p = __expf(row[jj] - mt);
                row[jj] = p;
                psum += p;
            }
            psum += __shfl_xor_sync(0xffffffffu, psum, 1);
            psum += __shfl_xor_sync(0xffffffffu, psum, 2);
            if ((tid & 3) == 0) {
                float scale = __expf(mold - mt);
                sScale[r] = scale;
                sSum[r] = sSum[r] * scale + psum;
                sMax[r] = mt;
            }
        }
        __syncthreads();

        {
            float sc[4];
#pragma unroll
            for (int i = 0; i < 4; i++) sc[i] = sScale[tq + 16 * i];
#pragma unroll
            for (int i = 0; i < 4; i++)
#pragma unroll
                for (int j = 0; j < 4; j++)
                    acc[i][j] *= sc[i];
#pragma unroll 8
            for (int k = 0; k < 64; k++) {
                float pv[4], vv[4];
#pragma unroll
                for (int i = 0; i < 4; i++) pv[i] = sS[(tq + 16 * i) * ST + k];
#pragma unroll
                for (int j = 0; j < 4; j++) vv[j] = sV[k * ST + tj + 16 * j];
#pragma unroll
                for (int i = 0; i < 4; i++)
#pragma unroll
                    for (int j = 0; j < 4; j++)
                        acc[i][j] += pv[i] * vv[j];
            }
        }
    }

#pragma unroll
    for (int i = 0; i < 4; i++) {
        int r = tq + 16 * i;
        float inv = 1.0f / sSum[r];
        size_t orow = (size_t)(rowbase + qt * 64 + r);
#pragma unroll
        for (int j = 0; j < 4; j++) {
            float v = acc[i][j] * inv;
            __nv_bfloat16 hi = __float2bfloat16(v);
            __nv_bfloat16 lo = __float2bfloat16(v - __bfloat162float(hi));
            ohi[orow * CC + h * DD + tj + 16 * j] = hi;
            olo[orow * CC + h * DD + tj + 16 * j] = lo;
        }
    }
}

// ---------------- launch ----------------
extern "C" void kernel_launch(void* const* d_in, const int* in_sizes, int n_in,
                              void* d_out, int out_size)
{
    const float* x     = (const float*)d_in[0];
    const float* ln1_g = (const float*)d_in[1];
    const float* ln1_b = (const float*)d_in[2];
    const float* qkv_w = (const float*)d_in[3];
    const float* qkv_b = (const float*)d_in[4];
    const float* out_w = (const float*)d_in[5];
    const float* out_b = (const float*)d_in[6];
    const float* ln2_g = (const float*)d_in[7];
    const float* ln2_b = (const float*)d_in[8];
    const float* ff1_w = (const float*)d_in[9];
    const float* ff1_b = (const float*)d_in[10];
    const float* ff2_w = (const float*)d_in[11];
    const float* ff2_b = (const float*)d_in[12];
    float* y = (float*)d_out;

    float *p_qkv, *p_x1;
    __nv_bfloat16 *p_hhi, *p_hlo, *p_ahi, *p_alo, *p_fhi, *p_flo;
    __nv_bfloat16 *p_wqh, *p_wql, *p_woh, *p_wol, *p_w1h, *p_w1l, *p_w2h, *p_w2l;
    cudaGetSymbolAddress((void**)&p_qkv, g_qkv);
    cudaGetSymbolAddress((void**)&p_x1,  g_x1);
    cudaGetSymbolAddress((void**)&p_hhi, g_hhi);
    cudaGetSymbolAddress((void**)&p_hlo, g_hlo);
    cudaGetSymbolAddress((void**)&p_ahi, g_ahi);
    cudaGetSymbolAddress((void**)&p_alo, g_alo);
    cudaGetSymbolAddress((void**)&p_fhi, g_fhi);
    cudaGetSymbolAddress((void**)&p_flo, g_flo);
    cudaGetSymbolAddress((void**)&p_wqh, g_wqkv_hi);
    cudaGetSymbolAddress((void**)&p_wql, g_wqkv_lo);
    cudaGetSymbolAddress((void**)&p_woh, g_wout_hi);
    cudaGetSymbolAddress((void**)&p_wol, g_wout_lo);
    cudaGetSymbolAddress((void**)&p_w1h, g_wff1_hi);
    cudaGetSymbolAddress((void**)&p_w1l, g_wff1_lo);
    cudaGetSymbolAddress((void**)&p_w2h, g_wff2_hi);
    cudaGetSymbolAddress((void**)&p_w2l, g_wff2_lo);

    const int ATTN_SMEM = (4 * 64 * ST + 192) * 4;
    cudaFuncSetAttribute(attn_kernel, cudaFuncAttributeMaxDynamicSharedMemorySize, ATTN_SMEM);
    cudaFuncSetAttribute(gemm_mma<0>, cudaFuncAttributeMaxDynamicSharedMemorySize, GSMEM_TOTAL);
    cudaFuncSetAttribute(gemm_mma<1>, cudaFuncAttributeMaxDynamicSharedMemorySize, GSMEM_TOTAL);
    cudaFuncSetAttribute(gemm_mma<2>, cudaFuncAttributeMaxDynamicSharedMemorySize, GSMEM_TOTAL);

    // weight transpose + split (weights are inputs; redo every call)
    wsplit_kernel<<<dim3(QKVC / 32, CC / 32), dim3(32, 8)>>>(qkv_w, p_wqh, p_wql, CC, QKVC);
    wsplit_kernel<<<dim3(CC / 32,  CC / 32), dim3(32, 8)>>>(out_w, p_woh, p_wol, CC, CC);
    wsplit_kernel<<<dim3(FF / 32,  CC / 32), dim3(32, 8)>>>(ff1_w, p_w1h, p_w1l, CC, FF);
    wsplit_kernel<<<dim3(CC / 32,  FF / 32), dim3(32, 8)>>>(ff2_w, p_w2h, p_w2l, FF, CC);

    // 1) h = LN1(x) -> split
    ln_kernel<<<MM, 256>>>(x, ln1_g, ln1_b, p_hhi, p_hlo);
    // 2) qkv = h @ qkv_w + qkv_b  (fp32 out)
    gemm_mma<0><<<dim3(QKVC / 128, MM / 128), 256, GSMEM_TOTAL>>>(
        p_hhi, p_hlo, p_wqh, p_wql, qkv_b, nullptr, p_qkv, nullptr, nullptr, CC, QKVC);
    // 3) attention -> split
    attn_kernel<<<dim3(TT / 64, HH, BB), 256, ATTN_SMEM>>>(p_qkv, p_ahi, p_alo);
    // 4) x1 = x + att @ out_w + out_b
    gemm_mma<1><<<dim3(CC / 128, MM / 128), 256, GSMEM_TOTAL>>>(
        p_ahi, p_alo, p_woh, p_wol, out_b, x, p_x1, nullptr, nullptr, CC, CC);
    // 5) h = LN2(x1) -> split
    ln_kernel<<<MM, 256>>>(p_x1, ln2_g, ln2_b, p_hhi, p_hlo);
    // 6) ff = gelu(h @ ff1_w + ff1_b) -> split
    gemm_mma<2><<<dim3(FF / 128, MM / 128), 256, GSMEM_TOTAL>>>(
        p_hhi, p_hlo, p_w1h, p_w1l, ff1_b, nullptr, nullptr, p_fhi, p_flo, CC, FF);
    // 7) y = x1 + ff @ ff2_w + ff2_b
    gemm_mma<1><<<dim3(CC / 128, MM / 128), 256, GSMEM_TOTAL>>>(
        p_fhi, p_flo, p_w2h, p_w2l, ff2_b, p_x1, y, nullptr, nullptr, FF, CC);
}

// round 5
// speedup vs baseline: 4.9392x; 1.3816x over previous
#include <cuda_runtime.h>
#include <cuda_bf16.h>
#include <math.h>
#include <stdint.h>

// ---------------- problem constants ----------------
#define BB   2
#define TT   2048
#define CC   1024
#define HH   16
#define DD   64
#define FF   4096
#define MM   (BB*TT)          // 4096 rows
#define QKVC (3*CC)           // 3072

// ---------------- scratch (device globals; no allocs allowed) ----------------
__device__ float g_x1 [MM*CC];                   // residual stream after attn
__device__ alignas(128) __nv_bfloat16 g_hhi[MM*CC], g_hlo[MM*CC];   // LN out split
__device__ alignas(128) __nv_bfloat16 g_qhi[MM*QKVC], g_qlo[MM*QKVC]; // qkv split
__device__ alignas(128) __nv_bfloat16 g_ahi[MM*CC], g_alo[MM*CC];   // attn out split
__device__ alignas(128) __nv_bfloat16 g_fhi[MM*FF], g_flo[MM*FF];   // gelu out split
// transposed split weights: Wt[n][k]
__device__ alignas(128) __nv_bfloat16 g_wqkv_hi[CC*QKVC], g_wqkv_lo[CC*QKVC];
__device__ alignas(128) __nv_bfloat16 g_wout_hi[CC*CC],   g_wout_lo[CC*CC];
__device__ alignas(128) __nv_bfloat16 g_wff1_hi[CC*FF],   g_wff1_lo[CC*FF];
__device__ alignas(128) __nv_bfloat16 g_wff2_hi[FF*CC],   g_wff2_lo[FF*CC];

// ================= helpers =================
__device__ __forceinline__ uint32_t smem_to_u32(const void* p) {
    uint32_t a;
    asm("{ .reg .u64 t; cvta.to.shared.u64 t, %1; cvt.u32.u64 %0, t; }" : "=r"(a) : "l"(p));
    return a;
}
#define CP_ASYNC16(dst, src) \
    asm volatile("cp.async.cg.shared.global [%0], [%1], 16;" :: "r"(dst), "l"(src))
#define CP_COMMIT() asm volatile("cp.async.commit_group;" ::: "memory")
#define CP_WAIT(n)  asm volatile("cp.async.wait_group %0;" :: "n"(n) : "memory")

__device__ __forceinline__ void ldsm4(uint32_t* r, uint32_t addr) {
    asm volatile("ldmatrix.sync.aligned.m8n8.x4.shared.b16 {%0,%1,%2,%3}, [%4];"
                 : "=r"(r[0]), "=r"(r[1]), "=r"(r[2]), "=r"(r[3]) : "r"(addr));
}
__device__ __forceinline__ void ldsm4t(uint32_t* r, uint32_t addr) {
    asm volatile("ldmatrix.sync.aligned.m8n8.x4.trans.shared.b16 {%0,%1,%2,%3}, [%4];"
                 : "=r"(r[0]), "=r"(r[1]), "=r"(r[2]), "=r"(r[3]) : "r"(addr));
}
__device__ __forceinline__ void mma16816(float* c, const uint32_t* a, const uint32_t* b) {
    asm volatile("mma.sync.aligned.m16n8k16.row.col.f32.bf16.bf16.f32 "
                 "{%0,%1,%2,%3}, {%4,%5,%6,%7}, {%8,%9}, {%0,%1,%2,%3};"
                 : "+f"(c[0]), "+f"(c[1]), "+f"(c[2]), "+f"(c[3])
                 : "r"(a[0]), "r"(a[1]), "r"(a[2]), "r"(a[3]), "r"(b[0]), "r"(b[1]));
}
// pack two floats into bf16x2 (x0 -> low), and the bf16 residuals into lo
__device__ __forceinline__ uint32_t split_pack(float x0, float x1, uint32_t& lo) {
    __nv_bfloat16 h0 = __float2bfloat16(x0), h1 = __float2bfloat16(x1);
    __nv_bfloat16 l0 = __float2bfloat16(x0 - __bfloat162float(h0));
    __nv_bfloat16 l1 = __float2bfloat16(x1 - __bfloat162float(h1));
    lo = ((uint32_t)__bfloat16_as_ushort(l1) << 16) | __bfloat16_as_ushort(l0);
    return ((uint32_t)__bfloat16_as_ushort(h1) << 16) | __bfloat16_as_ushort(h0);
}

// ================= weight transpose + bf16 split =================
__global__ void __launch_bounds__(256) wsplit_kernel(const float* __restrict__ W,
                                                     __nv_bfloat16* __restrict__ Whi,
                                                     __nv_bfloat16* __restrict__ Wlo,
                                                     int K, int N)
{
    __shared__ float t[32][33];
    int tx = threadIdx.x, ty = threadIdx.y;   // block (32,8)
    int n0 = blockIdx.x * 32, k0 = blockIdx.y * 32;
#pragma unroll
    for (int i = 0; i < 4; i++)
        t[ty + 8 * i][tx] = W[(size_t)(k0 + ty + 8 * i) * N + n0 + tx];
    __syncthreads();
#pragma unroll
    for (int i = 0; i < 4; i++) {
        int n = n0 + ty + 8 * i, k = k0 + tx;
        float v = t[tx][ty + 8 * i];
        __nv_bfloat16 hi = __float2bfloat16(v);
        __nv_bfloat16 lo = __float2bfloat16(v - __bfloat162float(hi));
        Whi[(size_t)n * K + k] = hi;
        Wlo[(size_t)n * K + k] = lo;
    }
}

// ================= LayerNorm with split-bf16 output =================
__global__ void __launch_bounds__(256) ln_kernel(const float* __restrict__ x,
                                                 const float* __restrict__ g,
                                                 const float* __restrict__ b,
                                                 __nv_bfloat16* __restrict__ yhi,
                                                 __nv_bfloat16* __restrict__ ylo)
{
    int row = blockIdx.x;
    const float* xr = x + (size_t)row * CC;
    int tid = threadIdx.x;

    float v[4];
    float s1 = 0.f, s2 = 0.f;
#pragma unroll
    for (int i = 0; i < 4; i++) {
        v[i] = xr[tid + i * 256];
        s1 += v[i];
        s2 += v[i] * v[i];
    }
#pragma unroll
    for (int o = 16; o; o >>= 1) {
        s1 += __shfl_xor_sync(0xffffffffu, s1, o);
        s2 += __shfl_xor_sync(0xffffffffu, s2, o);
    }
    __shared__ float r1[8], r2[8], sh_mean, sh_rstd;
    if ((tid & 31) == 0) { r1[tid >> 5] = s1; r2[tid >> 5] = s2; }
    __syncthreads();
    if (tid == 0) {
        float t1 = 0.f, t2 = 0.f;
#pragma unroll
        for (int i = 0; i < 8; i++) { t1 += r1[i]; t2 += r2[i]; }
        float mean = t1 * (1.0f / CC);
        float var  = t2 * (1.0f / CC) - mean * mean;
        sh_mean = mean;
        sh_rstd = rsqrtf(var + 1e-5f);
    }
    __syncthreads();
    float mean = sh_mean, rstd = sh_rstd;
#pragma unroll
    for (int i = 0; i < 4; i++) {
        int c = tid + i * 256;
        float o = (v[i] - mean) * rstd * g[c] + b[c];
        __nv_bfloat16 hi = __float2bfloat16(o);
        __nv_bfloat16 lo = __float2bfloat16(o - __bfloat162float(hi));
        yhi[(size_t)row * CC + c] = hi;
        ylo[(size_t)row * CC + c] = lo;
    }
}

// ================= mma.sync GEMM (split-bf16, 3 terms) =================
// E: 1 = fp32 out (+bias+res); 2 = gelu -> split bf16; 3 = split bf16 (+bias).
#define GS 4
#define SSTRIDE 40                         // halves per row
#define ATILE_BYTES (128*SSTRIDE*2)        // 10240
#define STAGE_BYTES (2*ATILE_BYTES)        // 20480
#define GSMEM_TOTAL (GS*STAGE_BYTES)       // 81920

template<int E>
__global__ void __launch_bounds__(256) gemm_mma(const __nv_bfloat16* __restrict__ Ahi,
                                                const __nv_bfloat16* __restrict__ Alo,
                                                const __nv_bfloat16* __restrict__ Bhi,
                                                const __nv_bfloat16* __restrict__ Blo,
                                                const float* __restrict__ bias,
                                                const float* __restrict__ res,
                                                float* __restrict__ outf,
                                                __nv_bfloat16* __restrict__ outhi,
                                                __nv_bfloat16* __restrict__ outlo,
                                                int K, int gN)
{
    extern __shared__ char smem[];
    uint32_t sbase = smem_to_u32(smem);
    int tid = threadIdx.x, lane = tid & 31, wid = tid >> 5;
    int bx = blockIdx.x, by = blockIdx.y;
    const int NK = K >> 5;
    const int NC = 3 * NK;
    int m0 = (wid & 3) * 32, n0 = (wid >> 2) * 64;

    const __nv_bfloat16* AhiB = Ahi + (size_t)(by * 128) * K;
    const __nv_bfloat16* AloB = Alo + (size_t)(by * 128) * K;
    const __nv_bfloat16* BhiB = Bhi + (size_t)(bx * 128) * K;
    const __nv_bfloat16* BloB = Blo + (size_t)(bx * 128) * K;

    int u = tid & 3;        // 16B unit within 64B row-chunk
    int r0 = tid >> 2;      // 0..63

    auto issue = [&](int c) {
        int seg = (c >= 2 * NK) ? 2 : (c >= NK ? 1 : 0);
        int kk = c - seg * NK;
        const __nv_bfloat16* As = (seg == 1) ? AloB : AhiB;
        const __nv_bfloat16* Bs = (seg == 2) ? BloB : BhiB;
        uint32_t stA = sbase + (c & (GS - 1)) * STAGE_BYTES;
        uint32_t stB = stA + ATILE_BYTES;
#pragma unroll
        for (int rr = 0; rr < 2; rr++) {
            int r = r0 + rr * 64;
            const void* ga = As + (size_t)r * K + kk * 32 + u * 8;
            const void* gb = Bs + (size_t)r * K + kk * 32 + u * 8;
            CP_ASYNC16(stA + (r * SSTRIDE + u * 8) * 2, ga);
            CP_ASYNC16(stB + (r * SSTRIDE + u * 8) * 2, gb);
        }
        CP_COMMIT();
    };

    float acc[2][8][4] = {};

    for (int c = 0; c < GS - 1; c++) issue(c);

    for (int c = 0; c < NC; c++) {
        CP_WAIT(GS - 2);          // stage c complete
        __syncthreads();          // all warps done reading stage (c-1)
        if (c + GS - 1 < NC) issue(c + GS - 1); else CP_COMMIT();

        uint32_t aB = sbase + (c & (GS - 1)) * STAGE_BYTES;
        uint32_t bB = aB + ATILE_BYTES;
#pragma unroll
        for (int kh = 0; kh < 2; kh++) {
            uint32_t a[2][4];
#pragma unroll
            for (int i = 0; i < 2; i++) {
                int row = m0 + i * 16 + (lane & 15);
                int col = kh * 16 + (lane >> 4) * 8;
                ldsm4(a[i], aB + (row * SSTRIDE + col) * 2);
            }
            uint32_t b[4][4];
#pragma unroll
            for (int g = 0; g < 4; g++) {
                int nrow = n0 + g * 16 + (lane & 7) + ((lane >> 4) & 1) * 8;
                int col = kh * 16 + ((lane >> 3) & 1) * 8;
                ldsm4(b[g], bB + (nrow * SSTRIDE + col) * 2);
            }
#pragma unroll
            for (int i = 0; i < 2; i++)
#pragma unroll
                for (int g = 0; g < 4; g++) {
                    mma16816(acc[i][g * 2 + 0], a[i], &b[g][0]);
                    mma16816(acc[i][g * 2 + 1], a[i], &b[g][2]);
                }
        }
    }

    // epilogue from registers
    int mb = by * 128 + m0;
    int nb = bx * 128 + n0;
#pragma unroll
    for (int i = 0; i < 2; i++) {
#pragma unroll
        for (int j = 0; j < 8; j++) {
            float* cc = acc[i][j];
            int n = nb + j * 8 + (lane & 3) * 2;
            float b0 = bias[n], b1 = bias[n + 1];
#pragma unroll
            for (int hrow = 0; hrow < 2; hrow++) {
                int m = mb + i * 16 + (lane >> 2) + hrow * 8;
                float v0 = cc[hrow * 2 + 0] + b0;
                float v1 = cc[hrow * 2 + 1] + b1;
                size_t off = (size_t)m * gN + n;
                if (E == 1) {
                    float2 rv = *(const float2*)(res + off);
                    v0 += rv.x; v1 += rv.y;
                    float2 ov; ov.x = v0; ov.y = v1;
                    *(float2*)(outf + off) = ov;
                } else {
                    if (E == 2) {
                        v0 = 0.5f * v0 * (1.0f + erff(v0 * 0.70710678118654752f));
                        v1 = 0.5f * v1 * (1.0f + erff(v1 * 0.70710678118654752f));
                    }
                    uint32_t lo, hi = split_pack(v0, v1, lo);
                    *(uint32_t*)(outhi + off) = hi;
                    *(uint32_t*)(outlo + off) = lo;
                }
            }
        }
    }
}

// ================= FA2 tensor-core attention =================
// Block: 128 threads (4 warps), 64-query tile; warp w owns rows 16w..16w+15.
// S = Qhi*Khi + Qlo*Khi + Qhi*Klo ; PV = Phi*Vhi + Plo*Vhi + Phi*Vlo.
// K frags: non-trans ldsm on [j][d]; V frags: trans ldsm on [j][d].
#define AST 72        // smem row stride in halves
#define ASMEM (6 * 64 * AST * 2)   // 55296 bytes

__global__ void __launch_bounds__(128) attn_fa2(const __nv_bfloat16* __restrict__ qh_g,
                                                const __nv_bfloat16* __restrict__ ql_g,
                                                __nv_bfloat16* __restrict__ ohi,
                                                __nv_bfloat16* __restrict__ olo)
{
    extern __shared__ __nv_bfloat16 sb[];
    __nv_bfloat16* sQh = sb;
    __nv_bfloat16* sQl = sQh + 64 * AST;
    __nv_bfloat16* sKh = sQl + 64 * AST;
    __nv_bfloat16* sKl = sKh + 64 * AST;
    __nv_bfloat16* sVh = sKl + 64 * AST;
    __nv_bfloat16* sVl = sVh + 64 * AST;
    uint32_t uQh = smem_to_u32(sQh), uQl = smem_to_u32(sQl);
    uint32_t uKh = smem_to_u32(sKh), uKl = smem_to_u32(sKl);
    uint32_t uVh = smem_to_u32(sVh), uVl = smem_to_u32(sVl);

    int tid = threadIdx.x, lane = tid & 31, w = tid >> 5;
    int qt = gridDim.x - 1 - blockIdx.x;       // heavy tiles first
    int h = blockIdx.y, b = blockIdx.z;
    size_t qbase = ((size_t)(b * TT + qt * 64)) * QKVC + h * DD;

    // load Q hi/lo into smem
    {
        int r0 = tid >> 3, uu = tid & 7;
#pragma unroll
        for (int rep = 0; rep < 4; rep++) {
            int r = r0 + rep * 16;
            *(uint4*)(sQh + r * AST + uu * 8) = *(const uint4*)(qh_g + qbase + (size_t)r * QKVC + uu * 8);
            *(uint4*)(sQl + r * AST + uu * 8) = *(const uint4*)(ql_g + qbase + (size_t)r * QKVC + uu * 8);
        }
    }
    __syncthreads();

    // Q fragments (held in regs for whole kernel)
    uint32_t qh[4][4], ql[4][4];
#pragma unroll
    for (int ks = 0; ks < 4; ks++) {
        uint32_t off = ((16 * w + (lane & 15)) * AST + ks * 16 + (lane >> 4) * 8) * 2;
        ldsm4(qh[ks], uQh + off);
        ldsm4(ql[ks], uQl + off);
    }

    float m0r = -1e30f, m1r = -1e30f;
    float l0r = 0.f, l1r = 0.f;
    float oacc[8][4] = {};

    for (int kt = 0; kt <= qt; kt++) {
        size_t kbase = ((size_t)(b * TT + kt * 64)) * QKVC + CC + h * DD;
        size_t vbase = kbase + CC;
        __syncthreads();          // previous iter's ldsm reads done
        {
            int r0 = tid >> 3, uu = tid & 7;
#pragma unroll
            for (int rep = 0; rep < 4; rep++) {
                int r = r0 + rep * 16;
                size_t go = (size_t)r * QKVC + uu * 8;
                int so = r * AST + uu * 8;
                *(uint4*)(sKh + so) = *(const uint4*)(qh_g + kbase + go);
                *(uint4*)(sKl + so) = *(const uint4*)(ql_g + kbase + go);
                *(uint4*)(sVh + so) = *(const uint4*)(qh_g + vbase + go);
                *(uint4*)(sVl + so) = *(const uint4*)(ql_g + vbase + go);
            }
        }
        __syncthreads();

        // ---- S = QK^T (3 terms) ----
        float sacc[8][4] = {};
#pragma unroll
        for (int ks = 0; ks < 4; ks++) {
            uint32_t kb[4][4];
            uint32_t boff = ((lane & 7) + ((lane >> 4) & 1) * 8) * AST + ks * 16 + ((lane >> 3) & 1) * 8;
#pragma unroll
            for (int g = 0; g < 4; g++) ldsm4(kb[g], uKh + (boff + g * 16 * AST) * 2);
#pragma unroll
            for (int g = 0; g < 4; g++) {
                mma16816(sacc[g * 2 + 0], qh[ks], &kb[g][0]);
                mma16816(sacc[g * 2 + 1], qh[ks], &kb[g][2]);
                mma16816(sacc[g * 2 + 0], ql[ks], &kb[g][0]);
                mma16816(sacc[g * 2 + 1], ql[ks], &kb[g][2]);
            }
#pragma unroll
            for (int g = 0; g < 4; g++) ldsm4(kb[g], uKl + (boff + g * 16 * AST) * 2);
#pragma unroll
            for (int g = 0; g < 4; g++) {
                mma16816(sacc[g * 2 + 0], qh[ks], &kb[g][0]);
                mma16816(sacc[g * 2 + 1], qh[ks], &kb[g][2]);
            }
        }

        // ---- scale, mask, online softmax (in-register) ----
        int rl0 = w * 16 + (lane >> 2);     // tile-local q row of c0,c1
        int rl1 = rl0 + 8;
        float mn0 = m0r, mn1 = m1r;
#pragma unroll
        for (int t = 0; t < 8; t++) {
            sacc[t][0] *= 0.125f; sacc[t][1] *= 0.125f;
            sacc[t][2] *= 0.125f; sacc[t][3] *= 0.125f;
            if (kt == qt) {
                int col = t * 8 + 2 * (lane & 3);
                if (col     > rl0) sacc[t][0] = -1e30f;
                if (col + 1 > rl0) sacc[t][1] = -1e30f;
                if (col     > rl1) sacc[t][2] = -1e30f;
                if (col + 1 > rl1) sacc[t][3] = -1e30f;
            }
            mn0 = fmaxf(mn0, fmaxf(sacc[t][0], sacc[t][1]));
            mn1 = fmaxf(mn1, fmaxf(sacc[t][2], sacc[t][3]));
        }
        mn0 = fmaxf(mn0, __shfl_xor_sync(0xffffffffu, mn0, 1));
        mn0 = fmaxf(mn0, __shfl_xor_sync(0xffffffffu, mn0, 2));
        mn1 = fmaxf(mn1, __shfl_xor_sync(0xffffffffu, mn1, 1));
        mn1 = fmaxf(mn1, __shfl_xor_sync(0xffffffffu, mn1, 2));
        float es0 = __expf(m0r - mn0), es1 = __expf(m1r - mn1);
        m0r = mn0; m1r = mn1;
        float rs0 = 0.f, rs1 = 0.f;
#pragma unroll
        for (int t = 0; t < 8; t++) {
            sacc[t][0] = __expf(sacc[t][0] - mn0);
            sacc[t][1] = __expf(sacc[t][1] - mn0);
            sacc[t][2] = __expf(sacc[t][2] - mn1);
            sacc[t][3] = __expf(sacc[t][3] - mn1);
            rs0 += sacc[t][0] + sacc[t][1];
            rs1 += sacc[t][2] + sacc[t][3];
        }
        rs0 += __shfl_xor_sync(0xffffffffu, rs0, 1);
        rs0 += __shfl_xor_sync(0xffffffffu, rs0, 2);
        rs1 += __shfl_xor_sync(0xffffffffu, rs1, 1);
        rs1 += __shfl_xor_sync(0xffffffffu, rs1, 2);
        l0r = l0r * es0 + rs0;
        l1r = l1r * es1 + rs1;
#pragma unroll
        for (int t = 0; t < 8; t++) {
            oacc[t][0] *= es0; oacc[t][1] *= es0;
            oacc[t][2] *= es1; oacc[t][3] *= es1;
        }

        // ---- PV (3 terms), P fragments repacked from sacc ----
#pragma unroll
        for (int ks = 0; ks < 4; ks++) {
            uint32_t pa[4], pl[4];
            pa[0] = split_pack(sacc[2 * ks][0],     sacc[2 * ks][1],     pl[0]);
            pa[1] = split_pack(sacc[2 * ks][2],     sacc[2 * ks][3],     pl[1]);
            pa[2] = split_pack(sacc[2 * ks + 1][0], sacc[2 * ks + 1][1], pl[2]);
            pa[3] = split_pack(sacc[2 * ks + 1][2], sacc[2 * ks + 1][3], pl[3]);

            uint32_t vb[4][4];
            uint32_t voff = (ks * 16 + (lane & 15)) * AST + ((lane >> 4) & 1) * 8;
#pragma unroll
            for (int g = 0; g < 4; g++) ldsm4t(vb[g], uVh + (voff + g * 16) * 2);
#pragma unroll
            for (int g = 0; g < 4; g++) {
                mma16816(oacc[g * 2 + 0], pa, &vb[g][0]);
                mma16816(oacc[g * 2 + 1], pa, &vb[g][2]);
                mma16816(oacc[g * 2 + 0], pl, &vb[g][0]);
                mma16816(oacc[g * 2 + 1], pl, &vb[g][2]);
            }
#pragma unroll
            for (int g = 0; g < 4; g++) ldsm4t(vb[g], uVl + (voff + g * 16) * 2);
#pragma unroll
            for (int g = 0; g < 4; g++) {
                mma16816(oacc[g * 2 + 0], pa, &vb[g][0]);
                mma16816(oacc[g * 2 + 1], pa, &vb[g][2]);
            }
        }
    }

    // ---- finalize & split-store ----
    float inv0 = 1.0f / l0r, inv1 = 1.0f / l1r;
    size_t r0g = (size_t)(b * TT + qt * 64 + w * 16 + (lane >> 2));
    size_t obase0 = r0g * CC + h * DD;
    size_t obase1 = (r0g + 8) * CC + h * DD;
#pragma unroll
    for (int t = 0; t < 8; t++) {
        int d = t * 8 + 2 * (lane & 3);
        uint32_t lo, hi;
        hi = split_pack(oacc[t][0] * inv0, oacc[t][1] * inv0, lo);
        *(uint32_t*)(ohi + obase0 + d) = hi;
        *(uint32_t*)(olo + obase0 + d) = lo;
        hi = split_pack(oacc[t][2] * inv1, oacc[t][3] * inv1, lo);
        *(uint32_t*)(ohi + obase1 + d) = hi;
        *(uint32_t*)(olo + obase1 + d) = lo;
    }
}

// ---------------- launch ----------------
extern "C" void kernel_launch(void* const* d_in, const int* in_sizes, int n_in,
                              void* d_out, int out_size)
{
    const float* x     = (const float*)d_in[0];
    const float* ln1_g = (const float*)d_in[1];
    const float* ln1_b = (const float*)d_in[2];
    const float* qkv_w = (const float*)d_in[3];
    const float* qkv_b = (const float*)d_in[4];
    const float* out_w = (const float*)d_in[5];
    const float* out_b = (const float*)d_in[6];
    const float* ln2_g = (const float*)d_in[7];
    const float* ln2_b = (const float*)d_in[8];
    const float* ff1_w = (const float*)d_in[9];
    const float* ff1_b = (const float*)d_in[10];
    const float* ff2_w = (const float*)d_in[11];
    const float* ff2_b = (const float*)d_in[12];
    float* y = (float*)d_out;

    float *p_x1;
    __nv_bfloat16 *p_hhi, *p_hlo, *p_qhi, *p_qlo, *p_ahi, *p_alo, *p_fhi, *p_flo;
    __nv_bfloat16 *p_wqh, *p_wql, *p_woh, *p_wol, *p_w1h, *p_w1l, *p_w2h, *p_w2l;
    cudaGetSymbolAddress((void**)&p_x1,  g_x1);
    cudaGetSymbolAddress((void**)&p_hhi, g_hhi);
    cudaGetSymbolAddress((void**)&p_hlo, g_hlo);
    cudaGetSymbolAddress((void**)&p_qhi, g_qhi);
    cudaGetSymbolAddress((void**)&p_qlo, g_qlo);
    cudaGetSymbolAddress((void**)&p_ahi, g_ahi);
    cudaGetSymbolAddress((void**)&p_alo, g_alo);
    cudaGetSymbolAddress((void**)&p_fhi, g_fhi);
    cudaGetSymbolAddress((void**)&p_flo, g_flo);
    cudaGetSymbolAddress((void**)&p_wqh, g_wqkv_hi);
    cudaGetSymbolAddress((void**)&p_wql, g_wqkv_lo);
    cudaGetSymbolAddress((void**)&p_woh, g_wout_hi);
    cudaGetSymbolAddress((void**)&p_wol, g_wout_lo);
    cudaGetSymbolAddress((void**)&p_w1h, g_wff1_hi);
    cudaGetSymbolAddress((void**)&p_w1l, g_wff1_lo);
    cudaGetSymbolAddress((void**)&p_w2h, g_wff2_hi);
    cudaGetSymbolAddress((void**)&p_w2l, g_wff2_lo);

    cudaFuncSetAttribute(attn_fa2, cudaFuncAttributeMaxDynamicSharedMemorySize, ASMEM);
    cudaFuncSetAttribute(gemm_mma<1>, cudaFuncAttributeMaxDynamicSharedMemorySize, GSMEM_TOTAL);
    cudaFuncSetAttribute(gemm_mma<2>, cudaFuncAttributeMaxDynamicSharedMemorySize, GSMEM_TOTAL);
    cudaFuncSetAttribute(gemm_mma<3>, cudaFuncAttributeMaxDynamicSharedMemorySize, GSMEM_TOTAL);

    // weight transpose + split
    wsplit_kernel<<<dim3(QKVC / 32, CC / 32), dim3(32, 8)>>>(qkv_w, p_wqh, p_wql, CC, QKVC);
    wsplit_kernel<<<dim3(CC / 32,  CC / 32), dim3(32, 8)>>>(out_w, p_woh, p_wol, CC, CC);
    wsplit_kernel<<<dim3(FF / 32,  CC / 32), dim3(32, 8)>>>(ff1_w, p_w1h, p_w1l, CC, FF);
    wsplit_kernel<<<dim3(CC / 32,  FF / 32), dim3(32, 8)>>>(ff2_w, p_w2h, p_w2l, FF, CC);

    // 1) h = LN1(x) -> split
    ln_kernel<<<MM, 256>>>(x, ln1_g, ln1_b, p_hhi, p_hlo);
    // 2) qkv = h @ qkv_w + qkv_b -> split bf16
    gemm_mma<3><<<dim3(QKVC / 128, MM / 128), 256, GSMEM_TOTAL>>>(
        p_hhi, p_hlo, p_wqh, p_wql, qkv_b, nullptr, nullptr, p_qhi, p_qlo, CC, QKVC);
    // 3) attention -> split
    attn_fa2<<<dim3(TT / 64, HH, BB), 128, ASMEM>>>(p_qhi, p_qlo, p_ahi, p_alo);
    // 4) x1 = x + att @ out_w + out_b
    gemm_mma<1><<<dim3(CC / 128, MM / 128), 256, GSMEM_TOTAL>>>(
        p_ahi, p_alo, p_woh, p_wol, out_b, x, p_x1, nullptr, nullptr, CC, CC);
    // 5) h = LN2(x1) -> split
    ln_kernel<<<MM, 256>>>(p_x1, ln2_g, ln2_b, p_hhi, p_hlo);
    // 6) ff = gelu(h @ ff1_w + ff1_b) -> split
    gemm_mma<2><<<dim3(FF / 128, MM / 128), 256, GSMEM_TOTAL>>>(
        p_hhi, p_hlo, p_w1h, p_w1l, ff1_b, nullptr, nullptr, p_fhi, p_flo, CC, FF);
    // 7) y = x1 + ff @ ff2_w + ff2_b
    gemm_mma<1><<<dim3(CC / 128, MM / 128), 256, GSMEM_TOTAL>>>(
        p_fhi, p_flo, p_w2h, p_w2l, ff2_b, p_x1, y, nullptr, nullptr, FF, CC);
}

// round 6
// speedup vs baseline: 5.0784x; 1.0282x over previous
#include <cuda_runtime.h>
#include <cuda_bf16.h>
#include <math.h>
#include <stdint.h>

// ---------------- problem constants ----------------
#define BB   2
#define TT   2048
#define CC   1024
#define HH   16
#define DD   64
#define FF   4096
#define MM   (BB*TT)          // 4096 rows
#define QKVC (3*CC)           // 3072

// ---------------- scratch (device globals; no allocs allowed) ----------------
__device__ float g_x1 [MM*CC];                   // residual stream after attn
__device__ alignas(128) __nv_bfloat16 g_hhi[MM*CC], g_hlo[MM*CC];   // LN out split
__device__ alignas(128) __nv_bfloat16 g_qhi[MM*QKVC], g_qlo[MM*QKVC]; // qkv split
__device__ alignas(128) __nv_bfloat16 g_ahi[MM*CC], g_alo[MM*CC];   // attn out split
__device__ alignas(128) __nv_bfloat16 g_fhi[MM*FF], g_flo[MM*FF];   // gelu out split
// transposed split weights: Wt[n][k]
__device__ alignas(128) __nv_bfloat16 g_wqkv_hi[CC*QKVC], g_wqkv_lo[CC*QKVC];
__device__ alignas(128) __nv_bfloat16 g_wout_hi[CC*CC],   g_wout_lo[CC*CC];
__device__ alignas(128) __nv_bfloat16 g_wff1_hi[CC*FF],   g_wff1_lo[CC*FF];
__device__ alignas(128) __nv_bfloat16 g_wff2_hi[FF*CC],   g_wff2_lo[FF*CC];

// ================= helpers =================
__device__ __forceinline__ uint32_t smem_to_u32(const void* p) {
    uint32_t a;
    asm("{ .reg .u64 t; cvta.to.shared.u64 t, %1; cvt.u32.u64 %0, t; }" : "=r"(a) : "l"(p));
    return a;
}
#define CP_ASYNC16(dst, src) \
    asm volatile("cp.async.cg.shared.global [%0], [%1], 16;" :: "r"(dst), "l"(src))
#define CP_COMMIT() asm volatile("cp.async.commit_group;" ::: "memory")
#define CP_WAIT(n)  asm volatile("cp.async.wait_group %0;" :: "n"(n) : "memory")

__device__ __forceinline__ void ldsm4(uint32_t* r, uint32_t addr) {
    asm volatile("ldmatrix.sync.aligned.m8n8.x4.shared.b16 {%0,%1,%2,%3}, [%4];"
                 : "=r"(r[0]), "=r"(r[1]), "=r"(r[2]), "=r"(r[3]) : "r"(addr));
}
__device__ __forceinline__ void ldsm4t(uint32_t* r, uint32_t addr) {
    asm volatile("ldmatrix.sync.aligned.m8n8.x4.trans.shared.b16 {%0,%1,%2,%3}, [%4];"
                 : "=r"(r[0]), "=r"(r[1]), "=r"(r[2]), "=r"(r[3]) : "r"(addr));
}
__device__ __forceinline__ void mma16816(float* c, const uint32_t* a, const uint32_t* b) {
    asm volatile("mma.sync.aligned.m16n8k16.row.col.f32.bf16.bf16.f32 "
                 "{%0,%1,%2,%3}, {%4,%5,%6,%7}, {%8,%9}, {%0,%1,%2,%3};"
                 : "+f"(c[0]), "+f"(c[1]), "+f"(c[2]), "+f"(c[3])
                 : "r"(a[0]), "r"(a[1]), "r"(a[2]), "r"(a[3]), "r"(b[0]), "r"(b[1]));
}
// pack two floats into bf16x2 (x0 -> low), and the bf16 residuals into lo
__device__ __forceinline__ uint32_t split_pack(float x0, float x1, uint32_t& lo) {
    __nv_bfloat16 h0 = __float2bfloat16(x0), h1 = __float2bfloat16(x1);
    __nv_bfloat16 l0 = __float2bfloat16(x0 - __bfloat162float(h0));
    __nv_bfloat16 l1 = __float2bfloat16(x1 - __bfloat162float(h1));
    lo = ((uint32_t)__bfloat16_as_ushort(l1) << 16) | __bfloat16_as_ushort(l0);
    return ((uint32_t)__bfloat16_as_ushort(h1) << 16) | __bfloat16_as_ushort(h0);
}

// ================= weight transpose + bf16 split =================
__global__ void __launch_bounds__(256) wsplit_kernel(const float* __restrict__ W,
                                                     __nv_bfloat16* __restrict__ Whi,
                                                     __nv_bfloat16* __restrict__ Wlo,
                                                     int K, int N)
{
    __shared__ float t[32][33];
    int tx = threadIdx.x, ty = threadIdx.y;   // block (32,8)
    int n0 = blockIdx.x * 32, k0 = blockIdx.y * 32;
#pragma unroll
    for (int i = 0; i < 4; i++)
        t[ty + 8 * i][tx] = W[(size_t)(k0 + ty + 8 * i) * N + n0 + tx];
    __syncthreads();
#pragma unroll
    for (int i = 0; i < 4; i++) {
        int n = n0 + ty + 8 * i, k = k0 + tx;
        float v = t[tx][ty + 8 * i];
        __nv_bfloat16 hi = __float2bfloat16(v);
        __nv_bfloat16 lo = __float2bfloat16(v - __bfloat162float(hi));
        Whi[(size_t)n * K + k] = hi;
        Wlo[(size_t)n * K + k] = lo;
    }
}

// ================= LayerNorm with split-bf16 output =================
__global__ void __launch_bounds__(256) ln_kernel(const float* __restrict__ x,
                                                 const float* __restrict__ g,
                                                 const float* __restrict__ b,
                                                 __nv_bfloat16* __restrict__ yhi,
                                                 __nv_bfloat16* __restrict__ ylo)
{
    int row = blockIdx.x;
    const float* xr = x + (size_t)row * CC;
    int tid = threadIdx.x;

    float v[4];
    float s1 = 0.f, s2 = 0.f;
#pragma unroll
    for (int i = 0; i < 4; i++) {
        v[i] = xr[tid + i * 256];
        s1 += v[i];
        s2 += v[i] * v[i];
    }
#pragma unroll
    for (int o = 16; o; o >>= 1) {
        s1 += __shfl_xor_sync(0xffffffffu, s1, o);
        s2 += __shfl_xor_sync(0xffffffffu, s2, o);
    }
    __shared__ float r1[8], r2[8], sh_mean, sh_rstd;
    if ((tid & 31) == 0) { r1[tid >> 5] = s1; r2[tid >> 5] = s2; }
    __syncthreads();
    if (tid == 0) {
        float t1 = 0.f, t2 = 0.f;
#pragma unroll
        for (int i = 0; i < 8; i++) { t1 += r1[i]; t2 += r2[i]; }
        float mean = t1 * (1.0f / CC);
        float var  = t2 * (1.0f / CC) - mean * mean;
        sh_mean = mean;
        sh_rstd = rsqrtf(var + 1e-5f);
    }
    __syncthreads();
    float mean = sh_mean, rstd = sh_rstd;
#pragma unroll
    for (int i = 0; i < 4; i++) {
        int c = tid + i * 256;
        float o = (v[i] - mean) * rstd * g[c] + b[c];
        __nv_bfloat16 hi = __float2bfloat16(o);
        __nv_bfloat16 lo = __float2bfloat16(o - __bfloat162float(hi));
        yhi[(size_t)row * CC + c] = hi;
        ylo[(size_t)row * CC + c] = lo;
    }
}

// ================= mma.sync GEMM (split-bf16, 3 terms) =================
// E: 1 = fp32 out (+bias+res); 2 = gelu -> split bf16; 3 = split bf16 (+bias).
#define GS 4
#define SSTRIDE 40                         // halves per row
#define ATILE_BYTES (128*SSTRIDE*2)        // 10240
#define STAGE_BYTES (2*ATILE_BYTES)        // 20480
#define GSMEM_TOTAL (GS*STAGE_BYTES)       // 81920

template<int E>
__global__ void __launch_bounds__(256, 2) gemm_mma(const __nv_bfloat16* __restrict__ Ahi,
                                                   const __nv_bfloat16* __restrict__ Alo,
                                                   const __nv_bfloat16* __restrict__ Bhi,
                                                   const __nv_bfloat16* __restrict__ Blo,
                                                   const float* __restrict__ bias,
                                                   const float* __restrict__ res,
                                                   float* __restrict__ outf,
                                                   __nv_bfloat16* __restrict__ outhi,
                                                   __nv_bfloat16* __restrict__ outlo,
                                                   int K, int gN)
{
    extern __shared__ char smem[];
    uint32_t sbase = smem_to_u32(smem);
    int tid = threadIdx.x, lane = tid & 31, wid = tid >> 5;
    int bx = blockIdx.x, by = blockIdx.y;
    const int NK = K >> 5;
    const int NC = 3 * NK;
    int m0 = (wid & 3) * 32, n0 = (wid >> 2) * 64;

    const __nv_bfloat16* AhiB = Ahi + (size_t)(by * 128) * K;
    const __nv_bfloat16* AloB = Alo + (size_t)(by * 128) * K;
    const __nv_bfloat16* BhiB = Bhi + (size_t)(bx * 128) * K;
    const __nv_bfloat16* BloB = Blo + (size_t)(bx * 128) * K;

    int u = tid & 3;        // 16B unit within 64B row-chunk
    int r0 = tid >> 2;      // 0..63

    auto issue = [&](int c) {
        int seg = (c >= 2 * NK) ? 2 : (c >= NK ? 1 : 0);
        int kk = c - seg * NK;
        const __nv_bfloat16* As = (seg == 1) ? AloB : AhiB;
        const __nv_bfloat16* Bs = (seg == 2) ? BloB : BhiB;
        uint32_t stA = sbase + (c & (GS - 1)) * STAGE_BYTES;
        uint32_t stB = stA + ATILE_BYTES;
#pragma unroll
        for (int rr = 0; rr < 2; rr++) {
            int r = r0 + rr * 64;
            const void* ga = As + (size_t)r * K + kk * 32 + u * 8;
            const void* gb = Bs + (size_t)r * K + kk * 32 + u * 8;
            CP_ASYNC16(stA + (r * SSTRIDE + u * 8) * 2, ga);
            CP_ASYNC16(stB + (r * SSTRIDE + u * 8) * 2, gb);
        }
        CP_COMMIT();
    };

    float acc[2][8][4] = {};

    for (int c = 0; c < GS - 1; c++) issue(c);

    for (int c = 0; c < NC; c++) {
        CP_WAIT(GS - 2);          // stage c complete
        __syncthreads();          // all warps done reading stage (c-1)
        if (c + GS - 1 < NC) issue(c + GS - 1); else CP_COMMIT();

        uint32_t aB = sbase + (c & (GS - 1)) * STAGE_BYTES;
        uint32_t bB = aB + ATILE_BYTES;
#pragma unroll
        for (int kh = 0; kh < 2; kh++) {
            uint32_t a[2][4];
#pragma unroll
            for (int i = 0; i < 2; i++) {
                int row = m0 + i * 16 + (lane & 15);
                int col = kh * 16 + (lane >> 4) * 8;
                ldsm4(a[i], aB + (row * SSTRIDE + col) * 2);
            }
            uint32_t b[4][4];
#pragma unroll
            for (int g = 0; g < 4; g++) {
                int nrow = n0 + g * 16 + (lane & 7) + ((lane >> 4) & 1) * 8;
                int col = kh * 16 + ((lane >> 3) & 1) * 8;
                ldsm4(b[g], bB + (nrow * SSTRIDE + col) * 2);
            }
#pragma unroll
            for (int i = 0; i < 2; i++)
#pragma unroll
                for (int g = 0; g < 4; g++) {
                    mma16816(acc[i][g * 2 + 0], a[i], &b[g][0]);
                    mma16816(acc[i][g * 2 + 1], a[i], &b[g][2]);
                }
        }
    }

    // epilogue from registers
    int mb = by * 128 + m0;
    int nb = bx * 128 + n0;
#pragma unroll
    for (int i = 0; i < 2; i++) {
#pragma unroll
        for (int j = 0; j < 8; j++) {
            float* cc = acc[i][j];
            int n = nb + j * 8 + (lane & 3) * 2;
            float b0 = bias[n], b1 = bias[n + 1];
#pragma unroll
            for (int hrow = 0; hrow < 2; hrow++) {
                int m = mb + i * 16 + (lane >> 2) + hrow * 8;
                float v0 = cc[hrow * 2 + 0] + b0;
                float v1 = cc[hrow * 2 + 1] + b1;
                size_t off = (size_t)m * gN + n;
                if (E == 1) {
                    float2 rv = *(const float2*)(res + off);
                    v0 += rv.x; v1 += rv.y;
                    float2 ov; ov.x = v0; ov.y = v1;
                    *(float2*)(outf + off) = ov;
                } else {
                    if (E == 2) {
                        v0 = 0.5f * v0 * (1.0f + erff(v0 * 0.70710678118654752f));
                        v1 = 0.5f * v1 * (1.0f + erff(v1 * 0.70710678118654752f));
                    }
                    uint32_t lo, hi = split_pack(v0, v1, lo);
                    *(uint32_t*)(outhi + off) = hi;
                    *(uint32_t*)(outlo + off) = lo;
                }
            }
        }
    }
}

// ================= FA2 tensor-core attention (cp.async double-buffered) =====
// Block: 128 threads (4 warps), 64-query tile; warp w owns rows 16w..16w+15.
// S = Qhi*Khi + Qlo*Khi + Qhi*Klo ; PV = Phi*Vhi + Plo*Vhi + Phi*Vlo.
#define AST 72        // smem row stride in halves
#define ATILE (64 * AST)                 // halves per tile
#define KVSTAGE (4 * ATILE)              // Kh,Kl,Vh,Vl
#define ASMEM ((2 * ATILE + 2 * KVSTAGE) * 2)   // 92160 bytes

__global__ void __launch_bounds__(128) attn_fa2(const __nv_bfloat16* __restrict__ qh_g,
                                                const __nv_bfloat16* __restrict__ ql_g,
                                                __nv_bfloat16* __restrict__ ohi,
                                                __nv_bfloat16* __restrict__ olo)
{
    extern __shared__ __nv_bfloat16 sb[];
    __nv_bfloat16* sQh = sb;
    __nv_bfloat16* sQl = sQh + ATILE;
    __nv_bfloat16* sKV = sQl + ATILE;    // 2 stages of [Kh|Kl|Vh|Vl]
    uint32_t uQh = smem_to_u32(sQh), uQl = smem_to_u32(sQl);
    uint32_t uKV = smem_to_u32(sKV);

    int tid = threadIdx.x, lane = tid & 31, w = tid >> 5;
    int qt = gridDim.x - 1 - blockIdx.x;       // heavy tiles first
    int h = blockIdx.y, b = blockIdx.z;
    size_t qbase = ((size_t)(b * TT + qt * 64)) * QKVC + h * DD;

    int r0 = tid >> 3, uu = tid & 7;

    // issue cp.async for K/V tiles (hi+lo) of kt into stage s
    auto issue_kv = [&](int kt, int s) {
        size_t kbase = ((size_t)(b * TT + kt * 64)) * QKVC + CC + h * DD;
        size_t vbase = kbase + CC;
        uint32_t st = uKV + s * KVSTAGE * 2;
#pragma unroll
        for (int rep = 0; rep < 4; rep++) {
            int r = r0 + rep * 16;
            size_t go = (size_t)r * QKVC + uu * 8;
            uint32_t so = (r * AST + uu * 8) * 2;
            CP_ASYNC16(st + so,                 qh_g + kbase + go);
            CP_ASYNC16(st + ATILE * 2 + so,     ql_g + kbase + go);
            CP_ASYNC16(st + ATILE * 4 + so,     qh_g + vbase + go);
            CP_ASYNC16(st + ATILE * 6 + so,     ql_g + vbase + go);
        }
        CP_COMMIT();
    };

    // load Q hi/lo into smem (plain loads) + prefetch kt=0
    issue_kv(0, 0);
#pragma unroll
    for (int rep = 0; rep < 4; rep++) {
        int r = r0 + rep * 16;
        *(uint4*)(sQh + r * AST + uu * 8) = *(const uint4*)(qh_g + qbase + (size_t)r * QKVC + uu * 8);
        *(uint4*)(sQl + r * AST + uu * 8) = *(const uint4*)(ql_g + qbase + (size_t)r * QKVC + uu * 8);
    }
    __syncthreads();

    // Q fragments (held in regs for whole kernel)
    uint32_t qh[4][4], ql[4][4];
#pragma unroll
    for (int ks = 0; ks < 4; ks++) {
        uint32_t off = ((16 * w + (lane & 15)) * AST + ks * 16 + (lane >> 4) * 8) * 2;
        ldsm4(qh[ks], uQh + off);
        ldsm4(ql[ks], uQl + off);
    }

    float m0r = -1e30f, m1r = -1e30f;
    float l0r = 0.f, l1r = 0.f;
    float oacc[8][4] = {};

    for (int kt = 0; kt <= qt; kt++) {
        int s = kt & 1;
        __syncthreads();                       // all reads of stage s (from kt-2) done
        if (kt + 1 <= qt) issue_kv(kt + 1, s ^ 1); else CP_COMMIT();
        CP_WAIT(1);                            // stage s (kt) arrived
        __syncthreads();

        uint32_t uKh = uKV + (s * KVSTAGE) * 2;
        uint32_t uKl = uKh + ATILE * 2;
        uint32_t uVh = uKh + ATILE * 4;
        uint32_t uVl = uKh + ATILE * 6;

        // ---- S = QK^T (3 terms) ----
        float sacc[8][4] = {};
#pragma unroll
        for (int ks = 0; ks < 4; ks++) {
            uint32_t kb[4][4];
            uint32_t boff = ((lane & 7) + ((lane >> 4) & 1) * 8) * AST + ks * 16 + ((lane >> 3) & 1) * 8;
#pragma unroll
            for (int g = 0; g < 4; g++) ldsm4(kb[g], uKh + (boff + g * 16 * AST) * 2);
#pragma unroll
            for (int g = 0; g < 4; g++) {
                mma16816(sacc[g * 2 + 0], qh[ks], &kb[g][0]);
                mma16816(sacc[g * 2 + 1], qh[ks], &kb[g][2]);
                mma16816(sacc[g * 2 + 0], ql[ks], &kb[g][0]);
                mma16816(sacc[g * 2 + 1], ql[ks], &kb[g][2]);
            }
#pragma unroll
            for (int g = 0; g < 4; g++) ldsm4(kb[g], uKl + (boff + g * 16 * AST) * 2);
#pragma unroll
            for (int g = 0; g < 4; g++) {
                mma16816(sacc[g * 2 + 0], qh[ks], &kb[g][0]);
                mma16816(sacc[g * 2 + 1], qh[ks], &kb[g][2]);
            }
        }

        // ---- scale, mask, online softmax (in-register) ----
        int rl0 = w * 16 + (lane >> 2);     // tile-local q row of c0,c1
        int rl1 = rl0 + 8;
        float mn0 = m0r, mn1 = m1r;
#pragma unroll
        for (int t = 0; t < 8; t++) {
            sacc[t][0] *= 0.125f; sacc[t][1] *= 0.125f;
            sacc[t][2] *= 0.125f; sacc[t][3] *= 0.125f;
            if (kt == qt) {
                int col = t * 8 + 2 * (lane & 3);
                if (col     > rl0) sacc[t][0] = -1e30f;
                if (col + 1 > rl0) sacc[t][1] = -1e30f;
                if (col     > rl1) sacc[t][2] = -1e30f;
                if (col + 1 > rl1) sacc[t][3] = -1e30f;
            }
            mn0 = fmaxf(mn0, fmaxf(sacc[t][0], sacc[t][1]));
            mn1 = fmaxf(mn1, fmaxf(sacc[t][2], sacc[t][3]));
        }
        mn0 = fmaxf(mn0, __shfl_xor_sync(0xffffffffu, mn0, 1));
        mn0 = fmaxf(mn0, __shfl_xor_sync(0xffffffffu, mn0, 2));
        mn1 = fmaxf(mn1, __shfl_xor_sync(0xffffffffu, mn1, 1));
        mn1 = fmaxf(mn1, __shfl_xor_sync(0xffffffffu, mn1, 2));
        float es0 = __expf(m0r - mn0), es1 = __expf(m1r - mn1);
        m0r = mn0; m1r = mn1;
        float rs0 = 0.f, rs1 = 0.f;
#pragma unroll
        for (int t = 0; t < 8; t++) {
            sacc[t][0] = __expf(sacc[t][0] - mn0);
            sacc[t][1] = __expf(sacc[t][1] - mn0);
            sacc[t][2] = __expf(sacc[t][2] - mn1);
            sacc[t][3] = __expf(sacc[t][3] - mn1);
            rs0 += sacc[t][0] + sacc[t][1];
            rs1 += sacc[t][2] + sacc[t][3];
        }
        rs0 += __shfl_xor_sync(0xffffffffu, rs0, 1);
        rs0 += __shfl_xor_sync(0xffffffffu, rs0, 2);
        rs1 += __shfl_xor_sync(0xffffffffu, rs1, 1);
        rs1 += __shfl_xor_sync(0xffffffffu, rs1, 2);
        l0r = l0r * es0 + rs0;
        l1r = l1r * es1 + rs1;
#pragma unroll
        for (int t = 0; t < 8; t++) {
            oacc[t][0] *= es0; oacc[t][1] *= es0;
            oacc[t][2] *= es1; oacc[t][3] *= es1;
        }

        // ---- PV (3 terms), P fragments repacked from sacc ----
#pragma unroll
        for (int ks = 0; ks < 4; ks++) {
            uint32_t pa[4], pl[4];
            pa[0] = split_pack(sacc[2 * ks][0],     sacc[2 * ks][1],     pl[0]);
            pa[1] = split_pack(sacc[2 * ks][2],     sacc[2 * ks][3],     pl[1]);
            pa[2] = split_pack(sacc[2 * ks + 1][0], sacc[2 * ks + 1][1], pl[2]);
            pa[3] = split_pack(sacc[2 * ks + 1][2], sacc[2 * ks + 1][3], pl[3]);

            uint32_t vb[4][4];
            uint32_t voff = (ks * 16 + (lane & 15)) * AST + ((lane >> 4) & 1) * 8;
#pragma unroll
            for (int g = 0; g < 4; g++) ldsm4t(vb[g], uVh + (voff + g * 16) * 2);
#pragma unroll
            for (int g = 0; g < 4; g++) {
                mma16816(oacc[g * 2 + 0], pa, &vb[g][0]);
                mma16816(oacc[g * 2 + 1], pa, &vb[g][2]);
                mma16816(oacc[g * 2 + 0], pl, &vb[g][0]);
                mma16816(oacc[g * 2 + 1], pl, &vb[g][2]);
            }
#pragma unroll
            for (int g = 0; g < 4; g++) ldsm4t(vb[g], uVl + (voff + g * 16) * 2);
#pragma unroll
            for (int g = 0; g < 4; g++) {
                mma16816(oacc[g * 2 + 0], pa, &vb[g][0]);
                mma16816(oacc[g * 2 + 1], pa, &vb[g][2]);
            }
        }
    }

    // ---- finalize & split-store ----
    float inv0 = 1.0f / l0r, inv1 = 1.0f / l1r;
    size_t r0g = (size_t)(b * TT + qt * 64 + w * 16 + (lane >> 2));
    size_t obase0 = r0g * CC + h * DD;
    size_t obase1 = (r0g + 8) * CC + h * DD;
#pragma unroll
    for (int t = 0; t < 8; t++) {
        int d = t * 8 + 2 * (lane & 3);
        uint32_t lo, hi;
        hi = split_pack(oacc[t][0] * inv0, oacc[t][1] * inv0, lo);
        *(uint32_t*)(ohi + obase0 + d) = hi;
        *(uint32_t*)(olo + obase0 + d) = lo;
        hi = split_pack(oacc[t][2] * inv1, oacc[t][3] * inv1, lo);
        *(uint32_t*)(ohi + obase1 + d) = hi;
        *(uint32_t*)(olo + obase1 + d) = lo;
    }
}

// ---------------- launch ----------------
extern "C" void kernel_launch(void* const* d_in, const int* in_sizes, int n_in,
                              void* d_out, int out_size)
{
    const float* x     = (const float*)d_in[0];
    const float* ln1_g = (const float*)d_in[1];
    const float* ln1_b = (const float*)d_in[2];
    const float* qkv_w = (const float*)d_in[3];
    const float* qkv_b = (const float*)d_in[4];
    const float* out_w = (const float*)d_in[5];
    const float* out_b = (const float*)d_in[6];
    const float* ln2_g = (const float*)d_in[7];
    const float* ln2_b = (const float*)d_in[8];
    const float* ff1_w = (const float*)d_in[9];
    const float* ff1_b = (const float*)d_in[10];
    const float* ff2_w = (const float*)d_in[11];
    const float* ff2_b = (const float*)d_in[12];
    float* y = (float*)d_out;

    float *p_x1;
    __nv_bfloat16 *p_hhi, *p_hlo, *p_qhi, *p_qlo, *p_ahi, *p_alo, *p_fhi, *p_flo;
    __nv_bfloat16 *p_wqh, *p_wql, *p_woh, *p_wol, *p_w1h, *p_w1l, *p_w2h, *p_w2l;
    cudaGetSymbolAddress((void**)&p_x1,  g_x1);
    cudaGetSymbolAddress((void**)&p_hhi, g_hhi);
    cudaGetSymbolAddress((void**)&p_hlo, g_hlo);
    cudaGetSymbolAddress((void**)&p_qhi, g_qhi);
    cudaGetSymbolAddress((void**)&p_qlo, g_qlo);
    cudaGetSymbolAddress((void**)&p_ahi, g_ahi);
    cudaGetSymbolAddress((void**)&p_alo, g_alo);
    cudaGetSymbolAddress((void**)&p_fhi, g_fhi);
    cudaGetSymbolAddress((void**)&p_flo, g_flo);
    cudaGetSymbolAddress((void**)&p_wqh, g_wqkv_hi);
    cudaGetSymbolAddress((void**)&p_wql, g_wqkv_lo);
    cudaGetSymbolAddress((void**)&p_woh, g_wout_hi);
    cudaGetSymbolAddress((void**)&p_wol, g_wout_lo);
    cudaGetSymbolAddress((void**)&p_w1h, g_wff1_hi);
    cudaGetSymbolAddress((void**)&p_w1l, g_wff1_lo);
    cudaGetSymbolAddress((void**)&p_w2h, g_wff2_hi);
    cudaGetSymbolAddress((void**)&p_w2l, g_wff2_lo);

    cudaFuncSetAttribute(attn_fa2, cudaFuncAttributeMaxDynamicSharedMemorySize, ASMEM);
    cudaFuncSetAttribute(gemm_mma<1>, cudaFuncAttributeMaxDynamicSharedMemorySize, GSMEM_TOTAL);
    cudaFuncSetAttribute(gemm_mma<2>, cudaFuncAttributeMaxDynamicSharedMemorySize, GSMEM_TOTAL);
    cudaFuncSetAttribute(gemm_mma<3>, cudaFuncAttributeMaxDynamicSharedMemorySize, GSMEM_TOTAL);

    // weight transpose + split
    wsplit_kernel<<<dim3(QKVC / 32, CC / 32), dim3(32, 8)>>>(qkv_w, p_wqh, p_wql, CC, QKVC);
    wsplit_kernel<<<dim3(CC / 32,  CC / 32), dim3(32, 8)>>>(out_w, p_woh, p_wol, CC, CC);
    wsplit_kernel<<<dim3(FF / 32,  CC / 32), dim3(32, 8)>>>(ff1_w, p_w1h, p_w1l, CC, FF);
    wsplit_kernel<<<dim3(CC / 32,  FF / 32), dim3(32, 8)>>>(ff2_w, p_w2h, p_w2l, FF, CC);

    // 1) h = LN1(x) -> split
    ln_kernel<<<MM, 256>>>(x, ln1_g, ln1_b, p_hhi, p_hlo);
    // 2) qkv = h @ qkv_w + qkv_b -> split bf16
    gemm_mma<3><<<dim3(QKVC / 128, MM / 128), 256, GSMEM_TOTAL>>>(
        p_hhi, p_hlo, p_wqh, p_wql, qkv_b, nullptr, nullptr, p_qhi, p_qlo, CC, QKVC);
    // 3) attention -> split
    attn_fa2<<<dim3(TT / 64, HH, BB), 128, ASMEM>>>(p_qhi, p_qlo, p_ahi, p_alo);
    // 4) x1 = x + att @ out_w + out_b
    gemm_mma<1><<<dim3(CC / 128, MM / 128), 256, GSMEM_TOTAL>>>(
        p_ahi, p_alo, p_woh, p_wol, out_b, x, p_x1, nullptr, nullptr, CC, CC);
    // 5) h = LN2(x1) -> split
    ln_kernel<<<MM, 256>>>(p_x1, ln2_g, ln2_b, p_hhi, p_hlo);
    // 6) ff = gelu(h @ ff1_w + ff1_b) -> split
    gemm_mma<2><<<dim3(FF / 128, MM / 128), 256, GSMEM_TOTAL>>>(
        p_hhi, p_hlo, p_w1h, p_w1l, ff1_b, nullptr, nullptr, p_fhi, p_flo, CC, FF);
    // 7) y = x1 + ff @ ff2_w + ff2_b
    gemm_mma<1><<<dim3(CC / 128, MM / 128), 256, GSMEM_TOTAL>>>(
        p_fhi, p_flo, p_w2h, p_w2l, ff2_b, p_x1, y, nullptr, nullptr, FF, CC);
}

// round 7
// speedup vs baseline: 6.3019x; 1.2409x over previous
#include <cuda_runtime.h>
#include <cuda_fp16.h>
#include <math.h>
#include <stdint.h>

// ---------------- problem constants ----------------
#define BB   2
#define TT   2048
#define CC   1024
#define HH   16
#define DD   64
#define FF   4096
#define MM   (BB*TT)          // 4096 rows
#define QKVC (3*CC)           // 3072

// ---------------- scratch (device globals; no allocs allowed) ----------------
__device__ float g_x1 [MM*CC];                   // residual stream after attn
__device__ alignas(128) __half g_hhi[MM*CC], g_hlo[MM*CC];     // LN out split
__device__ alignas(128) __half g_qhi[MM*QKVC], g_qlo[MM*QKVC]; // qkv split
__device__ alignas(128) __half g_ahi[MM*CC], g_alo[MM*CC];     // attn out split
__device__ alignas(128) __half g_fhi[MM*FF], g_flo[MM*FF];     // gelu out split
// transposed split weights: Wt[n][k]
__device__ alignas(128) __half g_wqkv_hi[CC*QKVC], g_wqkv_lo[CC*QKVC];
__device__ alignas(128) __half g_wout_hi[CC*CC];
__device__ alignas(128) __half g_wff1_hi[CC*FF];
__device__ alignas(128) __half g_wff2_hi[FF*CC];

// ================= helpers =================
__device__ __forceinline__ uint32_t smem_to_u32(const void* p) {
    uint32_t a;
    asm("{ .reg .u64 t; cvta.to.shared.u64 t, %1; cvt.u32.u64 %0, t; }" : "=r"(a) : "l"(p));
    return a;
}
#define CP_ASYNC16(dst, src) \
    asm volatile("cp.async.cg.shared.global [%0], [%1], 16;" :: "r"(dst), "l"(src))
#define CP_COMMIT() asm volatile("cp.async.commit_group;" ::: "memory")
#define CP_WAIT(n)  asm volatile("cp.async.wait_group %0;" :: "n"(n) : "memory")

__device__ __forceinline__ void ldsm4(uint32_t* r, uint32_t addr) {
    asm volatile("ldmatrix.sync.aligned.m8n8.x4.shared.b16 {%0,%1,%2,%3}, [%4];"
                 : "=r"(r[0]), "=r"(r[1]), "=r"(r[2]), "=r"(r[3]) : "r"(addr));
}
__device__ __forceinline__ void ldsm4t(uint32_t* r, uint32_t addr) {
    asm volatile("ldmatrix.sync.aligned.m8n8.x4.trans.shared.b16 {%0,%1,%2,%3}, [%4];"
                 : "=r"(r[0]), "=r"(r[1]), "=r"(r[2]), "=r"(r[3]) : "r"(addr));
}
__device__ __forceinline__ void mma16816(float* c, const uint32_t* a, const uint32_t* b) {
    asm volatile("mma.sync.aligned.m16n8k16.row.col.f32.f16.f16.f32 "
                 "{%0,%1,%2,%3}, {%4,%5,%6,%7}, {%8,%9}, {%0,%1,%2,%3};"
                 : "+f"(c[0]), "+f"(c[1]), "+f"(c[2]), "+f"(c[3])
                 : "r"(a[0]), "r"(a[1]), "r"(a[2]), "r"(a[3]), "r"(b[0]), "r"(b[1]));
}
// pack two floats into fp16x2 (x0 -> low), and fp16 residuals into lo
__device__ __forceinline__ uint32_t split_pack(float x0, float x1, uint32_t& lo) {
    __half h0 = __float2half(x0), h1 = __float2half(x1);
    __half l0 = __float2half(x0 - __half2float(h0));
    __half l1 = __float2half(x1 - __half2float(h1));
    lo = ((uint32_t)__half_as_ushort(l1) << 16) | __half_as_ushort(l0);
    return ((uint32_t)__half_as_ushort(h1) << 16) | __half_as_ushort(h0);
}

// ================= weight transpose + fp16 split =================
// W[K][N] row-major -> Wt_hi[N][K] (+ optional Wt_lo)
__global__ void __launch_bounds__(256) wsplit_kernel(const float* __restrict__ W,
                                                     __half* __restrict__ Whi,
                                                     __half* __restrict__ Wlo,
                                                     int K, int N)
{
    __shared__ float t[32][33];
    int tx = threadIdx.x, ty = threadIdx.y;   // block (32,8)
    int n0 = blockIdx.x * 32, k0 = blockIdx.y * 32;
#pragma unroll
    for (int i = 0; i < 4; i++)
        t[ty + 8 * i][tx] = W[(size_t)(k0 + ty + 8 * i) * N + n0 + tx];
    __syncthreads();
#pragma unroll
    for (int i = 0; i < 4; i++) {
        int n = n0 + ty + 8 * i, k = k0 + tx;
        float v = t[tx][ty + 8 * i];
        __half hi = __float2half(v);
        Whi[(size_t)n * K + k] = hi;
        if (Wlo) Wlo[(size_t)n * K + k] = __float2half(v - __half2float(hi));
    }
}

// ================= LayerNorm with split-fp16 output =================
__global__ void __launch_bounds__(256) ln_kernel(const float* __restrict__ x,
                                                 const float* __restrict__ g,
                                                 const float* __restrict__ b,
                                                 __half* __restrict__ yhi,
                                                 __half* __restrict__ ylo)
{
    int row = blockIdx.x;
    const float* xr = x + (size_t)row * CC;
    int tid = threadIdx.x;

    float v[4];
    float s1 = 0.f, s2 = 0.f;
#pragma unroll
    for (int i = 0; i < 4; i++) {
        v[i] = xr[tid + i * 256];
        s1 += v[i];
        s2 += v[i] * v[i];
    }
#pragma unroll
    for (int o = 16; o; o >>= 1) {
        s1 += __shfl_xor_sync(0xffffffffu, s1, o);
        s2 += __shfl_xor_sync(0xffffffffu, s2, o);
    }
    __shared__ float r1[8], r2[8], sh_mean, sh_rstd;
    if ((tid & 31) == 0) { r1[tid >> 5] = s1; r2[tid >> 5] = s2; }
    __syncthreads();
    if (tid == 0) {
        float t1 = 0.f, t2 = 0.f;
#pragma unroll
        for (int i = 0; i < 8; i++) { t1 += r1[i]; t2 += r2[i]; }
        float mean = t1 * (1.0f / CC);
        float var  = t2 * (1.0f / CC) - mean * mean;
        sh_mean = mean;
        sh_rstd = rsqrtf(var + 1e-5f);
    }
    __syncthreads();
    float mean = sh_mean, rstd = sh_rstd;
#pragma unroll
    for (int i = 0; i < 4; i++) {
        int c = tid + i * 256;
        float o = (v[i] - mean) * rstd * g[c] + b[c];
        __half hi = __float2half(o);
        yhi[(size_t)row * CC + c] = hi;
        ylo[(size_t)row * CC + c] = __float2half(o - __half2float(hi));
    }
}

// ================= mma.sync GEMM (split-fp16) =================
// TERMS==2: C = Ahi*B + Alo*B (B = Whi only; error = A*Wlo ~ 2^-11 rms)
// TERMS==3: C = Ahi*Bhi + Alo*Bhi + Ahi*Blo (error ~2^-22)
// E: 1 = fp32 out (+bias+res); 2 = gelu -> split fp16; 3 = split fp16 (+bias).
// Stage holds [Ahi | Alo | Bhi (| Blo)] for one 32-wide K-chunk; 4 stages.
#define GS 4
#define SSTRIDE 40                         // halves per row
#define TILE_B (128*SSTRIDE*2)             // 10240 bytes

template<int E, int TERMS>
__global__ void __launch_bounds__(256) gemm_mma(const __half* __restrict__ Ahi,
                                                const __half* __restrict__ Alo,
                                                const __half* __restrict__ Bhi,
                                                const __half* __restrict__ Blo,
                                                const float* __restrict__ bias,
                                                const float* __restrict__ res,
                                                float* __restrict__ outf,
                                                __half* __restrict__ outhi,
                                                __half* __restrict__ outlo,
                                                int K, int gN)
{
    constexpr int NT = TERMS + 1;            // tiles per stage
    constexpr uint32_t STAGE = NT * TILE_B;
    extern __shared__ char smem[];
    uint32_t sbase = smem_to_u32(smem);
    int tid = threadIdx.x, lane = tid & 31, wid = tid >> 5;
    int bx = blockIdx.x, by = blockIdx.y;
    const int NK = K >> 5;
    int m0 = (wid & 3) * 32, n0 = (wid >> 2) * 64;

    const __half* AhiB = Ahi + (size_t)(by * 128) * K;
    const __half* AloB = Alo + (size_t)(by * 128) * K;
    const __half* BhiB = Bhi + (size_t)(bx * 128) * K;
    const __half* BloB = TERMS == 3 ? Blo + (size_t)(bx * 128) * K : nullptr;

    int u = tid & 3;        // 16B unit within 64B row
    int r0 = tid >> 2;      // 0..63

    auto issue = [&](int kk) {
        uint32_t st = sbase + (kk & (GS - 1)) * STAGE;
#pragma unroll
        for (int rr = 0; rr < 2; rr++) {
            int r = r0 + rr * 64;
            size_t go = (size_t)r * K + kk * 32 + u * 8;
            uint32_t so = (r * SSTRIDE + u * 8) * 2;
            CP_ASYNC16(st + so,              AhiB + go);
            CP_ASYNC16(st + TILE_B + so,     AloB + go);
            CP_ASYNC16(st + 2 * TILE_B + so, BhiB + go);
            if (TERMS == 3) CP_ASYNC16(st + 3 * TILE_B + so, BloB + go);
        }
        CP_COMMIT();
    };

    float acc[2][8][4] = {};

    for (int c = 0; c < GS - 1; c++) issue(c);

    for (int c = 0; c < NK; c++) {
        CP_WAIT(GS - 2);          // stage c complete
        __syncthreads();          // all warps done reading stage (c-1)
        if (c + GS - 1 < NK) issue(c + GS - 1); else CP_COMMIT();

        uint32_t st = sbase + (c & (GS - 1)) * STAGE;
#pragma unroll
        for (int kh = 0; kh < 2; kh++) {
            uint32_t ah[2][4], al[2][4];
#pragma unroll
            for (int i = 0; i < 2; i++) {
                uint32_t aoff = ((m0 + i * 16 + (lane & 15)) * SSTRIDE + kh * 16 + (lane >> 4) * 8) * 2;
                ldsm4(ah[i], st + aoff);
                ldsm4(al[i], st + TILE_B + aoff);
            }
            uint32_t boff = ((n0 + (lane & 7) + ((lane >> 4) & 1) * 8) * SSTRIDE
                             + kh * 16 + ((lane >> 3) & 1) * 8) * 2;
            uint32_t bh[4][4];
#pragma unroll
            for (int g = 0; g < 4; g++) ldsm4(bh[g], st + 2 * TILE_B + boff + g * 16 * SSTRIDE * 2);
#pragma unroll
            for (int i = 0; i < 2; i++)
#pragma unroll
                for (int g = 0; g < 4; g++) {
                    mma16816(acc[i][g * 2 + 0], ah[i], &bh[g][0]);
                    mma16816(acc[i][g * 2 + 1], ah[i], &bh[g][2]);
                    mma16816(acc[i][g * 2 + 0], al[i], &bh[g][0]);
                    mma16816(acc[i][g * 2 + 1], al[i], &bh[g][2]);
                }
            if (TERMS == 3) {
                uint32_t bl[4][4];
#pragma unroll
                for (int g = 0; g < 4; g++) ldsm4(bl[g], st + 3 * TILE_B + boff + g * 16 * SSTRIDE * 2);
#pragma unroll
                for (int i = 0; i < 2; i++)
#pragma unroll
                    for (int g = 0; g < 4; g++) {
                        mma16816(acc[i][g * 2 + 0], ah[i], &bl[g][0]);
                        mma16816(acc[i][g * 2 + 1], ah[i], &bl[g][2]);
                    }
            }
        }
    }

    // epilogue from registers
    int mb = by * 128 + m0;
    int nb = bx * 128 + n0;
#pragma unroll
    for (int i = 0; i < 2; i++) {
#pragma unroll
        for (int j = 0; j < 8; j++) {
            float* cc = acc[i][j];
            int n = nb + j * 8 + (lane & 3) * 2;
            float b0 = bias[n], b1 = bias[n + 1];
#pragma unroll
            for (int hrow = 0; hrow < 2; hrow++) {
                int m = mb + i * 16 + (lane >> 2) + hrow * 8;
                float v0 = cc[hrow * 2 + 0] + b0;
                float v1 = cc[hrow * 2 + 1] + b1;
                size_t off = (size_t)m * gN + n;
                if (E == 1) {
                    float2 rv = *(const float2*)(res + off);
                    v0 += rv.x; v1 += rv.y;
                    float2 ov; ov.x = v0; ov.y = v1;
                    *(float2*)(outf + off) = ov;
                } else {
                    if (E == 2) {
                        v0 = 0.5f * v0 * (1.0f + erff(v0 * 0.70710678118654752f));
                        v1 = 0.5f * v1 * (1.0f + erff(v1 * 0.70710678118654752f));
                    }
                    uint32_t lo, hi = split_pack(v0, v1, lo);
                    *(uint32_t*)(outhi + off) = hi;
                    *(uint32_t*)(outlo + off) = lo;
                }
            }
        }
    }
}

// ================= FA2 tensor-core attention (fp16 3-term, cp.async) =====
#define AST 72        // smem row stride in halves
#define ATILE (64 * AST)                 // halves per tile
#define KVSTAGE (4 * ATILE)              // Kh,Kl,Vh,Vl
#define ASMEM ((2 * ATILE + 2 * KVSTAGE) * 2)   // 92160 bytes

__global__ void __launch_bounds__(128) attn_fa2(const __half* __restrict__ qh_g,
                                                const __half* __restrict__ ql_g,
                                                __half* __restrict__ ohi,
                                                __half* __restrict__ olo)
{
    extern __shared__ __half sb[];
    __half* sQh = sb;
    __half* sQl = sQh + ATILE;
    __half* sKV = sQl + ATILE;    // 2 stages of [Kh|Kl|Vh|Vl]
    uint32_t uQh = smem_to_u32(sQh), uQl = smem_to_u32(sQl);
    uint32_t uKV = smem_to_u32(sKV);

    int tid = threadIdx.x, lane = tid & 31, w = tid >> 5;
    int qt = gridDim.x - 1 - blockIdx.x;       // heavy tiles first
    int h = blockIdx.y, b = blockIdx.z;
    size_t qbase = ((size_t)(b * TT + qt * 64)) * QKVC + h * DD;

    int r0 = tid >> 3, uu = tid & 7;

    auto issue_kv = [&](int kt, int s) {
        size_t kbase = ((size_t)(b * TT + kt * 64)) * QKVC + CC + h * DD;
        size_t vbase = kbase + CC;
        uint32_t st = uKV + s * KVSTAGE * 2;
#pragma unroll
        for (int rep = 0; rep < 4; rep++) {
            int r = r0 + rep * 16;
            size_t go = (size_t)r * QKVC + uu * 8;
            uint32_t so = (r * AST + uu * 8) * 2;
            CP_ASYNC16(st + so,             qh_g + kbase + go);
            CP_ASYNC16(st + ATILE * 2 + so, ql_g + kbase + go);
            CP_ASYNC16(st + ATILE * 4 + so, qh_g + vbase + go);
            CP_ASYNC16(st + ATILE * 6 + so, ql_g + vbase + go);
        }
        CP_COMMIT();
    };

    issue_kv(0, 0);
#pragma unroll
    for (int rep = 0; rep < 4; rep++) {
        int r = r0 + rep * 16;
        *(uint4*)(sQh + r * AST + uu * 8) = *(const uint4*)(qh_g + qbase + (size_t)r * QKVC + uu * 8);
        *(uint4*)(sQl + r * AST + uu * 8) = *(const uint4*)(ql_g + qbase + (size_t)r * QKVC + uu * 8);
    }
    __syncthreads();

    uint32_t qh[4][4], ql[4][4];
#pragma unroll
    for (int ks = 0; ks < 4; ks++) {
        uint32_t off = ((16 * w + (lane & 15)) * AST + ks * 16 + (lane >> 4) * 8) * 2;
        ldsm4(qh[ks], uQh + off);
        ldsm4(ql[ks], uQl + off);
    }

    float m0r = -1e30f, m1r = -1e30f;
    float l0r = 0.f, l1r = 0.f;
    float oacc[8][4] = {};

    for (int kt = 0; kt <= qt; kt++) {
        int s = kt & 1;
        __syncthreads();
        if (kt + 1 <= qt) issue_kv(kt + 1, s ^ 1); else CP_COMMIT();
        CP_WAIT(1);
        __syncthreads();

        uint32_t uKh = uKV + (s * KVSTAGE) * 2;
        uint32_t uKl = uKh + ATILE * 2;
        uint32_t uVh = uKh + ATILE * 4;
        uint32_t uVl = uKh + ATILE * 6;

        // ---- S = QK^T (3 terms) ----
        float sacc[8][4] = {};
#pragma unroll
        for (int ks = 0; ks < 4; ks++) {
            uint32_t kb[4][4];
            uint32_t boff = ((lane & 7) + ((lane >> 4) & 1) * 8) * AST + ks * 16 + ((lane >> 3) & 1) * 8;
#pragma unroll
            for (int g = 0; g < 4; g++) ldsm4(kb[g], uKh + (boff + g * 16 * AST) * 2);
#pragma unroll
            for (int g = 0; g < 4; g++) {
                mma16816(sacc[g * 2 + 0], qh[ks], &kb[g][0]);
                mma16816(sacc[g * 2 + 1], qh[ks], &kb[g][2]);
                mma16816(sacc[g * 2 + 0], ql[ks], &kb[g][0]);
                mma16816(sacc[g * 2 + 1], ql[ks], &kb[g][2]);
            }
#pragma unroll
            for (int g = 0; g < 4; g++) ldsm4(kb[g], uKl + (boff + g * 16 * AST) * 2);
#pragma unroll
            for (int g = 0; g < 4; g++) {
                mma16816(sacc[g * 2 + 0], qh[ks], &kb[g][0]);
                mma16816(sacc[g * 2 + 1], qh[ks], &kb[g][2]);
            }
        }

        // ---- scale, mask, online softmax ----
        int rl0 = w * 16 + (lane >> 2);
        int rl1 = rl0 + 8;
        float mn0 = m0r, mn1 = m1r;
#pragma unroll
        for (int t = 0; t < 8; t++) {
            sacc[t][0] *= 0.125f; sacc[t][1] *= 0.125f;
            sacc[t][2] *= 0.125f; sacc[t][3] *= 0.125f;
            if (kt == qt) {
                int col = t * 8 + 2 * (lane & 3);
                if (col     > rl0) sacc[t][0] = -1e30f;
                if (col + 1 > rl0) sacc[t][1] = -1e30f;
                if (col     > rl1) sacc[t][2] = -1e30f;
                if (col + 1 > rl1) sacc[t][3] = -1e30f;
            }
            mn0 = fmaxf(mn0, fmaxf(sacc[t][0], sacc[t][1]));
            mn1 = fmaxf(mn1, fmaxf(sacc[t][2], sacc[t][3]));
        }
        mn0 = fmaxf(mn0, __shfl_xor_sync(0xffffffffu, mn0, 1));
        mn0 = fmaxf(mn0, __shfl_xor_sync(0xffffffffu, mn0, 2));
        mn1 = fmaxf(mn1, __shfl_xor_sync(0xffffffffu, mn1, 1));
        mn1 = fmaxf(mn1, __shfl_xor_sync(0xffffffffu, mn1, 2));
        float es0 = __expf(m0r - mn0), es1 = __expf(m1r - mn1);
        m0r = mn0; m1r = mn1;
        float rs0 = 0.f, rs1 = 0.f;
#pragma unroll
        for (int t = 0; t < 8; t++) {
            sacc[t][0] = __expf(sacc[t][0] - mn0);
            sacc[t][1] = __expf(sacc[t][1] - mn0);
            sacc[t][2] = __expf(sacc[t][2] - mn1);
            sacc[t][3] = __expf(sacc[t][3] - mn1);
            rs0 += sacc[t][0] + sacc[t][1];
            rs1 += sacc[t][2] + sacc[t][3];
        }
        rs0 += __shfl_xor_sync(0xffffffffu, rs0, 1);
        rs0 += __shfl_xor_sync(0xffffffffu, rs0, 2);
        rs1 += __shfl_xor_sync(0xffffffffu, rs1, 1);
        rs1 += __shfl_xor_sync(0xffffffffu, rs1, 2);
        l0r = l0r * es0 + rs0;
        l1r = l1r * es1 + rs1;
#pragma unroll
        for (int t = 0; t < 8; t++) {
            oacc[t][0] *= es0; oacc[t][1] *= es0;
            oacc[t][2] *= es1; oacc[t][3] *= es1;
        }

        // ---- PV (3 terms) ----
#pragma unroll
        for (int ks = 0; ks < 4; ks++) {
            uint32_t pa[4], pl[4];
            pa[0] = split_pack(sacc[2 * ks][0],     sacc[2 * ks][1],     pl[0]);
            pa[1] = split_pack(sacc[2 * ks][2],     sacc[2 * ks][3],     pl[1]);
            pa[2] = split_pack(sacc[2 * ks + 1][0], sacc[2 * ks + 1][1], pl[2]);
            pa[3] = split_pack(sacc[2 * ks + 1][2], sacc[2 * ks + 1][3], pl[3]);

            uint32_t vb[4][4];
            uint32_t voff = (ks * 16 + (lane & 15)) * AST + ((lane >> 4) & 1) * 8;
#pragma unroll
            for (int g = 0; g < 4; g++) ldsm4t(vb[g], uVh + (voff + g * 16) * 2);
#pragma unroll
            for (int g = 0; g < 4; g++) {
                mma16816(oacc[g * 2 + 0], pa, &vb[g][0]);
                mma16816(oacc[g * 2 + 1], pa, &vb[g][2]);
                mma16816(oacc[g * 2 + 0], pl, &vb[g][0]);
                mma16816(oacc[g * 2 + 1], pl, &vb[g][2]);
            }
#pragma unroll
            for (int g = 0; g < 4; g++) ldsm4t(vb[g], uVl + (voff + g * 16) * 2);
#pragma unroll
            for (int g = 0; g < 4; g++) {
                mma16816(oacc[g * 2 + 0], pa, &vb[g][0]);
                mma16816(oacc[g * 2 + 1], pa, &vb[g][2]);
            }
        }
    }

    float inv0 = 1.0f / l0r, inv1 = 1.0f / l1r;
    size_t r0g = (size_t)(b * TT + qt * 64 + w * 16 + (lane >> 2));
    size_t obase0 = r0g * CC + h * DD;
    size_t obase1 = (r0g + 8) * CC + h * DD;
#pragma unroll
    for (int t = 0; t < 8; t++) {
        int d = t * 8 + 2 * (lane & 3);
        uint32_t lo, hi;
        hi = split_pack(oacc[t][0] * inv0, oacc[t][1] * inv0, lo);
        *(uint32_t*)(ohi + obase0 + d) = hi;
        *(uint32_t*)(olo + obase0 + d) = lo;
        hi = split_pack(oacc[t][2] * inv1, oacc[t][3] * inv1, lo);
        *(uint32_t*)(ohi + obase1 + d) = hi;
        *(uint32_t*)(olo + obase1 + d) = lo;
    }
}

// ---------------- launch ----------------
extern "C" void kernel_launch(void* const* d_in, const int* in_sizes, int n_in,
                              void* d_out, int out_size)
{
    const float* x     = (const float*)d_in[0];
    const float* ln1_g = (const float*)d_in[1];
    const float* ln1_b = (const float*)d_in[2];
    const float* qkv_w = (const float*)d_in[3];
    const float* qkv_b = (const float*)d_in[4];
    const float* out_w = (const float*)d_in[5];
    const float* out_b = (const float*)d_in[6];
    const float* ln2_g = (const float*)d_in[7];
    const float* ln2_b = (const float*)d_in[8];
    const float* ff1_w = (const float*)d_in[9];
    const float* ff1_b = (const float*)d_in[10];
    const float* ff2_w = (const float*)d_in[11];
    const float* ff2_b = (const float*)d_in[12];
    float* y = (float*)d_out;

    float *p_x1;
    __half *p_hhi, *p_hlo, *p_qhi, *p_qlo, *p_ahi, *p_alo, *p_fhi, *p_flo;
    __half *p_wqh, *p_wql, *p_woh, *p_w1h, *p_w2h;
    cudaGetSymbolAddress((void**)&p_x1,  g_x1);
    cudaGetSymbolAddress((void**)&p_hhi, g_hhi);
    cudaGetSymbolAddress((void**)&p_hlo, g_hlo);
    cudaGetSymbolAddress((void**)&p_qhi, g_qhi);
    cudaGetSymbolAddress((void**)&p_qlo, g_qlo);
    cudaGetSymbolAddress((void**)&p_ahi, g_ahi);
    cudaGetSymbolAddress((void**)&p_alo, g_alo);
    cudaGetSymbolAddress((void**)&p_fhi, g_fhi);
    cudaGetSymbolAddress((void**)&p_flo, g_flo);
    cudaGetSymbolAddress((void**)&p_wqh, g_wqkv_hi);
    cudaGetSymbolAddress((void**)&p_wql, g_wqkv_lo);
    cudaGetSymbolAddress((void**)&p_woh, g_wout_hi);
    cudaGetSymbolAddress((void**)&p_w1h, g_wff1_hi);
    cudaGetSymbolAddress((void**)&p_w2h, g_wff2_hi);

    const int GSMEM2 = GS * 3 * TILE_B;   // 122880
    const int GSMEM3 = GS * 4 * TILE_B;   // 163840
    cudaFuncSetAttribute(attn_fa2, cudaFuncAttributeMaxDynamicSharedMemorySize, ASMEM);
    cudaFuncSetAttribute((const void*)gemm_mma<3,3>, cudaFuncAttributeMaxDynamicSharedMemorySize, GSMEM3);
    cudaFuncSetAttribute((const void*)gemm_mma<1,2>, cudaFuncAttributeMaxDynamicSharedMemorySize, GSMEM2);
    cudaFuncSetAttribute((const void*)gemm_mma<2,2>, cudaFuncAttributeMaxDynamicSharedMemorySize, GSMEM2);

    // weight transpose + split (qkv: hi+lo; others: hi only)
    wsplit_kernel<<<dim3(QKVC / 32, CC / 32), dim3(32, 8)>>>(qkv_w, p_wqh, p_wql, CC, QKVC);
    wsplit_kernel<<<dim3(CC / 32,  CC / 32), dim3(32, 8)>>>(out_w, p_woh, nullptr, CC, CC);
    wsplit_kernel<<<dim3(FF / 32,  CC / 32), dim3(32, 8)>>>(ff1_w, p_w1h, nullptr, CC, FF);
    wsplit_kernel<<<dim3(CC / 32,  FF / 32), dim3(32, 8)>>>(ff2_w, p_w2h, nullptr, FF, CC);

    // 1) h = LN1(x) -> split
    ln_kernel<<<MM, 256>>>(x, ln1_g, ln1_b, p_hhi, p_hlo);
    // 2) qkv = h @ qkv_w + qkv_b -> split fp16 (3-term, near-exact)
    gemm_mma<3,3><<<dim3(QKVC / 128, MM / 128), 256, GSMEM3>>>(
        p_hhi, p_hlo, p_wqh, p_wql, qkv_b, nullptr, nullptr, p_qhi, p_qlo, CC, QKVC);
    // 3) attention -> split
    attn_fa2<<<dim3(TT / 64, HH, BB), 128, ASMEM>>>(p_qhi, p_qlo, p_ahi, p_alo);
    // 4) x1 = x + att @ out_w + out_b   (2-term)
    gemm_mma<1,2><<<dim3(CC / 128, MM / 128), 256, GSMEM2>>>(
        p_ahi, p_alo, p_woh, nullptr, out_b, x, p_x1, nullptr, nullptr, CC, CC);
    // 5) h = LN2(x1) -> split
    ln_kernel<<<MM, 256>>>(p_x1, ln2_g, ln2_b, p_hhi, p_hlo);
    // 6) ff = gelu(h @ ff1_w + ff1_b) -> split   (2-term)
    gemm_mma<2,2><<<dim3(FF / 128, MM / 128), 256, GSMEM2>>>(
        p_hhi, p_hlo, p_w1h, nullptr, ff1_b, nullptr, nullptr, p_fhi, p_flo, CC, FF);
    // 7) y = x1 + ff @ ff2_w + ff2_b   (2-term)
    gemm_mma<1,2><<<dim3(CC / 128, MM / 128), 256, GSMEM2>>>(
        p_fhi, p_flo, p_w2h, nullptr, ff2_b, p_x1, y, nullptr, nullptr, FF, CC);
}

// round 8
// speedup vs baseline: 7.7342x; 1.2273x over previous
#include <cuda_runtime.h>
#include <cuda_fp16.h>
#include <math.h>
#include <stdint.h>

// ---------------- problem constants ----------------
#define BB   2
#define TT   2048
#define CC   1024
#define HH   16
#define DD   64
#define FF   4096
#define MM   (BB*TT)          // 4096 rows
#define QKVC (3*CC)           // 3072

// ---------------- scratch (device globals; no allocs allowed) ----------------
__device__ float g_x1 [MM*CC];                   // residual stream after attn
__device__ alignas(128) __half g_hhi[MM*CC], g_hlo[MM*CC];     // LN out split
__device__ alignas(128) __half g_q  [MM*QKVC];                 // qkv fp16
__device__ alignas(128) __half g_ahi[MM*CC], g_alo[MM*CC];     // attn out split
__device__ alignas(128) __half g_fhi[MM*FF], g_flo[MM*FF];     // gelu out split
// transposed fp16 weights: Wt[n][k]
__device__ alignas(128) __half g_wqkv_hi[CC*QKVC];
__device__ alignas(128) __half g_wout_hi[CC*CC];
__device__ alignas(128) __half g_wff1_hi[CC*FF];
__device__ alignas(128) __half g_wff2_hi[FF*CC];

// ================= helpers =================
__device__ __forceinline__ uint32_t smem_to_u32(const void* p) {
    uint32_t a;
    asm("{ .reg .u64 t; cvta.to.shared.u64 t, %1; cvt.u32.u64 %0, t; }" : "=r"(a) : "l"(p));
    return a;
}
#define CP_ASYNC16(dst, src) \
    asm volatile("cp.async.cg.shared.global [%0], [%1], 16;" :: "r"(dst), "l"(src))
#define CP_COMMIT() asm volatile("cp.async.commit_group;" ::: "memory")
#define CP_WAIT(n)  asm volatile("cp.async.wait_group %0;" :: "n"(n) : "memory")

__device__ __forceinline__ void ldsm4(uint32_t* r, uint32_t addr) {
    asm volatile("ldmatrix.sync.aligned.m8n8.x4.shared.b16 {%0,%1,%2,%3}, [%4];"
                 : "=r"(r[0]), "=r"(r[1]), "=r"(r[2]), "=r"(r[3]) : "r"(addr));
}
__device__ __forceinline__ void ldsm4t(uint32_t* r, uint32_t addr) {
    asm volatile("ldmatrix.sync.aligned.m8n8.x4.trans.shared.b16 {%0,%1,%2,%3}, [%4];"
                 : "=r"(r[0]), "=r"(r[1]), "=r"(r[2]), "=r"(r[3]) : "r"(addr));
}
__device__ __forceinline__ void mma16816(float* c, const uint32_t* a, const uint32_t* b) {
    asm volatile("mma.sync.aligned.m16n8k16.row.col.f32.f16.f16.f32 "
                 "{%0,%1,%2,%3}, {%4,%5,%6,%7}, {%8,%9}, {%0,%1,%2,%3};"
                 : "+f"(c[0]), "+f"(c[1]), "+f"(c[2]), "+f"(c[3])
                 : "r"(a[0]), "r"(a[1]), "r"(a[2]), "r"(a[3]), "r"(b[0]), "r"(b[1]));
}
__device__ __forceinline__ uint32_t pack2(float x0, float x1) {
    __half2 h = __floats2half2_rn(x0, x1);
    return *(uint32_t*)&h;
}
// pack two floats into fp16x2 (x0 -> low), and fp16 residuals into lo
__device__ __forceinline__ uint32_t split_pack(float x0, float x1, uint32_t& lo) {
    __half h0 = __float2half(x0), h1 = __float2half(x1);
    __half l0 = __float2half(x0 - __half2float(h0));
    __half l1 = __float2half(x1 - __half2float(h1));
    lo = ((uint32_t)__half_as_ushort(l1) << 16) | __half_as_ushort(l0);
    return ((uint32_t)__half_as_ushort(h1) << 16) | __half_as_ushort(h0);
}

// ================= weight transpose to fp16 =================
// W[K][N] row-major -> Wt_hi[N][K]
__global__ void __launch_bounds__(256) wsplit_kernel(const float* __restrict__ W,
                                                     __half* __restrict__ Whi,
                                                     int K, int N)
{
    __shared__ float t[32][33];
    int tx = threadIdx.x, ty = threadIdx.y;   // block (32,8)
    int n0 = blockIdx.x * 32, k0 = blockIdx.y * 32;
#pragma unroll
    for (int i = 0; i < 4; i++)
        t[ty + 8 * i][tx] = W[(size_t)(k0 + ty + 8 * i) * N + n0 + tx];
    __syncthreads();
#pragma unroll
    for (int i = 0; i < 4; i++) {
        int n = n0 + ty + 8 * i, k = k0 + tx;
        Whi[(size_t)n * K + k] = __float2half(t[tx][ty + 8 * i]);
    }
}

// ================= LayerNorm with split-fp16 output (vectorized) =========
__global__ void __launch_bounds__(256) ln_kernel(const float* __restrict__ x,
                                                 const float* __restrict__ g,
                                                 const float* __restrict__ b,
                                                 __half* __restrict__ yhi,
                                                 __half* __restrict__ ylo)
{
    int row = blockIdx.x;
    int tid = threadIdx.x;
    float4 v = ((const float4*)(x + (size_t)row * CC))[tid];
    float s1 = v.x + v.y + v.z + v.w;
    float s2 = v.x * v.x + v.y * v.y + v.z * v.z + v.w * v.w;
#pragma unroll
    for (int o = 16; o; o >>= 1) {
        s1 += __shfl_xor_sync(0xffffffffu, s1, o);
        s2 += __shfl_xor_sync(0xffffffffu, s2, o);
    }
    __shared__ float r1[8], r2[8], sh_mean, sh_rstd;
    if ((tid & 31) == 0) { r1[tid >> 5] = s1; r2[tid >> 5] = s2; }
    __syncthreads();
    if (tid == 0) {
        float t1 = 0.f, t2 = 0.f;
#pragma unroll
        for (int i = 0; i < 8; i++) { t1 += r1[i]; t2 += r2[i]; }
        float mean = t1 * (1.0f / CC);
        float var  = t2 * (1.0f / CC) - mean * mean;
        sh_mean = mean;
        sh_rstd = rsqrtf(var + 1e-5f);
    }
    __syncthreads();
    float mean = sh_mean, rstd = sh_rstd;
    float4 gv = ((const float4*)g)[tid];
    float4 bv = ((const float4*)b)[tid];
    float o0 = (v.x - mean) * rstd * gv.x + bv.x;
    float o1 = (v.y - mean) * rstd * gv.y + bv.y;
    float o2 = (v.z - mean) * rstd * gv.z + bv.z;
    float o3 = (v.w - mean) * rstd * gv.w + bv.w;
    uint32_t l0, h0 = split_pack(o0, o1, l0);
    uint32_t l1, h1 = split_pack(o2, o3, l1);
    uint2 hv; hv.x = h0; hv.y = h1;
    uint2 lv; lv.x = l0; lv.y = l1;
    *(uint2*)(yhi + (size_t)row * CC + tid * 4) = hv;
    *(uint2*)(ylo + (size_t)row * CC + tid * 4) = lv;
}

// ================= mma.sync GEMM (fp16, 2-term A-split) =================
// C = Ahi*B + Alo*B  (B fp16 hi only; error ~2^-11 weight rounding)
// E: 1 = fp32 out (+bias+res); 2 = gelu -> split fp16; 4 = single fp16 (+bias).
#define GS 4
#define SSTRIDE 40                         // halves per row
#define TILE_B (128*SSTRIDE*2)             // 10240 bytes
#define GSMEM2 (GS * 3 * TILE_B)           // 122880

template<int E>
__global__ void __launch_bounds__(256) gemm_mma(const __half* __restrict__ Ahi,
                                                const __half* __restrict__ Alo,
                                                const __half* __restrict__ Bhi,
                                                const float* __restrict__ bias,
                                                const float* __restrict__ res,
                                                float* __restrict__ outf,
                                                __half* __restrict__ outhi,
                                                __half* __restrict__ outlo,
                                                int K, int gN)
{
    constexpr uint32_t STAGE = 3 * TILE_B;
    extern __shared__ char smem[];
    uint32_t sbase = smem_to_u32(smem);
    int tid = threadIdx.x, lane = tid & 31, wid = tid >> 5;
    int bx = blockIdx.x, by = blockIdx.y;
    const int NK = K >> 5;
    int m0 = (wid & 3) * 32, n0 = (wid >> 2) * 64;

    const __half* AhiB = Ahi + (size_t)(by * 128) * K;
    const __half* AloB = Alo + (size_t)(by * 128) * K;
    const __half* BhiB = Bhi + (size_t)(bx * 128) * K;

    int u = tid & 3;        // 16B unit within 64B row
    int r0 = tid >> 2;      // 0..63

    auto issue = [&](int kk) {
        uint32_t st = sbase + (kk & (GS - 1)) * STAGE;
#pragma unroll
        for (int rr = 0; rr < 2; rr++) {
            int r = r0 + rr * 64;
            size_t go = (size_t)r * K + kk * 32 + u * 8;
            uint32_t so = (r * SSTRIDE + u * 8) * 2;
            CP_ASYNC16(st + so,              AhiB + go);
            CP_ASYNC16(st + TILE_B + so,     AloB + go);
            CP_ASYNC16(st + 2 * TILE_B + so, BhiB + go);
        }
        CP_COMMIT();
    };

    float acc[2][8][4] = {};

    for (int c = 0; c < GS - 1; c++) issue(c);

    for (int c = 0; c < NK; c++) {
        CP_WAIT(GS - 2);          // stage c complete
        __syncthreads();          // all warps done reading stage (c-1)
        if (c + GS - 1 < NK) issue(c + GS - 1); else CP_COMMIT();

        uint32_t st = sbase + (c & (GS - 1)) * STAGE;
#pragma unroll
        for (int kh = 0; kh < 2; kh++) {
            uint32_t ah[2][4], al[2][4];
#pragma unroll
            for (int i = 0; i < 2; i++) {
                uint32_t aoff = ((m0 + i * 16 + (lane & 15)) * SSTRIDE + kh * 16 + (lane >> 4) * 8) * 2;
                ldsm4(ah[i], st + aoff);
                ldsm4(al[i], st + TILE_B + aoff);
            }
            uint32_t boff = ((n0 + (lane & 7) + ((lane >> 4) & 1) * 8) * SSTRIDE
                             + kh * 16 + ((lane >> 3) & 1) * 8) * 2;
            uint32_t bh[4][4];
#pragma unroll
            for (int g = 0; g < 4; g++) ldsm4(bh[g], st + 2 * TILE_B + boff + g * 16 * SSTRIDE * 2);
#pragma unroll
            for (int i = 0; i < 2; i++)
#pragma unroll
                for (int g = 0; g < 4; g++) {
                    mma16816(acc[i][g * 2 + 0], ah[i], &bh[g][0]);
                    mma16816(acc[i][g * 2 + 1], ah[i], &bh[g][2]);
                    mma16816(acc[i][g * 2 + 0], al[i], &bh[g][0]);
                    mma16816(acc[i][g * 2 + 1], al[i], &bh[g][2]);
                }
        }
    }

    // epilogue from registers
    int mb = by * 128 + m0;
    int nb = bx * 128 + n0;
#pragma unroll
    for (int i = 0; i < 2; i++) {
#pragma unroll
        for (int j = 0; j < 8; j++) {
            float* cc = acc[i][j];
            int n = nb + j * 8 + (lane & 3) * 2;
            float b0 = bias[n], b1 = bias[n + 1];
#pragma unroll
            for (int hrow = 0; hrow < 2; hrow++) {
                int m = mb + i * 16 + (lane >> 2) + hrow * 8;
                float v0 = cc[hrow * 2 + 0] + b0;
                float v1 = cc[hrow * 2 + 1] + b1;
                size_t off = (size_t)m * gN + n;
                if (E == 1) {
                    float2 rv = *(const float2*)(res + off);
                    v0 += rv.x; v1 += rv.y;
                    float2 ov; ov.x = v0; ov.y = v1;
                    *(float2*)(outf + off) = ov;
                } else if (E == 4) {
                    *(uint32_t*)(outhi + off) = pack2(v0, v1);
                } else {
                    v0 = 0.5f * v0 * (1.0f + erff(v0 * 0.70710678118654752f));
                    v1 = 0.5f * v1 * (1.0f + erff(v1 * 0.70710678118654752f));
                    uint32_t lo, hi = split_pack(v0, v1, lo);
                    *(uint32_t*)(outhi + off) = hi;
                    *(uint32_t*)(outlo + off) = lo;
                }
            }
        }
    }
}

// ================= FA2 tensor-core attention (single fp16, cp.async) =====
#define AST 72        // smem row stride in halves
#define ATILE (64 * AST)                 // halves per tile
#define KVSTAGE (2 * ATILE)              // K,V
#define ASMEM ((ATILE + 2 * KVSTAGE) * 2)   // 46080 bytes

__global__ void __launch_bounds__(128) attn_fa2(const __half* __restrict__ q_g,
                                                __half* __restrict__ ohi,
                                                __half* __restrict__ olo)
{
    extern __shared__ __half sb[];
    __half* sQ = sb;
    __half* sKV = sQ + ATILE;    // 2 stages of [K|V]
    uint32_t uQ = smem_to_u32(sQ);
    uint32_t uKV = smem_to_u32(sKV);

    int tid = threadIdx.x, lane = tid & 31, w = tid >> 5;
    int qt = gridDim.x - 1 - blockIdx.x;       // heavy tiles first
    int h = blockIdx.y, b = blockIdx.z;
    size_t qbase = ((size_t)(b * TT + qt * 64)) * QKVC + h * DD;

    int r0 = tid >> 3, uu = tid & 7;

    auto issue_kv = [&](int kt, int s) {
        size_t kbase = ((size_t)(b * TT + kt * 64)) * QKVC + CC + h * DD;
        size_t vbase = kbase + CC;
        uint32_t st = uKV + s * KVSTAGE * 2;
#pragma unroll
        for (int rep = 0; rep < 4; rep++) {
            int r = r0 + rep * 16;
            size_t go = (size_t)r * QKVC + uu * 8;
            uint32_t so = (r * AST + uu * 8) * 2;
            CP_ASYNC16(st + so,             q_g + kbase + go);
            CP_ASYNC16(st + ATILE * 2 + so, q_g + vbase + go);
        }
        CP_COMMIT();
    };

    issue_kv(0, 0);
#pragma unroll
    for (int rep = 0; rep < 4; rep++) {
        int r = r0 + rep * 16;
        *(uint4*)(sQ + r * AST + uu * 8) = *(const uint4*)(q_g + qbase + (size_t)r * QKVC + uu * 8);
    }
    __syncthreads();

    uint32_t qh[4][4];
#pragma unroll
    for (int ks = 0; ks < 4; ks++) {
        uint32_t off = ((16 * w + (lane & 15)) * AST + ks * 16 + (lane >> 4) * 8) * 2;
        ldsm4(qh[ks], uQ + off);
    }

    float m0r = -1e30f, m1r = -1e30f;
    float l0r = 0.f, l1r = 0.f;
    float oacc[8][4] = {};

    for (int kt = 0; kt <= qt; kt++) {
        int s = kt & 1;
        __syncthreads();
        if (kt + 1 <= qt) issue_kv(kt + 1, s ^ 1); else CP_COMMIT();
        CP_WAIT(1);
        __syncthreads();

        uint32_t uK = uKV + (s * KVSTAGE) * 2;
        uint32_t uV = uK + ATILE * 2;

        // ---- S = QK^T ----
        float sacc[8][4] = {};
#pragma unroll
        for (int ks = 0; ks < 4; ks++) {
            uint32_t kb[4][4];
            uint32_t boff = ((lane & 7) + ((lane >> 4) & 1) * 8) * AST + ks * 16 + ((lane >> 3) & 1) * 8;
#pragma unroll
            for (int g = 0; g < 4; g++) ldsm4(kb[g], uK + (boff + g * 16 * AST) * 2);
#pragma unroll
            for (int g = 0; g < 4; g++) {
                mma16816(sacc[g * 2 + 0], qh[ks], &kb[g][0]);
                mma16816(sacc[g * 2 + 1], qh[ks], &kb[g][2]);
            }
        }

        // ---- scale, mask, online softmax ----
        int rl0 = w * 16 + (lane >> 2);
        int rl1 = rl0 + 8;
        float mn0 = m0r, mn1 = m1r;
#pragma unroll
        for (int t = 0; t < 8; t++) {
            sacc[t][0] *= 0.125f; sacc[t][1] *= 0.125f;
            sacc[t][2] *= 0.125f; sacc[t][3] *= 0.125f;
            if (kt == qt) {
                int col = t * 8 + 2 * (lane & 3);
                if (col     > rl0) sacc[t][0] = -1e30f;
                if (col + 1 > rl0) sacc[t][1] = -1e30f;
                if (col     > rl1) sacc[t][2] = -1e30f;
                if (col + 1 > rl1) sacc[t][3] = -1e30f;
            }
            mn0 = fmaxf(mn0, fmaxf(sacc[t][0], sacc[t][1]));
            mn1 = fmaxf(mn1, fmaxf(sacc[t][2], sacc[t][3]));
        }
        mn0 = fmaxf(mn0, __shfl_xor_sync(0xffffffffu, mn0, 1));
        mn0 = fmaxf(mn0, __shfl_xor_sync(0xffffffffu, mn0, 2));
        mn1 = fmaxf(mn1, __shfl_xor_sync(0xffffffffu, mn1, 1));
        mn1 = fmaxf(mn1, __shfl_xor_sync(0xffffffffu, mn1, 2));
        float es0 = __expf(m0r - mn0), es1 = __expf(m1r - mn1);
        m0r = mn0; m1r = mn1;
        float rs0 = 0.f, rs1 = 0.f;
#pragma unroll
        for (int t = 0; t < 8; t++) {
            sacc[t][0] = __expf(sacc[t][0] - mn0);
            sacc[t][1] = __expf(sacc[t][1] - mn0);
            sacc[t][2] = __expf(sacc[t][2] - mn1);
            sacc[t][3] = __expf(sacc[t][3] - mn1);
            rs0 += sacc[t][0] + sacc[t][1];
            rs1 += sacc[t][2] + sacc[t][3];
        }
        rs0 += __shfl_xor_sync(0xffffffffu, rs0, 1);
        rs0 += __shfl_xor_sync(0xffffffffu, rs0, 2);
        rs1 += __shfl_xor_sync(0xffffffffu, rs1, 1);
        rs1 += __shfl_xor_sync(0xffffffffu, rs1, 2);
        l0r = l0r * es0 + rs0;
        l1r = l1r * es1 + rs1;
#pragma unroll
        for (int t = 0; t < 8; t++) {
            oacc[t][0] *= es0; oacc[t][1] *= es0;
            oacc[t][2] *= es1; oacc[t][3] *= es1;
        }

        // ---- PV ----
#pragma unroll
        for (int ks = 0; ks < 4; ks++) {
            uint32_t pa[4];
            pa[0] = pack2(sacc[2 * ks][0],     sacc[2 * ks][1]);
            pa[1] = pack2(sacc[2 * ks][2],     sacc[2 * ks][3]);
            pa[2] = pack2(sacc[2 * ks + 1][0], sacc[2 * ks + 1][1]);
            pa[3] = pack2(sacc[2 * ks + 1][2], sacc[2 * ks + 1][3]);

            uint32_t vb[4][4];
            uint32_t voff = (ks * 16 + (lane & 15)) * AST + ((lane >> 4) & 1) * 8;
#pragma unroll
            for (int g = 0; g < 4; g++) ldsm4t(vb[g], uV + (voff + g * 16) * 2);
#pragma unroll
            for (int g = 0; g < 4; g++) {
                mma16816(oacc[g * 2 + 0], pa, &vb[g][0]);
                mma16816(oacc[g * 2 + 1], pa, &vb[g][2]);
            }
        }
    }

    float inv0 = 1.0f / l0r, inv1 = 1.0f / l1r;
    size_t r0g = (size_t)(b * TT + qt * 64 + w * 16 + (lane >> 2));
    size_t obase0 = r0g * CC + h * DD;
    size_t obase1 = (r0g + 8) * CC + h * DD;
#pragma unroll
    for (int t = 0; t < 8; t++) {
        int d = t * 8 + 2 * (lane & 3);
        uint32_t lo, hi;
        hi = split_pack(oacc[t][0] * inv0, oacc[t][1] * inv0, lo);
        *(uint32_t*)(ohi + obase0 + d) = hi;
        *(uint32_t*)(olo + obase0 + d) = lo;
        hi = split_pack(oacc[t][2] * inv1, oacc[t][3] * inv1, lo);
        *(uint32_t*)(ohi + obase1 + d) = hi;
        *(uint32_t*)(olo + obase1 + d) = lo;
    }
}

// ---------------- launch ----------------
extern "C" void kernel_launch(void* const* d_in, const int* in_sizes, int n_in,
                              void* d_out, int out_size)
{
    const float* x     = (const float*)d_in[0];
    const float* ln1_g = (const float*)d_in[1];
    const float* ln1_b = (const float*)d_in[2];
    const float* qkv_w = (const float*)d_in[3];
    const float* qkv_b = (const float*)d_in[4];
    const float* out_w = (const float*)d_in[5];
    const float* out_b = (const float*)d_in[6];
    const float* ln2_g = (const float*)d_in[7];
    const float* ln2_b = (const float*)d_in[8];
    const float* ff1_w = (const float*)d_in[9];
    const float* ff1_b = (const float*)d_in[10];
    const float* ff2_w = (const float*)d_in[11];
    const float* ff2_b = (const float*)d_in[12];
    float* y = (float*)d_out;

    float *p_x1;
    __half *p_hhi, *p_hlo, *p_q, *p_ahi, *p_alo, *p_fhi, *p_flo;
    __half *p_wqh, *p_woh, *p_w1h, *p_w2h;
    cudaGetSymbolAddress((void**)&p_x1,  g_x1);
    cudaGetSymbolAddress((void**)&p_hhi, g_hhi);
    cudaGetSymbolAddress((void**)&p_hlo, g_hlo);
    cudaGetSymbolAddress((void**)&p_q,   g_q);
    cudaGetSymbolAddress((void**)&p_ahi, g_ahi);
    cudaGetSymbolAddress((void**)&p_alo, g_alo);
    cudaGetSymbolAddress((void**)&p_fhi, g_fhi);
    cudaGetSymbolAddress((void**)&p_flo, g_flo);
    cudaGetSymbolAddress((void**)&p_wqh, g_wqkv_hi);
    cudaGetSymbolAddress((void**)&p_woh, g_wout_hi);
    cudaGetSymbolAddress((void**)&p_w1h, g_wff1_hi);
    cudaGetSymbolAddress((void**)&p_w2h, g_wff2_hi);

    cudaFuncSetAttribute(attn_fa2, cudaFuncAttributeMaxDynamicSharedMemorySize, ASMEM);
    cudaFuncSetAttribute((const void*)gemm_mma<1>, cudaFuncAttributeMaxDynamicSharedMemorySize, GSMEM2);
    cudaFuncSetAttribute((const void*)gemm_mma<2>, cudaFuncAttributeMaxDynamicSharedMemorySize, GSMEM2);
    cudaFuncSetAttribute((const void*)gemm_mma<4>, cudaFuncAttributeMaxDynamicSharedMemorySize, GSMEM2);

    // weight transpose to fp16 (hi only)
    wsplit_kernel<<<dim3(QKVC / 32, CC / 32), dim3(32, 8)>>>(qkv_w, p_wqh, CC, QKVC);
    wsplit_kernel<<<dim3(CC / 32,  CC / 32), dim3(32, 8)>>>(out_w, p_woh, CC, CC);
    wsplit_kernel<<<dim3(FF / 32,  CC / 32), dim3(32, 8)>>>(ff1_w, p_w1h, CC, FF);
    wsplit_kernel<<<dim3(CC / 32,  FF / 32), dim3(32, 8)>>>(ff2_w, p_w2h, FF, CC);

    // 1) h = LN1(x) -> split
    ln_kernel<<<MM, 256>>>(x, ln1_g, ln1_b, p_hhi, p_hlo);
    // 2) qkv = h @ qkv_w + qkv_b -> single fp16
    gemm_mma<4><<<dim3(QKVC / 128, MM / 128), 256, GSMEM2>>>(
        p_hhi, p_hlo, p_wqh, qkv_b, nullptr, nullptr, p_q, nullptr, CC, QKVC);
    // 3) attention -> split
    attn_fa2<<<dim3(TT / 64, HH, BB), 128, ASMEM>>>(p_q, p_ahi, p_alo);
    // 4) x1 = x + att @ out_w + out_b
    gemm_mma<1><<<dim3(CC / 128, MM / 128), 256, GSMEM2>>>(
        p_ahi, p_alo, p_woh, out_b, x, p_x1, nullptr, nullptr, CC, CC);
    // 5) h = LN2(x1) -> split
    ln_kernel<<<MM, 256>>>(p_x1, ln2_g, ln2_b, p_hhi, p_hlo);
    // 6) ff = gelu(h @ ff1_w + ff1_b) -> split
    gemm_mma<2><<<dim3(FF / 128, MM / 128), 256, GSMEM2>>>(
        p_hhi, p_hlo, p_w1h, ff1_b, nullptr, nullptr, p_fhi, p_flo, CC, FF);
    // 7) y = x1 + ff @ ff2_w + ff2_b
    gemm_mma<1><<<dim3(CC / 128, MM / 128), 256, GSMEM2>>>(
        p_fhi, p_flo, p_w2h, ff2_b, p_x1, y, nullptr, nullptr, FF, CC);
}

// round 10
// speedup vs baseline: 13.6026x; 1.7588x over previous
#include <cuda_runtime.h>
#include <cuda_fp16.h>
#include <math.h>
#include <stdint.h>

// ---------------- problem constants ----------------
#define BB   2
#define TT   2048
#define CC   1024
#define HH   16
#define DD   64
#define FF   4096
#define MM   (BB*TT)          // 4096 rows
#define QKVC (3*CC)           // 3072

// ---------------- scratch (device globals; no allocs allowed) ----------------
__device__ float g_x1 [MM*CC];                   // residual stream after attn
__device__ alignas(128) __half g_h [MM*CC];      // LN out fp16
__device__ alignas(128) __half g_q [MM*QKVC];    // qkv fp16
__device__ alignas(128) __half g_a [MM*CC];      // attn out fp16
__device__ alignas(128) __half g_f [MM*FF];      // gelu out fp16
// transposed fp16 weights: Wt[n][k]
__device__ alignas(128) __half g_wqkv[CC*QKVC];
__device__ alignas(128) __half g_wout[CC*CC];
__device__ alignas(128) __half g_wff1[CC*FF];
__device__ alignas(128) __half g_wff2[FF*CC];

// ================= helpers =================
__device__ __forceinline__ uint32_t smem_to_u32(const void* p) {
    uint32_t a;
    asm("{ .reg .u64 t; cvta.to.shared.u64 t, %1; cvt.u32.u64 %0, t; }" : "=r"(a) : "l"(p));
    return a;
}
#define CP_ASYNC16(dst, src) \
    asm volatile("cp.async.cg.shared.global [%0], [%1], 16;" :: "r"(dst), "l"(src))
#define CP_COMMIT() asm volatile("cp.async.commit_group;" ::: "memory")
#define CP_WAIT(n)  asm volatile("cp.async.wait_group %0;" :: "n"(n) : "memory")

__device__ __forceinline__ void ldsm4(uint32_t* r, uint32_t addr) {
    asm volatile("ldmatrix.sync.aligned.m8n8.x4.shared.b16 {%0,%1,%2,%3}, [%4];"
                 : "=r"(r[0]), "=r"(r[1]), "=r"(r[2]), "=r"(r[3]) : "r"(addr));
}
__device__ __forceinline__ void ldsm4t(uint32_t* r, uint32_t addr) {
    asm volatile("ldmatrix.sync.aligned.m8n8.x4.trans.shared.b16 {%0,%1,%2,%3}, [%4];"
                 : "=r"(r[0]), "=r"(r[1]), "=r"(r[2]), "=r"(r[3]) : "r"(addr));
}
__device__ __forceinline__ void mma16816(float* c, const uint32_t* a, const uint32_t* b) {
    asm volatile("mma.sync.aligned.m16n8k16.row.col.f32.f16.f16.f32 "
                 "{%0,%1,%2,%3}, {%4,%5,%6,%7}, {%8,%9}, {%0,%1,%2,%3};"
                 : "+f"(c[0]), "+f"(c[1]), "+f"(c[2]), "+f"(c[3])
                 : "r"(a[0]), "r"(a[1]), "r"(a[2]), "r"(a[3]), "r"(b[0]), "r"(b[1]));
}
__device__ __forceinline__ uint32_t pack2(float x0, float x1) {
    __half2 h = __floats2half2_rn(x0, x1);
    return *(uint32_t*)&h;
}

// ================= weight transpose to fp16 =================
// W[K][N] row-major -> Wt[N][K]
__global__ void __launch_bounds__(256) wsplit_kernel(const float* __restrict__ W,
                                                     __half* __restrict__ Wt,
                                                     int K, int N)
{
    __shared__ float t[32][33];
    int tx = threadIdx.x, ty = threadIdx.y;   // block (32,8)
    int n0 = blockIdx.x * 32, k0 = blockIdx.y * 32;
#pragma unroll
    for (int i = 0; i < 4; i++)
        t[ty + 8 * i][tx] = W[(size_t)(k0 + ty + 8 * i) * N + n0 + tx];
    __syncthreads();
#pragma unroll
    for (int i = 0; i < 4; i++) {
        int n = n0 + ty + 8 * i, k = k0 + tx;
        Wt[(size_t)n * K + k] = __float2half(t[tx][ty + 8 * i]);
    }
}

// ================= LayerNorm -> fp16 (vectorized) =================
__global__ void __launch_bounds__(256) ln_kernel(const float* __restrict__ x,
                                                 const float* __restrict__ g,
                                                 const float* __restrict__ b,
                                                 __half* __restrict__ y)
{
    int row = blockIdx.x;
    int tid = threadIdx.x;
    float4 v = ((const float4*)(x + (size_t)row * CC))[tid];
    float s1 = v.x + v.y + v.z + v.w;
    float s2 = v.x * v.x + v.y * v.y + v.z * v.z + v.w * v.w;
#pragma unroll
    for (int o = 16; o; o >>= 1) {
        s1 += __shfl_xor_sync(0xffffffffu, s1, o);
        s2 += __shfl_xor_sync(0xffffffffu, s2, o);
    }
    __shared__ float r1[8], r2[8], sh_mean, sh_rstd;
    if ((tid & 31) == 0) { r1[tid >> 5] = s1; r2[tid >> 5] = s2; }
    __syncthreads();
    if (tid == 0) {
        float t1 = 0.f, t2 = 0.f;
#pragma unroll
        for (int i = 0; i < 8; i++) { t1 += r1[i]; t2 += r2[i]; }
        float mean = t1 * (1.0f / CC);
        float var  = t2 * (1.0f / CC) - mean * mean;
        sh_mean = mean;
        sh_rstd = rsqrtf(var + 1e-5f);
    }
    __syncthreads();
    float mean = sh_mean, rstd = sh_rstd;
    float4 gv = ((const float4*)g)[tid];
    float4 bv = ((const float4*)b)[tid];
    uint2 hv;
    hv.x = pack2((v.x - mean) * rstd * gv.x + bv.x, (v.y - mean) * rstd * gv.y + bv.y);
    hv.y = pack2((v.z - mean) * rstd * gv.z + bv.z, (v.w - mean) * rstd * gv.w + bv.w);
    *(uint2*)(y + (size_t)row * CC + tid * 4) = hv;
}

// ================= mma.sync GEMM (plain fp16) =================
// C = A*B + bias   A[M][K], B = Wt[N][K] fp16
// E: 1 = fp32 out (+bias+res); 2 = gelu -> fp16; 4 = fp16 (+bias).
#define GS 4
#define SSTRIDE 40                         // halves per row
#define TILE_B (128*SSTRIDE*2)             // 10240 bytes
#define GSMEM2 (GS * 2 * TILE_B)           // 81920

template<int E>
__global__ void __launch_bounds__(256, 2) gemm_mma(const __half* __restrict__ A,
                                                   const __half* __restrict__ B,
                                                   const float* __restrict__ bias,
                                                   const float* __restrict__ res,
                                                   float* __restrict__ outf,
                                                   __half* __restrict__ outh,
                                                   int K, int gN)
{
    constexpr uint32_t STAGE = 2 * TILE_B;
    extern __shared__ char smem[];
    uint32_t sbase = smem_to_u32(smem);
    int tid = threadIdx.x, lane = tid & 31, wid = tid >> 5;
    int bx = blockIdx.x, by = blockIdx.y;
    const int NK = K >> 5;
    int m0 = (wid & 3) * 32, n0 = (wid >> 2) * 64;

    const __half* Ap = A + (size_t)(by * 128) * K;
    const __half* Bp = B + (size_t)(bx * 128) * K;

    int u = tid & 3;        // 16B unit within 64B row
    int r0 = tid >> 2;      // 0..63

    auto issue = [&](int kk) {
        uint32_t st = sbase + (kk & (GS - 1)) * STAGE;
#pragma unroll
        for (int rr = 0; rr < 2; rr++) {
            int r = r0 + rr * 64;
            size_t go = (size_t)r * K + kk * 32 + u * 8;
            uint32_t so = (r * SSTRIDE + u * 8) * 2;
            CP_ASYNC16(st + so,          Ap + go);
            CP_ASYNC16(st + TILE_B + so, Bp + go);
        }
        CP_COMMIT();
    };

    float acc[2][8][4] = {};

    for (int c = 0; c < GS - 1; c++) issue(c);

    for (int c = 0; c < NK; c++) {
        CP_WAIT(GS - 2);          // stage c complete
        __syncthreads();          // all warps done reading stage (c-1)
        if (c + GS - 1 < NK) issue(c + GS - 1); else CP_COMMIT();

        uint32_t st = sbase + (c & (GS - 1)) * STAGE;
#pragma unroll
        for (int kh = 0; kh < 2; kh++) {
            uint32_t ah[2][4];
#pragma unroll
            for (int i = 0; i < 2; i++) {
                uint32_t aoff = ((m0 + i * 16 + (lane & 15)) * SSTRIDE + kh * 16 + (lane >> 4) * 8) * 2;
                ldsm4(ah[i], st + aoff);
            }
            uint32_t boff = ((n0 + (lane & 7) + ((lane >> 4) & 1) * 8) * SSTRIDE
                             + kh * 16 + ((lane >> 3) & 1) * 8) * 2;
            uint32_t bh[4][4];
#pragma unroll
            for (int g = 0; g < 4; g++) ldsm4(bh[g], st + TILE_B + boff + g * 16 * SSTRIDE * 2);
#pragma unroll
            for (int i = 0; i < 2; i++)
#pragma unroll
                for (int g = 0; g < 4; g++) {
                    mma16816(acc[i][g * 2 + 0], ah[i], &bh[g][0]);
                    mma16816(acc[i][g * 2 + 1], ah[i], &bh[g][2]);
                }
        }
    }

    // epilogue from registers
    int mb = by * 128 + m0;
    int nb = bx * 128 + n0;
#pragma unroll
    for (int i = 0; i < 2; i++) {
#pragma unroll
        for (int j = 0; j < 8; j++) {
            float* cc = acc[i][j];
            int n = nb + j * 8 + (lane & 3) * 2;
            float b0 = bias[n], b1 = bias[n + 1];
#pragma unroll
            for (int hrow = 0; hrow < 2; hrow++) {
                int m = mb + i * 16 + (lane >> 2) + hrow * 8;
                float v0 = cc[hrow * 2 + 0] + b0;
                float v1 = cc[hrow * 2 + 1] + b1;
                size_t off = (size_t)m * gN + n;
                if (E == 1) {
                    float2 rv = *(const float2*)(res + off);
                    v0 += rv.x; v1 += rv.y;
                    float2 ov; ov.x = v0; ov.y = v1;
                    *(float2*)(outf + off) = ov;
                } else if (E == 4) {
                    *(uint32_t*)(outh + off) = pack2(v0, v1);
                } else {
                    v0 = 0.5f * v0 * (1.0f + erff(v0 * 0.70710678118654752f));
                    v1 = 0.5f * v1 * (1.0f + erff(v1 * 0.70710678118654752f));
                    *(uint32_t*)(outh + off) = pack2(v0, v1);
                }
            }
        }
    }
}

// ================= FA2 tensor-core attention (fp16, cp.async) =====
#define AST 72        // smem row stride in halves
#define ATILE (64 * AST)                 // halves per tile
#define KVSTAGE (2 * ATILE)              // K,V
#define ASMEM ((ATILE + 2 * KVSTAGE) * 2)   // 46080 bytes

__global__ void __launch_bounds__(128) attn_fa2(const __half* __restrict__ q_g,
                                                __half* __restrict__ o_g)
{
    extern __shared__ __half sb[];
    __half* sQ = sb;
    __half* sKV = sQ + ATILE;    // 2 stages of [K|V]
    uint32_t uQ = smem_to_u32(sQ);
    uint32_t uKV = smem_to_u32(sKV);

    int tid = threadIdx.x, lane = tid & 31, w = tid >> 5;
    int qt = gridDim.x - 1 - blockIdx.x;       // heavy tiles first
    int h = blockIdx.y, b = blockIdx.z;
    size_t qbase = ((size_t)(b * TT + qt * 64)) * QKVC + h * DD;

    int r0 = tid >> 3, uu = tid & 7;

    auto issue_kv = [&](int kt, int s) {
        size_t kbase = ((size_t)(b * TT + kt * 64)) * QKVC + CC + h * DD;
        size_t vbase = kbase + CC;
        uint32_t st = uKV + s * KVSTAGE * 2;
#pragma unroll
        for (int rep = 0; rep < 4; rep++) {
            int r = r0 + rep * 16;
            size_t go = (size_t)r * QKVC + uu * 8;
            uint32_t so = (r * AST + uu * 8) * 2;
            CP_ASYNC16(st + so,             q_g + kbase + go);
            CP_ASYNC16(st + ATILE * 2 + so, q_g + vbase + go);
        }
        CP_COMMIT();
    };

    issue_kv(0, 0);
#pragma unroll
    for (int rep = 0; rep < 4; rep++) {
        int r = r0 + rep * 16;
        *(uint4*)(sQ + r * AST + uu * 8) = *(const uint4*)(q_g + qbase + (size_t)r * QKVC + uu * 8);
    }
    __syncthreads();

    uint32_t qh[4][4];
#pragma unroll
    for (int ks = 0; ks < 4; ks++) {
        uint32_t off = ((16 * w + (lane & 15)) * AST + ks * 16 + (lane >> 4) * 8) * 2;
        ldsm4(qh[ks], uQ + off);
    }

    float m0r = -1e30f, m1r = -1e30f;
    float l0r = 0.f, l1r = 0.f;
    float oacc[8][4] = {};

    for (int kt = 0; kt <= qt; kt++) {
        int s = kt & 1;
        __syncthreads();
        if (kt + 1 <= qt) issue_kv(kt + 1, s ^ 1); else CP_COMMIT();
        CP_WAIT(1);
        __syncthreads();

        uint32_t uK = uKV + (s * KVSTAGE) * 2;
        uint32_t uV = uK + ATILE * 2;

        // ---- S = QK^T ----
        float sacc[8][4] = {};
#pragma unroll
        for (int ks = 0; ks < 4; ks++) {
            uint32_t kb[4][4];
            uint32_t boff = ((lane & 7) + ((lane >> 4) & 1) * 8) * AST + ks * 16 + ((lane >> 3) & 1) * 8;
#pragma unroll
            for (int g = 0; g < 4; g++) ldsm4(kb[g], uK + (boff + g * 16 * AST) * 2);
#pragma unroll
            for (int g = 0; g < 4; g++) {
                mma16816(sacc[g * 2 + 0], qh[ks], &kb[g][0]);
                mma16816(sacc[g * 2 + 1], qh[ks], &kb[g][2]);
            }
        }

        // ---- scale, mask, online softmax ----
        int rl0 = w * 16 + (lane >> 2);
        int rl1 = rl0 + 8;
        float mn0 = m0r, mn1 = m1r;
#pragma unroll
        for (int t = 0; t < 8; t++) {
            sacc[t][0] *= 0.125f; sacc[t][1] *= 0.125f;
            sacc[t][2] *= 0.125f; sacc[t][3] *= 0.125f;
            if (kt == qt) {
                int col = t * 8 + 2 * (lane & 3);
                if (col     > rl0) sacc[t][0] = -1e30f;
                if (col + 1 > rl0) sacc[t][1] = -1e30f;
                if (col     > rl1) sacc[t][2] = -1e30f;
                if (col + 1 > rl1) sacc[t][3] = -1e30f;
            }
            mn0 = fmaxf(mn0, fmaxf(sacc[t][0], sacc[t][1]));
            mn1 = fmaxf(mn1, fmaxf(sacc[t][2], sacc[t][3]));
        }
        mn0 = fmaxf(mn0, __shfl_xor_sync(0xffffffffu, mn0, 1));
        mn0 = fmaxf(mn0, __shfl_xor_sync(0xffffffffu, mn0, 2));
        mn1 = fmaxf(mn1, __shfl_xor_sync(0xffffffffu, mn1, 1));
        mn1 = fmaxf(mn1, __shfl_xor_sync(0xffffffffu, mn1, 2));
        float es0 = __expf(m0r - mn0), es1 = __expf(m1r - mn1);
        m0r = mn0; m1r = mn1;
        float rs0 = 0.f, rs1 = 0.f;
#pragma unroll
        for (int t = 0; t < 8; t++) {
            sacc[t][0] = __expf(sacc[t][0] - mn0);
            sacc[t][1] = __expf(sacc[t][1] - mn0);
            sacc[t][2] = __expf(sacc[t][2] - mn1);
            sacc[t][3] = __expf(sacc[t][3] - mn1);
            rs0 += sacc[t][0] + sacc[t][1];
            rs1 += sacc[t][2] + sacc[t][3];
        }
        rs0 += __shfl_xor_sync(0xffffffffu, rs0, 1);
        rs0 += __shfl_xor_sync(0xffffffffu, rs0, 2);
        rs1 += __shfl_xor_sync(0xffffffffu, rs1, 1);
        rs1 += __shfl_xor_sync(0xffffffffu, rs1, 2);
        l0r = l0r * es0 + rs0;
        l1r = l1r * es1 + rs1;
#pragma unroll
        for (int t = 0; t < 8; t++) {
            oacc[t][0] *= es0; oacc[t][1] *= es0;
            oacc[t][2] *= es1; oacc[t][3] *= es1;
        }

        // ---- PV ----
#pragma unroll
        for (int ks = 0; ks < 4; ks++) {
            uint32_t pa[4];
            pa[0] = pack2(sacc[2 * ks][0],     sacc[2 * ks][1]);
            pa[1] = pack2(sacc[2 * ks][2],     sacc[2 * ks][3]);
            pa[2] = pack2(sacc[2 * ks + 1][0], sacc[2 * ks + 1][1]);
            pa[3] = pack2(sacc[2 * ks + 1][2], sacc[2 * ks + 1][3]);

            uint32_t vb[4][4];
            uint32_t voff = (ks * 16 + (lane & 15)) * AST + ((lane >> 4) & 1) * 8;
#pragma unroll
            for (int g = 0; g < 4; g++) ldsm4t(vb[g], uV + (voff + g * 16) * 2);
#pragma unroll
            for (int g = 0; g < 4; g++) {
                mma16816(oacc[g * 2 + 0], pa, &vb[g][0]);
                mma16816(oacc[g * 2 + 1], pa, &vb[g][2]);
            }
        }
    }

    float inv0 = 1.0f / l0r, inv1 = 1.0f / l1r;
    size_t r0g = (size_t)(b * TT + qt * 64 + w * 16 + (lane >> 2));
    size_t obase0 = r0g * CC + h * DD;
    size_t obase1 = (r0g + 8) * CC + h * DD;
#pragma unroll
    for (int t = 0; t < 8; t++) {
        int d = t * 8 + 2 * (lane & 3);
        *(uint32_t*)(o_g + obase0 + d) = pack2(oacc[t][0] * inv0, oacc[t][1] * inv0);
        *(uint32_t*)(o_g + obase1 + d) = pack2(oacc[t][2] * inv1, oacc[t][3] * inv1);
    }
}

// ---------------- launch ----------------
extern "C" void kernel_launch(void* const* d_in, const int* in_sizes, int n_in,
                              void* d_out, int out_size)
{
    const float* x     = (const float*)d_in[0];
    const float* ln1_g = (const float*)d_in[1];
    const float* ln1_b = (const float*)d_in[2];
    const float* qkv_w = (const float*)d_in[3];
    const float* qkv_b = (const float*)d_in[4];
    const float* out_w = (const float*)d_in[5];
    const float* out_b = (const float*)d_in[6];
    const float* ln2_g = (const float*)d_in[7];
    const float* ln2_b = (const float*)d_in[8];
    const float* ff1_w = (const float*)d_in[9];
    const float* ff1_b = (const float*)d_in[10];
    const float* ff2_w = (const float*)d_in[11];
    const float* ff2_b = (const float*)d_in[12];
    float* y = (float*)d_out;

    float *p_x1;
    __half *p_h, *p_q, *p_a, *p_f;
    __half *p_wq, *p_wo, *p_w1, *p_w2;
    cudaGetSymbolAddress((void**)&p_x1, g_x1);
    cudaGetSymbolAddress((void**)&p_h,  g_h);
    cudaGetSymbolAddress((void**)&p_q,  g_q);
    cudaGetSymbolAddress((void**)&p_a,  g_a);
    cudaGetSymbolAddress((void**)&p_f,  g_f);
    cudaGetSymbolAddress((void**)&p_wq, g_wqkv);
    cudaGetSymbolAddress((void**)&p_wo, g_wout);
    cudaGetSymbolAddress((void**)&p_w1, g_wff1);
    cudaGetSymbolAddress((void**)&p_w2, g_wff2);

    cudaFuncSetAttribute(attn_fa2, cudaFuncAttributeMaxDynamicSharedMemorySize, ASMEM);
    cudaFuncSetAttribute((const void*)gemm_mma<1>, cudaFuncAttributeMaxDynamicSharedMemorySize, GSMEM2);
    cudaFuncSetAttribute((const void*)gemm_mma<2>, cudaFuncAttributeMaxDynamicSharedMemorySize, GSMEM2);
    cudaFuncSetAttribute((const void*)gemm_mma<4>, cudaFuncAttributeMaxDynamicSharedMemorySize, GSMEM2);

    // weight transpose to fp16
    wsplit_kernel<<<dim3(QKVC / 32, CC / 32), dim3(32, 8)>>>(qkv_w, p_wq, CC, QKVC);
    wsplit_kernel<<<dim3(CC / 32,  CC / 32), dim3(32, 8)>>>(out_w, p_wo, CC, CC);
    wsplit_kernel<<<dim3(FF / 32,  CC / 32), dim3(32, 8)>>>(ff1_w, p_w1, CC, FF);
    wsplit_kernel<<<dim3(CC / 32,  FF / 32), dim3(32, 8)>>>(ff2_w, p_w2, FF, CC);

    // 1) h = LN1(x) -> fp16
    ln_kernel<<<MM, 256>>>(x, ln1_g, ln1_b, p_h);
    // 2) qkv = h @ qkv_w + qkv_b -> fp16
    gemm_mma<4><<<dim3(QKVC / 128, MM / 128), 256, GSMEM2>>>(
        p_h, p_wq, qkv_b, nullptr, nullptr, p_q, CC, QKVC);
    // 3) attention -> fp16
    attn_fa2<<<dim3(TT / 64, HH, BB), 128, ASMEM>>>(p_q, p_a);
    // 4) x1 = x + att @ out_w + out_b  (fp32)
    gemm_mma<1><<<dim3(CC / 128, MM / 128), 256, GSMEM2>>>(
        p_a, p_wo, out_b, x, p_x1, nullptr, CC, CC);
    // 5) h = LN2(x1) -> fp16
    ln_kernel<<<MM, 256>>>(p_x1, ln2_g, ln2_b, p_h);
    // 6) ff = gelu(h @ ff1_w + ff1_b) -> fp16
    gemm_mma<2><<<dim3(FF / 128, MM / 128), 256, GSMEM2>>>(
        p_h, p_w1, ff1_b, nullptr, nullptr, p_f, CC, FF);
    // 7) y = x1 + ff @ ff2_w + ff2_b
    gemm_mma<1><<<dim3(CC / 128, MM / 128), 256, GSMEM2>>>(
        p_f, p_w2, ff2_b, p_x1, y, nullptr, FF, CC);
}

// round 11
// speedup vs baseline: 14.9722x; 1.1007x over previous
#include <cuda_runtime.h>
#include <cuda_fp16.h>
#include <math.h>
#include <stdint.h>

// ---------------- problem constants ----------------
#define BB   2
#define TT   2048
#define CC   1024
#define HH   16
#define DD   64
#define FF   4096
#define MM   (BB*TT)          // 4096 rows
#define QKVC (3*CC)           // 3072

// ---------------- scratch (device globals; no allocs allowed) ----------------
__device__ float g_x1 [MM*CC];                   // residual stream after attn
__device__ alignas(128) __half g_h [MM*CC];      // LN out fp16
__device__ alignas(128) __half g_q [MM*QKVC];    // qkv fp16
__device__ alignas(128) __half g_a [MM*CC];      // attn out fp16
__device__ alignas(128) __half g_f [MM*FF];      // gelu out fp16
// fp16 weights, SAME layout as input: W[K][N]
__device__ alignas(128) __half g_wqkv[CC*QKVC];
__device__ alignas(128) __half g_wout[CC*CC];
__device__ alignas(128) __half g_wff1[CC*FF];
__device__ alignas(128) __half g_wff2[FF*CC];

// ================= helpers =================
__device__ __forceinline__ uint32_t smem_to_u32(const void* p) {
    uint32_t a;
    asm("{ .reg .u64 t; cvta.to.shared.u64 t, %1; cvt.u32.u64 %0, t; }" : "=r"(a) : "l"(p));
    return a;
}
#define CP_ASYNC16(dst, src) \
    asm volatile("cp.async.cg.shared.global [%0], [%1], 16;" :: "r"(dst), "l"(src))
#define CP_COMMIT() asm volatile("cp.async.commit_group;" ::: "memory")
#define CP_WAIT(n)  asm volatile("cp.async.wait_group %0;" :: "n"(n) : "memory")

__device__ __forceinline__ void ldsm4(uint32_t* r, uint32_t addr) {
    asm volatile("ldmatrix.sync.aligned.m8n8.x4.shared.b16 {%0,%1,%2,%3}, [%4];"
                 : "=r"(r[0]), "=r"(r[1]), "=r"(r[2]), "=r"(r[3]) : "r"(addr));
}
__device__ __forceinline__ void ldsm4t(uint32_t* r, uint32_t addr) {
    asm volatile("ldmatrix.sync.aligned.m8n8.x4.trans.shared.b16 {%0,%1,%2,%3}, [%4];"
                 : "=r"(r[0]), "=r"(r[1]), "=r"(r[2]), "=r"(r[3]) : "r"(addr));
}
__device__ __forceinline__ void mma16816(float* c, const uint32_t* a, const uint32_t* b) {
    asm volatile("mma.sync.aligned.m16n8k16.row.col.f32.f16.f16.f32 "
                 "{%0,%1,%2,%3}, {%4,%5,%6,%7}, {%8,%9}, {%0,%1,%2,%3};"
                 : "+f"(c[0]), "+f"(c[1]), "+f"(c[2]), "+f"(c[3])
                 : "r"(a[0]), "r"(a[1]), "r"(a[2]), "r"(a[3]), "r"(b[0]), "r"(b[1]));
}
__device__ __forceinline__ uint32_t pack2(float x0, float x1) {
    __half2 h = __floats2half2_rn(x0, x1);
    return *(uint32_t*)&h;
}

// ================= weight convert fp32 -> fp16 (same layout) =================
__global__ void __launch_bounds__(256) wconv_kernel(const float* __restrict__ W,
                                                    __half* __restrict__ Wh)
{
    size_t i = ((size_t)blockIdx.x * 256 + threadIdx.x) * 8;
    float4 a = *(const float4*)(W + i);
    float4 c = *(const float4*)(W + i + 4);
    uint4 o;
    o.x = pack2(a.x, a.y); o.y = pack2(a.z, a.w);
    o.z = pack2(c.x, c.y); o.w = pack2(c.z, c.w);
    *(uint4*)(Wh + i) = o;
}

// ================= LayerNorm -> fp16 (vectorized) =================
__global__ void __launch_bounds__(256) ln_kernel(const float* __restrict__ x,
                                                 const float* __restrict__ g,
                                                 const float* __restrict__ b,
                                                 __half* __restrict__ y)
{
    int row = blockIdx.x;
    int tid = threadIdx.x;
    float4 v = ((const float4*)(x + (size_t)row * CC))[tid];
    float s1 = v.x + v.y + v.z + v.w;
    float s2 = v.x * v.x + v.y * v.y + v.z * v.z + v.w * v.w;
#pragma unroll
    for (int o = 16; o; o >>= 1) {
        s1 += __shfl_xor_sync(0xffffffffu, s1, o);
        s2 += __shfl_xor_sync(0xffffffffu, s2, o);
    }
    __shared__ float r1[8], r2[8], sh_mean, sh_rstd;
    if ((tid & 31) == 0) { r1[tid >> 5] = s1; r2[tid >> 5] = s2; }
    __syncthreads();
    if (tid == 0) {
        float t1 = 0.f, t2 = 0.f;
#pragma unroll
        for (int i = 0; i < 8; i++) { t1 += r1[i]; t2 += r2[i]; }
        float mean = t1 * (1.0f / CC);
        float var  = t2 * (1.0f / CC) - mean * mean;
        sh_mean = mean;
        sh_rstd = rsqrtf(var + 1e-5f);
    }
    __syncthreads();
    float mean = sh_mean, rstd = sh_rstd;
    float4 gv = ((const float4*)g)[tid];
    float4 bv = ((const float4*)b)[tid];
    uint2 hv;
    hv.x = pack2((v.x - mean) * rstd * gv.x + bv.x, (v.y - mean) * rstd * gv.y + bv.y);
    hv.y = pack2((v.z - mean) * rstd * gv.z + bv.z, (v.w - mean) * rstd * gv.w + bv.w);
    *(uint2*)(y + (size_t)row * CC + tid * 4) = hv;
}

// ================= mma.sync GEMM (plain fp16, B K-major) =================
// C = A*B + bias   A[M][K] fp16, B = W[K][gN] fp16 (K-major; trans-ldsm frags)
// E: 1 = fp32 out (+bias+res); 2 = gelu -> fp16; 4 = fp16 (+bias).
#define GS 4
#define SSTRIDE 40                          // A smem row stride (halves)
#define TILE_A (128*SSTRIDE*2)              // 10240 bytes
#define SBST 136                            // B smem row stride (halves) = 272B
#define TILE_BK (32*SBST*2)                 // 8704 bytes
#define STAGE_SZ (TILE_A + TILE_BK)         // 18944
#define GSMEM2 (GS * STAGE_SZ)              // 75776

template<int E>
__global__ void __launch_bounds__(256, 2) gemm_mma(const __half* __restrict__ A,
                                                   const __half* __restrict__ B,
                                                   const float* __restrict__ bias,
                                                   const float* __restrict__ res,
                                                   float* __restrict__ outf,
                                                   __half* __restrict__ outh,
                                                   int K, int gN)
{
    extern __shared__ char smem[];
    uint32_t sbase = smem_to_u32(smem);
    int tid = threadIdx.x, lane = tid & 31, wid = tid >> 5;
    int bx = blockIdx.x, by = blockIdx.y;
    const int NK = K >> 5;
    int m0 = (wid & 3) * 32, n0 = (wid >> 2) * 64;

    const __half* Ap = A + (size_t)(by * 128) * K;
    const __half* Bp = B + bx * 128;         // [K][gN], col offset

    int uA = tid & 3;        // A: 16B unit within 64B row
    int rA = tid >> 2;       // 0..63
    int uB = tid & 15;       // B: 16B unit within 256B row
    int rB = tid >> 4;       // 0..15

    auto issue = [&](int kk) {
        uint32_t st = sbase + (kk & (GS - 1)) * STAGE_SZ;
#pragma unroll
        for (int rr = 0; rr < 2; rr++) {
            int r = rA + rr * 64;
            CP_ASYNC16(st + (r * SSTRIDE + uA * 8) * 2,
                       Ap + (size_t)r * K + kk * 32 + uA * 8);
        }
        uint32_t stB = st + TILE_A;
#pragma unroll
        for (int rr = 0; rr < 2; rr++) {
            int r = rB + rr * 16;
            CP_ASYNC16(stB + (r * SBST + uB * 8) * 2,
                       Bp + (size_t)(kk * 32 + r) * gN + uB * 8);
        }
        CP_COMMIT();
    };

    float acc[2][8][4] = {};

    for (int c = 0; c < GS - 1; c++) issue(c);

    for (int c = 0; c < NK; c++) {
        CP_WAIT(GS - 2);          // stage c complete
        __syncthreads();          // all warps done reading stage (c-1)
        if (c + GS - 1 < NK) issue(c + GS - 1); else CP_COMMIT();

        uint32_t st = sbase + (c & (GS - 1)) * STAGE_SZ;
        uint32_t stB = st + TILE_A;
#pragma unroll
        for (int kh = 0; kh < 2; kh++) {
            uint32_t ah[2][4];
#pragma unroll
            for (int i = 0; i < 2; i++) {
                uint32_t aoff = ((m0 + i * 16 + (lane & 15)) * SSTRIDE + kh * 16 + (lane >> 4) * 8) * 2;
                ldsm4(ah[i], st + aoff);
            }
            // B frags: trans-ldsm over [k][n] tile (mirrors attention V pattern)
            uint32_t boff = (kh * 16 + (lane & 15)) * SBST + n0 + ((lane >> 4) & 1) * 8;
            uint32_t bh[4][4];
#pragma unroll
            for (int g = 0; g < 4; g++) ldsm4t(bh[g], stB + (boff + g * 16) * 2);
#pragma unroll
            for (int i = 0; i < 2; i++)
#pragma unroll
                for (int g = 0; g < 4; g++) {
                    mma16816(acc[i][g * 2 + 0], ah[i], &bh[g][0]);
                    mma16816(acc[i][g * 2 + 1], ah[i], &bh[g][2]);
                }
        }
    }

    // epilogue from registers
    int mb = by * 128 + m0;
    int nb = bx * 128 + n0;
#pragma unroll
    for (int i = 0; i < 2; i++) {
#pragma unroll
        for (int j = 0; j < 8; j++) {
            float* cc = acc[i][j];
            int n = nb + j * 8 + (lane & 3) * 2;
            float b0 = bias[n], b1 = bias[n + 1];
#pragma unroll
            for (int hrow = 0; hrow < 2; hrow++) {
                int m = mb + i * 16 + (lane >> 2) + hrow * 8;
                float v0 = cc[hrow * 2 + 0] + b0;
                float v1 = cc[hrow * 2 + 1] + b1;
                size_t off = (size_t)m * gN + n;
                if (E == 1) {
                    float2 rv = *(const float2*)(res + off);
                    v0 += rv.x; v1 += rv.y;
                    float2 ov; ov.x = v0; ov.y = v1;
                    *(float2*)(outf + off) = ov;
                } else if (E == 4) {
                    *(uint32_t*)(outh + off) = pack2(v0, v1);
                } else {
                    v0 = 0.5f * v0 * (1.0f + erff(v0 * 0.70710678118654752f));
                    v1 = 0.5f * v1 * (1.0f + erff(v1 * 0.70710678118654752f));
                    *(uint32_t*)(outh + off) = pack2(v0, v1);
                }
            }
        }
    }
}

// ================= FA2 tensor-core attention (fp16, cp.async) =====
#define AST 72        // smem row stride in halves
#define ATILE (64 * AST)                 // halves per tile
#define KVSTAGE (2 * ATILE)              // K,V
#define ASMEM ((ATILE + 2 * KVSTAGE) * 2)   // 46080 bytes

__global__ void __launch_bounds__(128) attn_fa2(const __half* __restrict__ q_g,
                                                __half* __restrict__ o_g)
{
    extern __shared__ __half sb[];
    __half* sQ = sb;
    __half* sKV = sQ + ATILE;    // 2 stages of [K|V]
    uint32_t uQ = smem_to_u32(sQ);
    uint32_t uKV = smem_to_u32(sKV);

    int tid = threadIdx.x, lane = tid & 31, w = tid >> 5;
    int qt = gridDim.x - 1 - blockIdx.x;       // heavy tiles first
    int h = blockIdx.y, b = blockIdx.z;
    size_t qbase = ((size_t)(b * TT + qt * 64)) * QKVC + h * DD;

    int r0 = tid >> 3, uu = tid & 7;

    auto issue_kv = [&](int kt, int s) {
        size_t kbase = ((size_t)(b * TT + kt * 64)) * QKVC + CC + h * DD;
        size_t vbase = kbase + CC;
        uint32_t st = uKV + s * KVSTAGE * 2;
#pragma unroll
        for (int rep = 0; rep < 4; rep++) {
            int r = r0 + rep * 16;
            size_t go = (size_t)r * QKVC + uu * 8;
            uint32_t so = (r * AST + uu * 8) * 2;
            CP_ASYNC16(st + so,             q_g + kbase + go);
            CP_ASYNC16(st + ATILE * 2 + so, q_g + vbase + go);
        }
        CP_COMMIT();
    };

    issue_kv(0, 0);
#pragma unroll
    for (int rep = 0; rep < 4; rep++) {
        int r = r0 + rep * 16;
        *(uint4*)(sQ + r * AST + uu * 8) = *(const uint4*)(q_g + qbase + (size_t)r * QKVC + uu * 8);
    }
    __syncthreads();

    uint32_t qh[4][4];
#pragma unroll
    for (int ks = 0; ks < 4; ks++) {
        uint32_t off = ((16 * w + (lane & 15)) * AST + ks * 16 + (lane >> 4) * 8) * 2;
        ldsm4(qh[ks], uQ + off);
    }

    float m0r = -1e30f, m1r = -1e30f;
    float l0r = 0.f, l1r = 0.f;
    float oacc[8][4] = {};

    for (int kt = 0; kt <= qt; kt++) {
        int s = kt & 1;
        __syncthreads();
        if (kt + 1 <= qt) issue_kv(kt + 1, s ^ 1); else CP_COMMIT();
        CP_WAIT(1);
        __syncthreads();

        uint32_t uK = uKV + (s * KVSTAGE) * 2;
        uint32_t uV = uK + ATILE * 2;

        // ---- S = QK^T ----
        float sacc[8][4] = {};
#pragma unroll
        for (int ks = 0; ks < 4; ks++) {
            uint32_t kb[4][4];
            uint32_t boff = ((lane & 7) + ((lane >> 4) & 1) * 8) * AST + ks * 16 + ((lane >> 3) & 1) * 8;
#pragma unroll
            for (int g = 0; g < 4; g++) ldsm4(kb[g], uK + (boff + g * 16 * AST) * 2);
#pragma unroll
            for (int g = 0; g < 4; g++) {
                mma16816(sacc[g * 2 + 0], qh[ks], &kb[g][0]);
                mma16816(sacc[g * 2 + 1], qh[ks], &kb[g][2]);
            }
        }

        // ---- scale, mask, online softmax ----
        int rl0 = w * 16 + (lane >> 2);
        int rl1 = rl0 + 8;
        float mn0 = m0r, mn1 = m1r;
#pragma unroll
        for (int t = 0; t < 8; t++) {
            sacc[t][0] *= 0.125f; sacc[t][1] *= 0.125f;
            sacc[t][2] *= 0.125f; sacc[t][3] *= 0.125f;
            if (kt == qt) {
                int col = t * 8 + 2 * (lane & 3);
                if (col     > rl0) sacc[t][0] = -1e30f;
                if (col + 1 > rl0) sacc[t][1] = -1e30f;
                if (col     > rl1) sacc[t][2] = -1e30f;
                if (col + 1 > rl1) sacc[t][3] = -1e30f;
            }
            mn0 = fmaxf(mn0, fmaxf(sacc[t][0], sacc[t][1]));
            mn1 = fmaxf(mn1, fmaxf(sacc[t][2], sacc[t][3]));
        }
        mn0 = fmaxf(mn0, __shfl_xor_sync(0xffffffffu, mn0, 1));
        mn0 = fmaxf(mn0, __shfl_xor_sync(0xffffffffu, mn0, 2));
        mn1 = fmaxf(mn1, __shfl_xor_sync(0xffffffffu, mn1, 1));
        mn1 = fmaxf(mn1, __shfl_xor_sync(0xffffffffu, mn1, 2));
        float es0 = __expf(m0r - mn0), es1 = __expf(m1r - mn1);
        m0r = mn0; m1r = mn1;
        float rs0 = 0.f, rs1 = 0.f;
#pragma unroll
        for (int t = 0; t < 8; t++) {
            sacc[t][0] = __expf(sacc[t][0] - mn0);
            sacc[t][1] = __expf(sacc[t][1] - mn0);
            sacc[t][2] = __expf(sacc[t][2] - mn1);
            sacc[t][3] = __expf(sacc[t][3] - mn1);
            rs0 += sacc[t][0] + sacc[t][1];
            rs1 += sacc[t][2] + sacc[t][3];
        }
        rs0 += __shfl_xor_sync(0xffffffffu, rs0, 1);
        rs0 += __shfl_xor_sync(0xffffffffu, rs0, 2);
        rs1 += __shfl_xor_sync(0xffffffffu, rs1, 1);
        rs1 += __shfl_xor_sync(0xffffffffu, rs1, 2);
        l0r = l0r * es0 + rs0;
        l1r = l1r * es1 + rs1;
#pragma unroll
        for (int t = 0; t < 8; t++) {
            oacc[t][0] *= es0; oacc[t][1] *= es0;
            oacc[t][2] *= es1; oacc[t][3] *= es1;
        }

        // ---- PV ----
#pragma unroll
        for (int ks = 0; ks < 4; ks++) {
            uint32_t pa[4];
            pa[0] = pack2(sacc[2 * ks][0],     sacc[2 * ks][1]);
            pa[1] = pack2(sacc[2 * ks][2],     sacc[2 * ks][3]);
            pa[2] = pack2(sacc[2 * ks + 1][0], sacc[2 * ks + 1][1]);
            pa[3] = pack2(sacc[2 * ks + 1][2], sacc[2 * ks + 1][3]);

            uint32_t vb[4][4];
            uint32_t voff = (ks * 16 + (lane & 15)) * AST + ((lane >> 4) & 1) * 8;
#pragma unroll
            for (int g = 0; g < 4; g++) ldsm4t(vb[g], uV + (voff + g * 16) * 2);
#pragma unroll
            for (int g = 0; g < 4; g++) {
                mma16816(oacc[g * 2 + 0], pa, &vb[g][0]);
                mma16816(oacc[g * 2 + 1], pa, &vb[g][2]);
            }
        }
    }

    float inv0 = 1.0f / l0r, inv1 = 1.0f / l1r;
    size_t r0g = (size_t)(b * TT + qt * 64 + w * 16 + (lane >> 2));
    size_t obase0 = r0g * CC + h * DD;
    size_t obase1 = (r0g + 8) * CC + h * DD;
#pragma unroll
    for (int t = 0; t < 8; t++) {
        int d = t * 8 + 2 * (lane & 3);
        *(uint32_t*)(o_g + obase0 + d) = pack2(oacc[t][0] * inv0, oacc[t][1] * inv0);
        *(uint32_t*)(o_g + obase1 + d) = pack2(oacc[t][2] * inv1, oacc[t][3] * inv1);
    }
}

// ---------------- launch ----------------
extern "C" void kernel_launch(void* const* d_in, const int* in_sizes, int n_in,
                              void* d_out, int out_size)
{
    const float* x     = (const float*)d_in[0];
    const float* ln1_g = (const float*)d_in[1];
    const float* ln1_b = (const float*)d_in[2];
    const float* qkv_w = (const float*)d_in[3];
    const float* qkv_b = (const float*)d_in[4];
    const float* out_w = (const float*)d_in[5];
    const float* out_b = (const float*)d_in[6];
    const float* ln2_g = (const float*)d_in[7];
    const float* ln2_b = (const float*)d_in[8];
    const float* ff1_w = (const float*)d_in[9];
    const float* ff1_b = (const float*)d_in[10];
    const float* ff2_w = (const float*)d_in[11];
    const float* ff2_b = (const float*)d_in[12];
    float* y = (float*)d_out;

    float *p_x1;
    __half *p_h, *p_q, *p_a, *p_f;
    __half *p_wq, *p_wo, *p_w1, *p_w2;
    cudaGetSymbolAddress((void**)&p_x1, g_x1);
    cudaGetSymbolAddress((void**)&p_h,  g_h);
    cudaGetSymbolAddress((void**)&p_q,  g_q);
    cudaGetSymbolAddress((void**)&p_a,  g_a);
    cudaGetSymbolAddress((void**)&p_f,  g_f);
    cudaGetSymbolAddress((void**)&p_wq, g_wqkv);
    cudaGetSymbolAddress((void**)&p_wo, g_wout);
    cudaGetSymbolAddress((void**)&p_w1, g_wff1);
    cudaGetSymbolAddress((void**)&p_w2, g_wff2);

    cudaFuncSetAttribute(attn_fa2, cudaFuncAttributeMaxDynamicSharedMemorySize, ASMEM);
    cudaFuncSetAttribute((const void*)gemm_mma<1>, cudaFuncAttributeMaxDynamicSharedMemorySize, GSMEM2);
    cudaFuncSetAttribute((const void*)gemm_mma<2>, cudaFuncAttributeMaxDynamicSharedMemorySize, GSMEM2);
    cudaFuncSetAttribute((const void*)gemm_mma<4>, cudaFuncAttributeMaxDynamicSharedMemorySize, GSMEM2);

    // side stream + events, created once OUTSIDE graph capture (first call is the
    // eager correctness run). Reused identically every call -> deterministic work.
    static cudaStream_t s1 = nullptr;
    static cudaEvent_t e0 = nullptr, e1 = nullptr;
    if (!s1) {
        cudaStreamCreateWithFlags(&s1, cudaStreamNonBlocking);
        cudaEventCreateWithFlags(&e0, cudaEventDisableTiming);
        cudaEventCreateWithFlags(&e1, cudaEventDisableTiming);
    }

    // main stream: qkv weight convert + LN1 (both needed by qkv GEMM)
    wconv_kernel<<<CC * QKVC / 2048, 256>>>(qkv_w, p_wq);
    ln_kernel<<<MM, 256>>>(x, ln1_g, ln1_b, p_h);

    // fork: other weight converts overlap qkv GEMM + attention
    cudaEventRecord(e0, 0);
    cudaStreamWaitEvent(s1, e0, 0);
    wconv_kernel<<<CC * CC / 2048, 256, 0, s1>>>(out_w, p_wo);
    wconv_kernel<<<CC * FF / 2048, 256, 0, s1>>>(ff1_w, p_w1);
    wconv_kernel<<<FF * CC / 2048, 256, 0, s1>>>(ff2_w, p_w2);
    cudaEventRecord(e1, s1);

    // 2) qkv = h @ qkv_w + qkv_b -> fp16
    gemm_mma<4><<<dim3(QKVC / 128, MM / 128), 256, GSMEM2>>>(
        p_h, p_wq, qkv_b, nullptr, nullptr, p_q, CC, QKVC);
    // 3) attention -> fp16
    attn_fa2<<<dim3(TT / 64, HH, BB), 128, ASMEM>>>(p_q, p_a);

    // join: remaining GEMMs need the converted weights
    cudaStreamWaitEvent(0, e1, 0);

    // 4) x1 = x + att @ out_w + out_b  (fp32)
    gemm_mma<1><<<dim3(CC / 128, MM / 128), 256, GSMEM2>>>(
        p_a, p_wo, out_b, x, p_x1, nullptr, CC, CC);
    // 5) h = LN2(x1) -> fp16
    ln_kernel<<<MM, 256>>>(p_x1, ln2_g, ln2_b, p_h);
    // 6) ff = gelu(h @ ff1_w + ff1_b) -> fp16
    gemm_mma<2><<<dim3(FF / 128, MM / 128), 256, GSMEM2>>>(
        p_h, p_w1, ff1_b, nullptr, nullptr, p_f, CC, FF);
    // 7) y = x1 + ff @ ff2_w + ff2_b
    gemm_mma<1><<<dim3(CC / 128, MM / 128), 256, GSMEM2>>>(
        p_f, p_w2, ff2_b, p_x1, y, nullptr, FF, CC);
}